// round 5
// baseline (speedup 1.0000x reference)
#include <cuda_runtime.h>
#include <math.h>

#define Bb 4
#define Ss 4096
#define Dd 1024
#define Mm 2048
#define Kk 128
#define Vv 128
#define NGRP 8
#define NWRITES 1024
#define KEEP 1024

// ---------------- scratch (device globals; no allocations) ----------------
__device__ __align__(16) float g_xn[Bb * Ss * Dd];
__device__ __align__(16) float g_h[Bb * Ss * Dd];          // MLP hidden, later "combined"
__device__ __align__(16) float g_memk[Bb * Ss * Kk];
__device__ __align__(16) float g_memv[Bb * Ss * Vv];
__device__ __align__(16) float g_memq[Bb * Ss * Kk];
__device__ __align__(16) float g_sig[Bb * Ss];
__device__ __align__(16) int   g_topidx[Bb * NWRITES];
__device__ __align__(16) float g_q[Bb * Ss * Dd];
__device__ __align__(16) float g_k[Bb * Ss * Dd];
__device__ __align__(16) float g_v[Bb * Ss * Dd];
__device__ __align__(16) float g_sim[(size_t)Bb * Ss * Mm];   // 128 MB
__device__ __align__(16) float g_retr[Bb * Ss * Vv];
__device__ __align__(16) float g_memout[Bb * Ss * Dd];
__device__ __align__(16) float g_qmean[Bb * Dd];
__device__ __align__(16) float g_gctx[Bb * Dd];

// ---------------- LayerNorm + write-gate logit (fused) ----------------
// Harness-input loads are scalar; scratch writes are vectorized.
__global__ void ln_imp_kernel(const float* __restrict__ x,
                              const float* __restrict__ lng,
                              const float* __restrict__ lnb,
                              const float* __restrict__ wgw,
                              const float* __restrict__ wgb) {
    int row = blockIdx.x;
    int tid = threadIdx.x;
    const float* xr = x + (size_t)row * Dd + tid * 4;
    float x0 = xr[0], x1 = xr[1], x2 = xr[2], x3 = xr[3];
    __shared__ float red[256];

    red[tid] = x0 + x1 + x2 + x3; __syncthreads();
    for (int o = 128; o > 0; o >>= 1) { if (tid < o) red[tid] += red[tid + o]; __syncthreads(); }
    float mu = red[0] * (1.f / Dd);
    __syncthreads();

    float d0 = x0 - mu, d1 = x1 - mu, d2 = x2 - mu, d3 = x3 - mu;
    red[tid] = d0 * d0 + d1 * d1 + d2 * d2 + d3 * d3; __syncthreads();
    for (int o = 128; o > 0; o >>= 1) { if (tid < o) red[tid] += red[tid + o]; __syncthreads(); }
    float var = red[0] * (1.f / Dd);
    float rs = rsqrtf(var + 1e-5f);
    __syncthreads();

    float y0 = d0 * rs * lng[tid * 4 + 0] + lnb[tid * 4 + 0];
    float y1 = d1 * rs * lng[tid * 4 + 1] + lnb[tid * 4 + 1];
    float y2 = d2 * rs * lng[tid * 4 + 2] + lnb[tid * 4 + 2];
    float y3 = d3 * rs * lng[tid * 4 + 3] + lnb[tid * 4 + 3];
    ((float4*)(g_xn + (size_t)row * Dd))[tid] = make_float4(y0, y1, y2, y3);

    red[tid] = y0 * wgw[tid * 4 + 0] + y1 * wgw[tid * 4 + 1]
             + y2 * wgw[tid * 4 + 2] + y3 * wgw[tid * 4 + 3];
    __syncthreads();
    for (int o = 128; o > 0; o >>= 1) { if (tid < o) red[tid] += red[tid + o]; __syncthreads(); }
    if (tid == 0) {
        double l = (double)(red[0] + wgb[0]);
        g_sig[row] = (float)(1.0 / (1.0 + exp(-l)));   // correctly-rounded fp32 sigmoid
    }
}

// ---------------- per-batch full bitonic sort -> top-1024 indices ----------------
__global__ void topk_kernel() {
    __shared__ __align__(16) unsigned long long sk[Ss];
    int b = blockIdx.x, tid = threadIdx.x;
    for (int i = tid; i < Ss; i += 1024) {
        unsigned u = __float_as_uint(g_sig[b * Ss + i]);
        u = (u & 0x80000000u) ? ~u : (u | 0x80000000u);
        sk[i] = ((unsigned long long)u << 32) | (unsigned)(0xFFFFFFFFu - i);
    }
    __syncthreads();
    for (int k = 2; k <= Ss; k <<= 1) {
        for (int j = k >> 1; j > 0; j >>= 1) {
            for (int i = tid; i < Ss; i += 1024) {
                int ixj = i ^ j;
                if (ixj > i) {
                    bool desc = ((i & k) == 0);
                    unsigned long long a = sk[i], c = sk[ixj];
                    if ((a < c) == desc) { sk[i] = c; sk[ixj] = a; }
                }
            }
            __syncthreads();
        }
    }
    for (int i = tid; i < NWRITES; i += 1024)
        g_topidx[b * NWRITES + i] = (int)(0xFFFFFFFFu - (unsigned)sk[i]);
}

// ---------------- splice memory: [keep rows | gathered new entries] -> d_out ----------------
__global__ void assemble_kernel(const float* __restrict__ md, float* __restrict__ om) {
    int idx = blockIdx.x * blockDim.x + threadIdx.x;
    if (idx >= Bb * Mm * 256) return;
    int c = idx & 255;
    int m = (idx >> 8) & (Mm - 1);
    int b = idx >> 19;
    float val;
    if (m < KEEP) val = md[idx];
    else {
        int id = g_topidx[b * NWRITES + (m - KEEP)];
        val = (c < Kk) ? g_memk[((size_t)(b * Ss) + id) * Kk + c]
                       : g_memv[((size_t)(b * Ss) + id) * Vv + (c - Kk)];
    }
    om[idx] = val;
}

// ---------------- generic tiled fp32 GEMM ----------------
// C = act(alpha*A@op(B) + bias) [+ resid]. A is 16B-aligned scratch (float4);
// B/bias/resid may be harness inputs -> scalar loads only.
#define BM 64
#define BN 64
#define BKg 16

template <int TRANSB, int ACT, int RESID>
__global__ void gemm_k(const float* __restrict__ A, int lda, long sA,
                       const float* __restrict__ Bm, int ldb, long sB,
                       const float* __restrict__ bias,
                       const float* __restrict__ resid,
                       float* __restrict__ C, int ldc, long sC,
                       int Mr, int Kd, float alpha) {
    __shared__ __align__(16) float As[BKg][BM + 4];
    __shared__ __align__(16) float Bs[BKg][BN + 4];
    __shared__ __align__(16) float sbias[BN];
    long bz = blockIdx.z;
    A += bz * sA; Bm += bz * sB; C += bz * sC;
    if (RESID) resid += bz * sC;
    int n0 = blockIdx.x * BN, m0 = blockIdx.y * BM;
    int tid = threadIdx.x;
    int tx = tid & 15, ty = tid >> 4;

    if (tid < BN) sbias[tid] = bias ? bias[n0 + tid] : 0.f;

    float acc[4][4];
#pragma unroll
    for (int i = 0; i < 4; i++)
#pragma unroll
        for (int j = 0; j < 4; j++) acc[i][j] = 0.f;

    int aRow = tid >> 2, aCol = (tid & 3) * 4;

    for (int k0 = 0; k0 < Kd; k0 += BKg) {
        float4 av = make_float4(0.f, 0.f, 0.f, 0.f);
        if (m0 + aRow < Mr)
            av = *(const float4*)&A[(long)(m0 + aRow) * lda + k0 + aCol];
        As[aCol + 0][aRow] = av.x; As[aCol + 1][aRow] = av.y;
        As[aCol + 2][aRow] = av.z; As[aCol + 3][aRow] = av.w;

        if (TRANSB) {
            int n = tid >> 2, kc = (tid & 3) * 4;
            const float* bp = &Bm[(long)(n0 + n) * ldb + k0 + kc];
            Bs[kc + 0][n] = bp[0]; Bs[kc + 1][n] = bp[1];
            Bs[kc + 2][n] = bp[2]; Bs[kc + 3][n] = bp[3];
        } else {
            int kr = tid >> 4, n = (tid & 15) * 4;
            const float* bp = &Bm[(long)(k0 + kr) * ldb + n0 + n];
            Bs[kr][n + 0] = bp[0]; Bs[kr][n + 1] = bp[1];
            Bs[kr][n + 2] = bp[2]; Bs[kr][n + 3] = bp[3];
        }
        __syncthreads();

#pragma unroll
        for (int kk = 0; kk < BKg; kk++) {
            const float4 a = *(const float4*)&As[kk][ty * 4];
            const float4 b4 = *(const float4*)&Bs[kk][tx * 4];
            float ar[4] = {a.x, a.y, a.z, a.w};
            float br[4] = {b4.x, b4.y, b4.z, b4.w};
#pragma unroll
            for (int ii = 0; ii < 4; ii++)
#pragma unroll
                for (int jj = 0; jj < 4; jj++) acc[ii][jj] += ar[ii] * br[jj];
        }
        __syncthreads();
    }

#pragma unroll
    for (int i = 0; i < 4; i++) {
        int m = m0 + ty * 4 + i;
        if (m >= Mr) break;
#pragma unroll
        for (int j = 0; j < 4; j++) {
            int n = n0 + tx * 4 + j;
            float v = acc[i][j] * alpha + sbias[tx * 4 + j];
            if (ACT == 1) v = 0.5f * v * (1.f + erff(v * 0.7071067811865475f)); // exact gelu
            if (RESID) v += resid[(long)m * ldc + n];   // scalar load (harness input ok)
            C[(long)m * ldc + n] = v;
        }
    }
}

// ---------------- row softmax over M=2048 ----------------
__global__ void softmax_kernel(float* __restrict__ sim) {
    long row = blockIdx.x;
    float* p = sim + row * (long)Mm;
    int tid = threadIdx.x;
    float v[8];
    float mx = -3.4e38f;
#pragma unroll
    for (int t = 0; t < 8; t++) { v[t] = p[tid + t * 256]; mx = fmaxf(mx, v[t]); }
    __shared__ float red[256];
    red[tid] = mx; __syncthreads();
    for (int o = 128; o > 0; o >>= 1) { if (tid < o) red[tid] = fmaxf(red[tid], red[tid + o]); __syncthreads(); }
    mx = red[0]; __syncthreads();
    float s = 0.f;
#pragma unroll
    for (int t = 0; t < 8; t++) { v[t] = expf(v[t] - mx); s += v[t]; }
    red[tid] = s; __syncthreads();
    for (int o = 128; o > 0; o >>= 1) { if (tid < o) red[tid] += red[tid + o]; __syncthreads(); }
    float inv = 1.f / red[0];
#pragma unroll
    for (int t = 0; t < 8; t++) p[tid + t * 256] = v[t] * inv;
}

// ---------------- mean over S of queries ----------------
__global__ void qmean_kernel() {
    int d = blockIdx.x * 256 + threadIdx.x;
    int b = blockIdx.y;
    const float* p = g_q + (size_t)b * Ss * Dd + d;
    double s = 0.0;
    for (int t = 0; t < Ss; t++) s += p[(size_t)t * Dd];
    g_qmean[b * Dd + d] = (float)(s * (1.0 / Ss));
}

// ---------------- grouped conv(3) fused with combine epilogue ----------------
// combined = (conv(v) + conv_b + 0.1*gctx + 0.5*memout) * sigmoid(keys) -> g_h
__global__ void conv_combine_kernel(const float* __restrict__ cw,
                                    const float* __restrict__ cb) {
    __shared__ __align__(16) float vt[66][129];
    __shared__ __align__(16) float ws[16][128];   // <- float4-read tile: MUST be 16B-aligned
    __shared__ __align__(16) float cbs[128];
    int b = blockIdx.z, g = blockIdx.y, s0 = blockIdx.x * 64;
    int tid = threadIdx.x;
    int tx = tid & 15, ty = tid >> 4;

    if (tid < 128) cbs[tid] = cb[g * 128 + tid];

    for (int i = tid; i < 66 * 128; i += 256) {
        int rr = i >> 7, cc = i & 127;
        int s = s0 + rr - 1;
        vt[rr][cc] = (s >= 0 && s < Ss)
                     ? g_v[((size_t)(b * Ss) + s) * Dd + g * 128 + cc] : 0.f;
    }
    __syncthreads();

    float acc[4][8];
#pragma unroll
    for (int i = 0; i < 4; i++)
#pragma unroll
        for (int j = 0; j < 8; j++) acc[i][j] = 0.f;

    for (int h = 0; h < 3; h++) {
        for (int i0 = 0; i0 < 128; i0 += 16) {
            for (int i = tid; i < 16 * 128; i += 256) {
                int k = i >> 7, o = i & 127;
                ws[k][o] = cw[(((size_t)(g * 128 + o)) * 128 + (i0 + k)) * 3 + h];
            }
            __syncthreads();
#pragma unroll
            for (int k = 0; k < 16; k++) {
                float a0 = vt[ty * 4 + 0 + h][i0 + k];
                float a1 = vt[ty * 4 + 1 + h][i0 + k];
                float a2 = vt[ty * 4 + 2 + h][i0 + k];
                float a3 = vt[ty * 4 + 3 + h][i0 + k];
                float4 b0 = *(const float4*)&ws[k][tx * 8];
                float4 b1 = *(const float4*)&ws[k][tx * 8 + 4];
                float br[8] = {b0.x, b0.y, b0.z, b0.w, b1.x, b1.y, b1.z, b1.w};
                float ar[4] = {a0, a1, a2, a3};
#pragma unroll
                for (int ii = 0; ii < 4; ii++)
#pragma unroll
                    for (int jj = 0; jj < 8; jj++) acc[ii][jj] += ar[ii] * br[jj];
            }
            __syncthreads();
        }
    }

#pragma unroll
    for (int ii = 0; ii < 4; ii++) {
        int s = s0 + ty * 4 + ii;
#pragma unroll
        for (int jj = 0; jj < 8; jj++) {
            int oc = tx * 8 + jj;
            int o = g * 128 + oc;
            size_t idx = ((size_t)(b * Ss) + s) * Dd + o;
            float lc = acc[ii][jj] + cbs[oc];
            float kv = g_k[idx];
            float pw = 1.f / (1.f + expf(-kv));
            g_h[idx] = (lc + 0.1f * g_gctx[b * Dd + o] + 0.5f * g_memout[idx]) * pw;
        }
    }
}

// ---------------- launch ----------------
extern "C" void kernel_launch(void* const* d_in, const int* in_sizes, int n_in,
                              void* d_out, int out_size) {
    const float* x         = (const float*)d_in[0];
    const float* memdict   = (const float*)d_in[1];
    const float* ln_g      = (const float*)d_in[2];
    const float* ln_b      = (const float*)d_in[3];
    const float* mk_w1     = (const float*)d_in[4];
    const float* mk_b1     = (const float*)d_in[5];
    const float* mk_w2     = (const float*)d_in[6];
    const float* mk_b2     = (const float*)d_in[7];
    const float* mv_w1     = (const float*)d_in[8];
    const float* mv_b1     = (const float*)d_in[9];
    const float* mv_w2     = (const float*)d_in[10];
    const float* mv_b2     = (const float*)d_in[11];
    const float* mq_w1     = (const float*)d_in[12];
    const float* mq_b1     = (const float*)d_in[13];
    const float* mq_w2     = (const float*)d_in[14];
    const float* mq_b2     = (const float*)d_in[15];
    const float* wg_w      = (const float*)d_in[16];
    const float* wg_b      = (const float*)d_in[17];
    const float* q_w       = (const float*)d_in[18];
    const float* k_w       = (const float*)d_in[19];
    const float* v_w       = (const float*)d_in[20];
    const float* conv_w    = (const float*)d_in[21];
    const float* conv_b    = (const float*)d_in[22];
    const float* gp_w      = (const float*)d_in[23];
    const float* gp_b      = (const float*)d_in[24];
    const float* mr_w      = (const float*)d_in[25];
    const float* mr_b      = (const float*)d_in[26];
    const float* out_w     = (const float*)d_in[27];
    const float* out_b     = (const float*)d_in[28];

    float* out_main = (float*)d_out;
    float* out_mem  = out_main + (size_t)Bb * Ss * Dd;

    float *p_xn, *p_h, *p_memk, *p_memv, *p_memq, *p_q, *p_k, *p_v, *p_sim, *p_retr, *p_memout, *p_qmean, *p_gctx;
    cudaGetSymbolAddress((void**)&p_xn, g_xn);
    cudaGetSymbolAddress((void**)&p_h, g_h);
    cudaGetSymbolAddress((void**)&p_memk, g_memk);
    cudaGetSymbolAddress((void**)&p_memv, g_memv);
    cudaGetSymbolAddress((void**)&p_memq, g_memq);
    cudaGetSymbolAddress((void**)&p_q, g_q);
    cudaGetSymbolAddress((void**)&p_k, g_k);
    cudaGetSymbolAddress((void**)&p_v, g_v);
    cudaGetSymbolAddress((void**)&p_sim, g_sim);
    cudaGetSymbolAddress((void**)&p_retr, g_retr);
    cudaGetSymbolAddress((void**)&p_memout, g_memout);
    cudaGetSymbolAddress((void**)&p_qmean, g_qmean);
    cudaGetSymbolAddress((void**)&p_gctx, g_gctx);

    const int ROWS = Bb * Ss;           // 16384
    dim3 thr(256);

    // 1) LN + write-gate
    ln_imp_kernel<<<ROWS, 256>>>(x, ln_g, ln_b, wg_w, wg_b);
    // 2) top-k per batch
    topk_kernel<<<Bb, 1024>>>();

    // 3) mem_keys MLP
    gemm_k<0, 1, 0><<<dim3(Dd / BN, ROWS / BM, 1), thr>>>(p_xn, Dd, 0, mk_w1, Dd, 0, mk_b1, nullptr, p_h, Dd, 0, ROWS, Dd, 1.f);
    gemm_k<0, 0, 0><<<dim3(Kk / BN, ROWS / BM, 1), thr>>>(p_h, Dd, 0, mk_w2, Kk, 0, mk_b2, nullptr, p_memk, Kk, 0, ROWS, Dd, 1.f);
    // 4) mem_values MLP
    gemm_k<0, 1, 0><<<dim3(Dd / BN, ROWS / BM, 1), thr>>>(p_xn, Dd, 0, mv_w1, Dd, 0, mv_b1, nullptr, p_h, Dd, 0, ROWS, Dd, 1.f);
    gemm_k<0, 0, 0><<<dim3(Vv / BN, ROWS / BM, 1), thr>>>(p_h, Dd, 0, mv_w2, Vv, 0, mv_b2, nullptr, p_memv, Vv, 0, ROWS, Dd, 1.f);
    // 5) splice memory into d_out (fp32)
    assemble_kernel<<<(Bb * Mm * 256 + 255) / 256, 256>>>(memdict, out_mem);
    // 6) mem_queries MLP
    gemm_k<0, 1, 0><<<dim3(Dd / BN, ROWS / BM, 1), thr>>>(p_xn, Dd, 0, mq_w1, Dd, 0, mq_b1, nullptr, p_h, Dd, 0, ROWS, Dd, 1.f);
    gemm_k<0, 0, 0><<<dim3(Kk / BN, ROWS / BM, 1), thr>>>(p_h, Dd, 0, mq_w2, Kk, 0, mq_b2, nullptr, p_memq, Kk, 0, ROWS, Dd, 1.f);

    // 7) sim = q @ K^T / sqrt(K)   (batched; B rows = memory entries in d_out)
    gemm_k<1, 0, 0><<<dim3(Mm / BN, Ss / BM, Bb), thr>>>(p_memq, Kk, (long)Ss * Kk,
                                                         out_mem, 256, (long)Mm * 256,
                                                         nullptr, nullptr,
                                                         p_sim, Mm, (long)Ss * Mm,
                                                         Ss, Kk, 0.08838834764831845f);
    // 8) softmax rows
    softmax_kernel<<<ROWS, 256>>>(p_sim);
    // 9) retrieved = attn @ V  (batched)
    gemm_k<0, 0, 0><<<dim3(Vv / BN, Ss / BM, Bb), thr>>>(p_sim, Mm, (long)Ss * Mm,
                                                         out_mem + Kk, 256, (long)Mm * 256,
                                                         nullptr, nullptr,
                                                         p_retr, Vv, (long)Ss * Vv,
                                                         Ss, Mm, 1.f);
    // 10) memory_output = retrieved @ mr_w + mr_b
    gemm_k<0, 0, 0><<<dim3(Dd / BN, ROWS / BM, 1), thr>>>(p_retr, Vv, 0, mr_w, Dd, 0, mr_b, nullptr, p_memout, Dd, 0, ROWS, Vv, 1.f);

    // 11) q, k, v projections
    gemm_k<0, 0, 0><<<dim3(Dd / BN, ROWS / BM, 1), thr>>>(p_xn, Dd, 0, q_w, Dd, 0, nullptr, nullptr, p_q, Dd, 0, ROWS, Dd, 1.f);
    gemm_k<0, 0, 0><<<dim3(Dd / BN, ROWS / BM, 1), thr>>>(p_xn, Dd, 0, k_w, Dd, 0, nullptr, nullptr, p_k, Dd, 0, ROWS, Dd, 1.f);
    gemm_k<0, 0, 0><<<dim3(Dd / BN, ROWS / BM, 1), thr>>>(p_xn, Dd, 0, v_w, Dd, 0, nullptr, nullptr, p_v, Dd, 0, ROWS, Dd, 1.f);

    // 12) mean(queries) over S, 13) global ctx projection (M=4, row-guarded)
    qmean_kernel<<<dim3(Dd / 256, Bb), 256>>>();
    gemm_k<0, 0, 0><<<dim3(Dd / BN, 1, 1), thr>>>(p_qmean, Dd, 0, gp_w, Dd, 0, gp_b, nullptr, p_gctx, Dd, 0, Bb, Dd, 1.f);

    // 14) conv + combine -> g_h
    conv_combine_kernel<<<dim3(Ss / 64, NGRP, Bb), 256>>>(conv_w, conv_b);

    // 15) output = combined @ out_w + out_b + residual(x)
    gemm_k<0, 0, 1><<<dim3(Dd / BN, ROWS / BM, 1), thr>>>(p_h, Dd, 0, out_w, Dd, 0, out_b, x, out_main, Dd, 0, ROWS, Dd, 1.f);
}

// round 6
// speedup vs baseline: 2.6026x; 2.6026x over previous
#include <cuda_runtime.h>
#include <math.h>
#include <stdint.h>

#define Bb 4
#define Ss 4096
#define Dd 1024
#define Mm 2048
#define Kk 128
#define Vv 128
#define NGRP 8
#define NWRITES 1024
#define KEEP 1024

// ---------------- scratch (device globals; no allocations) ----------------
__device__ __align__(16) float g_xn[Bb * Ss * Dd];
__device__ __align__(16) float g_h[Bb * Ss * Dd];
__device__ __align__(16) float g_memk[Bb * Ss * Kk];
__device__ __align__(16) float g_memv[Bb * Ss * Vv];
__device__ __align__(16) float g_memq[Bb * Ss * Kk];
__device__ __align__(16) float g_sig[Bb * Ss];
__device__ __align__(16) int   g_topidx[Bb * NWRITES];
__device__ __align__(16) float g_q[Bb * Ss * Dd];
__device__ __align__(16) float g_k[Bb * Ss * Dd];
__device__ __align__(16) float g_v[Bb * Ss * Dd];
__device__ __align__(16) float g_sim[(size_t)Bb * Ss * Mm];   // 128 MB
__device__ __align__(16) float g_retr[Bb * Ss * Vv];
__device__ __align__(16) float g_memout[Bb * Ss * Dd];
__device__ __align__(16) float g_qmean[Bb * Dd];
__device__ __align__(16) float g_gctx[Bb * Dd];
__device__ __align__(16) float g_wt[3 * NGRP * 128 * 128];    // transposed conv weights

// ---------------- tf32 helpers ----------------
__device__ __forceinline__ uint32_t f2tf32(float f) {
    uint32_t u;
    asm("cvt.rna.tf32.f32 %0, %1;" : "=r"(u) : "f"(f));
    return u;
}
__device__ __forceinline__ void mma8(float* c, const uint32_t* a, const uint32_t* b) {
    asm volatile(
        "mma.sync.aligned.m16n8k8.row.col.f32.tf32.tf32.f32 "
        "{%0,%1,%2,%3}, {%4,%5,%6,%7}, {%8,%9}, {%0,%1,%2,%3};\n"
        : "+f"(c[0]), "+f"(c[1]), "+f"(c[2]), "+f"(c[3])
        : "r"(a[0]), "r"(a[1]), "r"(a[2]), "r"(a[3]), "r"(b[0]), "r"(b[1]));
}

#define TBM 128
#define TBN 128
#define TBK 32
#define TSTR 136          // k-row stride in 4B words; 136 % 32 == 8 -> conflict-free frag reads
__device__ __forceinline__ int swz(int k, int m) { return m ^ (((k >> 2) & 7) << 2); }

// ---------------- tf32 tensor-core GEMM ----------------
// C = act(alpha*A@op(B) + bias) [+ resid].  M%128==0, N%128==0, K%32==0.
template <int TRANSB, int ACT, int RESID>
__global__ void __launch_bounds__(256, 2) gemm_tc(
    const float* __restrict__ A, int lda, long sA,
    const float* __restrict__ Bm, int ldb, long sB,
    const float* __restrict__ bias,
    const float* __restrict__ resid,
    float* __restrict__ C, int ldc, long sC,
    int Kd, float alpha)
{
    __shared__ __align__(16) uint32_t As[TBK * TSTR];
    __shared__ __align__(16) uint32_t Bs[TBK * TSTR];
    __shared__ __align__(16) float sbias[TBN];
    long bz = blockIdx.z;
    A += bz * sA; Bm += bz * sB; C += bz * sC;
    if (RESID) resid += bz * sC;
    int n0 = blockIdx.x * TBN, m0 = blockIdx.y * TBM;
    int tid = threadIdx.x;
    int warp = tid >> 5, lane = tid & 31;
    int g = lane >> 2, tg = lane & 3;
    int wm = (warp & 1) * 64, wn = (warp >> 1) * 32;

    if (tid < TBN) sbias[tid] = bias ? bias[n0 + tid] : 0.f;

    float c[4][4][4];
#pragma unroll
    for (int a = 0; a < 4; a++)
#pragma unroll
        for (int b = 0; b < 4; b++)
#pragma unroll
            for (int e = 0; e < 4; e++) c[a][b][e] = 0.f;

    int arow = tid >> 3, acol = (tid & 7) * 4;

    for (int k0 = 0; k0 < Kd; k0 += TBK) {
#pragma unroll
        for (int p = 0; p < 4; p++) {
            int m = arow + p * 32;
            float4 v = *(const float4*)&A[(long)(m0 + m) * lda + k0 + acol];
            As[(acol + 0) * TSTR + swz(acol + 0, m)] = f2tf32(v.x);
            As[(acol + 1) * TSTR + swz(acol + 1, m)] = f2tf32(v.y);
            As[(acol + 2) * TSTR + swz(acol + 2, m)] = f2tf32(v.z);
            As[(acol + 3) * TSTR + swz(acol + 3, m)] = f2tf32(v.w);
        }
        if (TRANSB) {
            int k = tid & 31, nb = tid >> 5;
#pragma unroll
            for (int p = 0; p < 16; p++) {
                int n = nb + p * 8;
                Bs[k * TSTR + swz(k, n)] = f2tf32(Bm[(long)(n0 + n) * ldb + k0 + k]);
            }
        } else {
            int n = tid & 127, kb = tid >> 7;
#pragma unroll
            for (int p = 0; p < 16; p++) {
                int k = kb + p * 2;
                Bs[k * TSTR + swz(k, n)] = f2tf32(Bm[(long)(k0 + k) * ldb + n0 + n]);
            }
        }
        __syncthreads();
#pragma unroll
        for (int ks = 0; ks < 4; ks++) {
            int kk = ks * 8;
            uint32_t af[4][4], bf[4][2];
#pragma unroll
            for (int mi = 0; mi < 4; mi++) {
                int m = wm + mi * 16;
                af[mi][0] = As[(kk + tg) * TSTR + swz(kk + tg, m + g)];
                af[mi][1] = As[(kk + tg) * TSTR + swz(kk + tg, m + g + 8)];
                af[mi][2] = As[(kk + tg + 4) * TSTR + swz(kk + tg + 4, m + g)];
                af[mi][3] = As[(kk + tg + 4) * TSTR + swz(kk + tg + 4, m + g + 8)];
            }
#pragma unroll
            for (int ni = 0; ni < 4; ni++) {
                int n = wn + ni * 8;
                bf[ni][0] = Bs[(kk + tg) * TSTR + swz(kk + tg, n + g)];
                bf[ni][1] = Bs[(kk + tg + 4) * TSTR + swz(kk + tg + 4, n + g)];
            }
#pragma unroll
            for (int mi = 0; mi < 4; mi++)
#pragma unroll
                for (int ni = 0; ni < 4; ni++) mma8(c[mi][ni], af[mi], bf[ni]);
        }
        __syncthreads();
    }

#pragma unroll
    for (int mi = 0; mi < 4; mi++) {
#pragma unroll
        for (int ni = 0; ni < 4; ni++) {
            int row = m0 + wm + mi * 16 + g;
            int cb = wn + ni * 8 + 2 * tg;
            int col = n0 + cb;
            float v[4];
#pragma unroll
            for (int e = 0; e < 4; e++) v[e] = c[mi][ni][e] * alpha;
            v[0] += sbias[cb];     v[1] += sbias[cb + 1];
            v[2] += sbias[cb];     v[3] += sbias[cb + 1];
            if (ACT == 1) {
#pragma unroll
                for (int e = 0; e < 4; e++)
                    v[e] = 0.5f * v[e] * (1.f + erff(v[e] * 0.7071067811865475f));
            }
            if (RESID) {
                v[0] += resid[(long)row * ldc + col];
                v[1] += resid[(long)row * ldc + col + 1];
                v[2] += resid[(long)(row + 8) * ldc + col];
                v[3] += resid[(long)(row + 8) * ldc + col + 1];
            }
            *(float2*)&C[(long)row * ldc + col] = make_float2(v[0], v[1]);
            *(float2*)&C[(long)(row + 8) * ldc + col] = make_float2(v[2], v[3]);
        }
    }
}

// ---------------- conv weight transpose: wt[h][g][k][o] ----------------
__global__ void wt_kernel(const float* __restrict__ cw) {
    int idx = blockIdx.x * 256 + threadIdx.x;
    if (idx >= 3 * NGRP * 128 * 128) return;
    int o = idx & 127;
    int k = (idx >> 7) & 127;
    int hg = idx >> 14;
    int h = hg >> 3, grp = hg & 7;
    g_wt[idx] = cw[(((size_t)(grp * 128 + o)) * 128 + k) * 3 + h];
}

// ---------------- tensor-core grouped conv(3) + combine epilogue ----------------
// combined = (conv(v) + conv_b + 0.1*gctx + 0.5*memout) * sigmoid(keys) -> g_h
__global__ void __launch_bounds__(256, 2) conv_tc(const float* __restrict__ cb) {
    __shared__ __align__(16) uint32_t As[TBK * TSTR];
    __shared__ __align__(16) uint32_t Bs[TBK * TSTR];
    __shared__ __align__(16) float cbs[128];
    int b = blockIdx.z, grp = blockIdx.y, s0 = blockIdx.x * 128;
    int tid = threadIdx.x;
    int warp = tid >> 5, lane = tid & 31;
    int g = lane >> 2, tg = lane & 3;
    int wm = (warp & 1) * 64, wn = (warp >> 1) * 32;

    if (tid < 128) cbs[tid] = cb[grp * 128 + tid];

    float c[4][4][4];
#pragma unroll
    for (int a = 0; a < 4; a++)
#pragma unroll
        for (int d = 0; d < 4; d++)
#pragma unroll
            for (int e = 0; e < 4; e++) c[a][d][e] = 0.f;

    int arow = tid >> 3, acol = (tid & 7) * 4;

    for (int h = 0; h < 3; h++) {
        for (int k0 = 0; k0 < 128; k0 += TBK) {
#pragma unroll
            for (int p = 0; p < 4; p++) {
                int m = arow + p * 32;
                int s = s0 + m + h - 1;
                float4 v = make_float4(0.f, 0.f, 0.f, 0.f);
                if (s >= 0 && s < Ss)
                    v = *(const float4*)&g_v[((size_t)(b * Ss) + s) * Dd + grp * 128 + k0 + acol];
                As[(acol + 0) * TSTR + swz(acol + 0, m)] = f2tf32(v.x);
                As[(acol + 1) * TSTR + swz(acol + 1, m)] = f2tf32(v.y);
                As[(acol + 2) * TSTR + swz(acol + 2, m)] = f2tf32(v.z);
                As[(acol + 3) * TSTR + swz(acol + 3, m)] = f2tf32(v.w);
            }
            {
                int n = tid & 127, kb = tid >> 7;
#pragma unroll
                for (int p = 0; p < 16; p++) {
                    int k = kb + p * 2;
                    Bs[k * TSTR + swz(k, n)] =
                        f2tf32(g_wt[(((size_t)(h * NGRP + grp)) * 128 + k0 + k) * 128 + n]);
                }
            }
            __syncthreads();
#pragma unroll
            for (int ks = 0; ks < 4; ks++) {
                int kk = ks * 8;
                uint32_t af[4][4], bf[4][2];
#pragma unroll
                for (int mi = 0; mi < 4; mi++) {
                    int m = wm + mi * 16;
                    af[mi][0] = As[(kk + tg) * TSTR + swz(kk + tg, m + g)];
                    af[mi][1] = As[(kk + tg) * TSTR + swz(kk + tg, m + g + 8)];
                    af[mi][2] = As[(kk + tg + 4) * TSTR + swz(kk + tg + 4, m + g)];
                    af[mi][3] = As[(kk + tg + 4) * TSTR + swz(kk + tg + 4, m + g + 8)];
                }
#pragma unroll
                for (int ni = 0; ni < 4; ni++) {
                    int n = wn + ni * 8;
                    bf[ni][0] = Bs[(kk + tg) * TSTR + swz(kk + tg, n + g)];
                    bf[ni][1] = Bs[(kk + tg + 4) * TSTR + swz(kk + tg + 4, n + g)];
                }
#pragma unroll
                for (int mi = 0; mi < 4; mi++)
#pragma unroll
                    for (int ni = 0; ni < 4; ni++) mma8(c[mi][ni], af[mi], bf[ni]);
            }
            __syncthreads();
        }
    }

#pragma unroll
    for (int mi = 0; mi < 4; mi++) {
#pragma unroll
        for (int ni = 0; ni < 4; ni++) {
            int cbcol = wn + ni * 8 + 2 * tg;
            int o = grp * 128 + cbcol;
#pragma unroll
            for (int half = 0; half < 2; half++) {
                int s = s0 + wm + mi * 16 + g + half * 8;
                size_t idx = ((size_t)(b * Ss) + s) * Dd + o;
                float2 mo = *(const float2*)&g_memout[idx];
                float2 kv = *(const float2*)&g_k[idx];
                float gc0 = g_gctx[b * Dd + o], gc1 = g_gctx[b * Dd + o + 1];
                float l0 = c[mi][ni][half * 2 + 0] + cbs[cbcol];
                float l1 = c[mi][ni][half * 2 + 1] + cbs[cbcol + 1];
                float p0 = 1.f / (1.f + expf(-kv.x));
                float p1 = 1.f / (1.f + expf(-kv.y));
                float r0 = (l0 + 0.1f * gc0 + 0.5f * mo.x) * p0;
                float r1 = (l1 + 0.1f * gc1 + 0.5f * mo.y) * p1;
                *(float2*)&g_h[idx] = make_float2(r0, r1);
            }
        }
    }
}

// ---------------- LayerNorm + write-gate logit (fused) ----------------
__global__ void ln_imp_kernel(const float* __restrict__ x,
                              const float* __restrict__ lng,
                              const float* __restrict__ lnb,
                              const float* __restrict__ wgw,
                              const float* __restrict__ wgb) {
    int row = blockIdx.x;
    int tid = threadIdx.x;
    const float* xr = x + (size_t)row * Dd + tid * 4;
    float x0 = xr[0], x1 = xr[1], x2 = xr[2], x3 = xr[3];
    __shared__ float red[256];

    red[tid] = x0 + x1 + x2 + x3; __syncthreads();
    for (int o = 128; o > 0; o >>= 1) { if (tid < o) red[tid] += red[tid + o]; __syncthreads(); }
    float mu = red[0] * (1.f / Dd);
    __syncthreads();

    float d0 = x0 - mu, d1 = x1 - mu, d2 = x2 - mu, d3 = x3 - mu;
    red[tid] = d0 * d0 + d1 * d1 + d2 * d2 + d3 * d3; __syncthreads();
    for (int o = 128; o > 0; o >>= 1) { if (tid < o) red[tid] += red[tid + o]; __syncthreads(); }
    float var = red[0] * (1.f / Dd);
    float rs = rsqrtf(var + 1e-5f);
    __syncthreads();

    float y0 = d0 * rs * lng[tid * 4 + 0] + lnb[tid * 4 + 0];
    float y1 = d1 * rs * lng[tid * 4 + 1] + lnb[tid * 4 + 1];
    float y2 = d2 * rs * lng[tid * 4 + 2] + lnb[tid * 4 + 2];
    float y3 = d3 * rs * lng[tid * 4 + 3] + lnb[tid * 4 + 3];
    ((float4*)(g_xn + (size_t)row * Dd))[tid] = make_float4(y0, y1, y2, y3);

    red[tid] = y0 * wgw[tid * 4 + 0] + y1 * wgw[tid * 4 + 1]
             + y2 * wgw[tid * 4 + 2] + y3 * wgw[tid * 4 + 3];
    __syncthreads();
    for (int o = 128; o > 0; o >>= 1) { if (tid < o) red[tid] += red[tid + o]; __syncthreads(); }
    if (tid == 0) {
        double l = (double)(red[0] + wgb[0]);
        g_sig[row] = (float)(1.0 / (1.0 + exp(-l)));
    }
}

// ---------------- per-batch full bitonic sort -> top-1024 indices ----------------
__global__ void topk_kernel() {
    __shared__ __align__(16) unsigned long long sk[Ss];
    int b = blockIdx.x, tid = threadIdx.x;
    for (int i = tid; i < Ss; i += 1024) {
        unsigned u = __float_as_uint(g_sig[b * Ss + i]);
        u = (u & 0x80000000u) ? ~u : (u | 0x80000000u);
        sk[i] = ((unsigned long long)u << 32) | (unsigned)(0xFFFFFFFFu - i);
    }
    __syncthreads();
    for (int k = 2; k <= Ss; k <<= 1) {
        for (int j = k >> 1; j > 0; j >>= 1) {
            for (int i = tid; i < Ss; i += 1024) {
                int ixj = i ^ j;
                if (ixj > i) {
                    bool desc = ((i & k) == 0);
                    unsigned long long a = sk[i], c = sk[ixj];
                    if ((a < c) == desc) { sk[i] = c; sk[ixj] = a; }
                }
            }
            __syncthreads();
        }
    }
    for (int i = tid; i < NWRITES; i += 1024)
        g_topidx[b * NWRITES + i] = (int)(0xFFFFFFFFu - (unsigned)sk[i]);
}

// ---------------- splice memory -> d_out ----------------
__global__ void assemble_kernel(const float* __restrict__ md, float* __restrict__ om) {
    int idx = blockIdx.x * blockDim.x + threadIdx.x;
    if (idx >= Bb * Mm * 256) return;
    int c = idx & 255;
    int m = (idx >> 8) & (Mm - 1);
    int b = idx >> 19;
    float val;
    if (m < KEEP) val = md[idx];
    else {
        int id = g_topidx[b * NWRITES + (m - KEEP)];
        val = (c < Kk) ? g_memk[((size_t)(b * Ss) + id) * Kk + c]
                       : g_memv[((size_t)(b * Ss) + id) * Vv + (c - Kk)];
    }
    om[idx] = val;
}

// ---------------- small SIMT GEMM (only for M=4 gctx) ----------------
#define BM 64
#define BN 64
#define BKg 16
template <int TRANSB, int ACT, int RESID>
__global__ void gemm_k(const float* __restrict__ A, int lda, long sA,
                       const float* __restrict__ Bm, int ldb, long sB,
                       const float* __restrict__ bias,
                       const float* __restrict__ resid,
                       float* __restrict__ C, int ldc, long sC,
                       int Mr, int Kd, float alpha) {
    __shared__ __align__(16) float As[BKg][BM + 4];
    __shared__ __align__(16) float Bs[BKg][BN + 4];
    __shared__ __align__(16) float sbias[BN];
    long bz = blockIdx.z;
    A += bz * sA; Bm += bz * sB; C += bz * sC;
    if (RESID) resid += bz * sC;
    int n0 = blockIdx.x * BN, m0 = blockIdx.y * BM;
    int tid = threadIdx.x;
    int tx = tid & 15, ty = tid >> 4;

    if (tid < BN) sbias[tid] = bias ? bias[n0 + tid] : 0.f;

    float acc[4][4];
#pragma unroll
    for (int i = 0; i < 4; i++)
#pragma unroll
        for (int j = 0; j < 4; j++) acc[i][j] = 0.f;

    int aRow = tid >> 2, aCol = (tid & 3) * 4;

    for (int k0 = 0; k0 < Kd; k0 += BKg) {
        float4 av = make_float4(0.f, 0.f, 0.f, 0.f);
        if (m0 + aRow < Mr)
            av = *(const float4*)&A[(long)(m0 + aRow) * lda + k0 + aCol];
        As[aCol + 0][aRow] = av.x; As[aCol + 1][aRow] = av.y;
        As[aCol + 2][aRow] = av.z; As[aCol + 3][aRow] = av.w;

        if (TRANSB) {
            int n = tid >> 2, kc = (tid & 3) * 4;
            const float* bp = &Bm[(long)(n0 + n) * ldb + k0 + kc];
            Bs[kc + 0][n] = bp[0]; Bs[kc + 1][n] = bp[1];
            Bs[kc + 2][n] = bp[2]; Bs[kc + 3][n] = bp[3];
        } else {
            int kr = tid >> 4, n = (tid & 15) * 4;
            const float* bp = &Bm[(long)(k0 + kr) * ldb + n0 + n];
            Bs[kr][n + 0] = bp[0]; Bs[kr][n + 1] = bp[1];
            Bs[kr][n + 2] = bp[2]; Bs[kr][n + 3] = bp[3];
        }
        __syncthreads();

#pragma unroll
        for (int kk = 0; kk < BKg; kk++) {
            const float4 a = *(const float4*)&As[kk][ty * 4];
            const float4 b4 = *(const float4*)&Bs[kk][tx * 4];
            float ar[4] = {a.x, a.y, a.z, a.w};
            float br[4] = {b4.x, b4.y, b4.z, b4.w};
#pragma unroll
            for (int ii = 0; ii < 4; ii++)
#pragma unroll
                for (int jj = 0; jj < 4; jj++) acc[ii][jj] += ar[ii] * br[jj];
        }
        __syncthreads();
    }

#pragma unroll
    for (int i = 0; i < 4; i++) {
        int m = m0 + ty * 4 + i;
        if (m >= Mr) break;
#pragma unroll
        for (int j = 0; j < 4; j++) {
            int n = n0 + tx * 4 + j;
            float v = acc[i][j] * alpha + sbias[tx * 4 + j];
            if (ACT == 1) v = 0.5f * v * (1.f + erff(v * 0.7071067811865475f));
            if (RESID) v += resid[(long)m * ldc + n];
            C[(long)m * ldc + n] = v;
        }
    }
}

// ---------------- row softmax over M=2048 ----------------
__global__ void softmax_kernel(float* __restrict__ sim) {
    long row = blockIdx.x;
    float* p = sim + row * (long)Mm;
    int tid = threadIdx.x;
    float v[8];
    float mx = -3.4e38f;
#pragma unroll
    for (int t = 0; t < 8; t++) { v[t] = p[tid + t * 256]; mx = fmaxf(mx, v[t]); }
    __shared__ float red[256];
    red[tid] = mx; __syncthreads();
    for (int o = 128; o > 0; o >>= 1) { if (tid < o) red[tid] = fmaxf(red[tid], red[tid + o]); __syncthreads(); }
    mx = red[0]; __syncthreads();
    float s = 0.f;
#pragma unroll
    for (int t = 0; t < 8; t++) { v[t] = expf(v[t] - mx); s += v[t]; }
    red[tid] = s; __syncthreads();
    for (int o = 128; o > 0; o >>= 1) { if (tid < o) red[tid] += red[tid + o]; __syncthreads(); }
    float inv = 1.f / red[0];
#pragma unroll
    for (int t = 0; t < 8; t++) p[tid + t * 256] = v[t] * inv;
}

// ---------------- mean over S of queries ----------------
__global__ void qmean_kernel() {
    int d = blockIdx.x * 256 + threadIdx.x;
    int b = blockIdx.y;
    const float* p = g_q + (size_t)b * Ss * Dd + d;
    double s = 0.0;
    for (int t = 0; t < Ss; t++) s += p[(size_t)t * Dd];
    g_qmean[b * Dd + d] = (float)(s * (1.0 / Ss));
}

// ---------------- launch ----------------
extern "C" void kernel_launch(void* const* d_in, const int* in_sizes, int n_in,
                              void* d_out, int out_size) {
    const float* x      = (const float*)d_in[0];
    const float* memdict= (const float*)d_in[1];
    const float* ln_g   = (const float*)d_in[2];
    const float* ln_b   = (const float*)d_in[3];
    const float* mk_w1  = (const float*)d_in[4];
    const float* mk_b1  = (const float*)d_in[5];
    const float* mk_w2  = (const float*)d_in[6];
    const float* mk_b2  = (const float*)d_in[7];
    const float* mv_w1  = (const float*)d_in[8];
    const float* mv_b1  = (const float*)d_in[9];
    const float* mv_w2  = (const float*)d_in[10];
    const float* mv_b2  = (const float*)d_in[11];
    const float* mq_w1  = (const float*)d_in[12];
    const float* mq_b1  = (const float*)d_in[13];
    const float* mq_w2  = (const float*)d_in[14];
    const float* mq_b2  = (const float*)d_in[15];
    const float* wg_w   = (const float*)d_in[16];
    const float* wg_b   = (const float*)d_in[17];
    const float* q_w    = (const float*)d_in[18];
    const float* k_w    = (const float*)d_in[19];
    const float* v_w    = (const float*)d_in[20];
    const float* conv_w = (const float*)d_in[21];
    const float* conv_b = (const float*)d_in[22];
    const float* gp_w   = (const float*)d_in[23];
    const float* gp_b   = (const float*)d_in[24];
    const float* mr_w   = (const float*)d_in[25];
    const float* mr_b   = (const float*)d_in[26];
    const float* out_w  = (const float*)d_in[27];
    const float* out_b  = (const float*)d_in[28];

    float* out_main = (float*)d_out;
    float* out_mem  = out_main + (size_t)Bb * Ss * Dd;

    float *p_xn, *p_h, *p_memk, *p_memv, *p_memq, *p_q, *p_k, *p_v, *p_sim, *p_retr, *p_memout, *p_qmean, *p_gctx;
    cudaGetSymbolAddress((void**)&p_xn, g_xn);
    cudaGetSymbolAddress((void**)&p_h, g_h);
    cudaGetSymbolAddress((void**)&p_memk, g_memk);
    cudaGetSymbolAddress((void**)&p_memv, g_memv);
    cudaGetSymbolAddress((void**)&p_memq, g_memq);
    cudaGetSymbolAddress((void**)&p_q, g_q);
    cudaGetSymbolAddress((void**)&p_k, g_k);
    cudaGetSymbolAddress((void**)&p_v, g_v);
    cudaGetSymbolAddress((void**)&p_sim, g_sim);
    cudaGetSymbolAddress((void**)&p_retr, g_retr);
    cudaGetSymbolAddress((void**)&p_memout, g_memout);
    cudaGetSymbolAddress((void**)&p_qmean, g_qmean);
    cudaGetSymbolAddress((void**)&p_gctx, g_gctx);

    const int ROWS = Bb * Ss;           // 16384
    dim3 thr(256);

    // 1) LN + write-gate; conv weight transpose
    ln_imp_kernel<<<ROWS, 256>>>(x, ln_g, ln_b, wg_w, wg_b);
    wt_kernel<<<(3 * NGRP * 128 * 128 + 255) / 256, 256>>>(conv_w);
    // 2) top-k per batch
    topk_kernel<<<Bb, 1024>>>();

    // 3) mem_keys MLP
    gemm_tc<0, 1, 0><<<dim3(8, 128), thr>>>(p_xn, Dd, 0, mk_w1, Dd, 0, mk_b1, nullptr, p_h, Dd, 0, Dd, 1.f);
    gemm_tc<0, 0, 0><<<dim3(1, 128), thr>>>(p_h, Dd, 0, mk_w2, Kk, 0, mk_b2, nullptr, p_memk, Kk, 0, Dd, 1.f);
    // 4) mem_values MLP
    gemm_tc<0, 1, 0><<<dim3(8, 128), thr>>>(p_xn, Dd, 0, mv_w1, Dd, 0, mv_b1, nullptr, p_h, Dd, 0, Dd, 1.f);
    gemm_tc<0, 0, 0><<<dim3(1, 128), thr>>>(p_h, Dd, 0, mv_w2, Vv, 0, mv_b2, nullptr, p_memv, Vv, 0, Dd, 1.f);
    // 5) splice memory into d_out
    assemble_kernel<<<(Bb * Mm * 256 + 255) / 256, 256>>>(memdict, out_mem);
    // 6) mem_queries MLP
    gemm_tc<0, 1, 0><<<dim3(8, 128), thr>>>(p_xn, Dd, 0, mq_w1, Dd, 0, mq_b1, nullptr, p_h, Dd, 0, Dd, 1.f);
    gemm_tc<0, 0, 0><<<dim3(1, 128), thr>>>(p_h, Dd, 0, mq_w2, Kk, 0, mq_b2, nullptr, p_memq, Kk, 0, Dd, 1.f);

    // 7) sim = q @ K^T / sqrt(K)  (batched; B rows = memory entries in d_out)
    gemm_tc<1, 0, 0><<<dim3(16, 32, Bb), thr>>>(p_memq, Kk, (long)Ss * Kk,
                                                out_mem, 256, (long)Mm * 256,
                                                nullptr, nullptr,
                                                p_sim, Mm, (long)Ss * Mm,
                                                Kk, 0.08838834764831845f);
    // 8) softmax rows
    softmax_kernel<<<ROWS, 256>>>(p_sim);
    // 9) retrieved = attn @ V
    gemm_tc<0, 0, 0><<<dim3(1, 32, Bb), thr>>>(p_sim, Mm, (long)Ss * Mm,
                                               out_mem + Kk, 256, (long)Mm * 256,
                                               nullptr, nullptr,
                                               p_retr, Vv, (long)Ss * Vv,
                                               Mm, 1.f);
    // 10) memory_output = retrieved @ mr_w + mr_b
    gemm_tc<0, 0, 0><<<dim3(8, 128), thr>>>(p_retr, Vv, 0, mr_w, Dd, 0, mr_b, nullptr, p_memout, Dd, 0, Vv, 1.f);

    // 11) q, k, v projections
    gemm_tc<0, 0, 0><<<dim3(8, 128), thr>>>(p_xn, Dd, 0, q_w, Dd, 0, nullptr, nullptr, p_q, Dd, 0, Dd, 1.f);
    gemm_tc<0, 0, 0><<<dim3(8, 128), thr>>>(p_xn, Dd, 0, k_w, Dd, 0, nullptr, nullptr, p_k, Dd, 0, Dd, 1.f);
    gemm_tc<0, 0, 0><<<dim3(8, 128), thr>>>(p_xn, Dd, 0, v_w, Dd, 0, nullptr, nullptr, p_v, Dd, 0, Dd, 1.f);

    // 12) mean(queries); 13) global ctx projection (M=4, SIMT)
    qmean_kernel<<<dim3(Dd / 256, Bb), 256>>>();
    gemm_k<0, 0, 0><<<dim3(Dd / BN, 1, 1), thr>>>(p_qmean, Dd, 0, gp_w, Dd, 0, gp_b, nullptr, p_gctx, Dd, 0, Bb, Dd, 1.f);

    // 14) conv + combine -> g_h  (tensor-core)
    conv_tc<<<dim3(Ss / 128, NGRP, Bb), thr>>>(conv_b);

    // 15) output = combined @ out_w + out_b + residual(x)
    gemm_tc<0, 0, 1><<<dim3(8, 128), thr>>>(p_h, Dd, 0, out_w, Dd, 0, out_b, x, out_main, Dd, 0, Dd, 1.f);
}

// round 7
// speedup vs baseline: 3.1599x; 1.2141x over previous
#include <cuda_runtime.h>
#include <math.h>
#include <stdint.h>

#define Bb 4
#define Ss 4096
#define Dd 1024
#define Mm 2048
#define Kk 128
#define Vv 128
#define NGRP 8
#define NWRITES 1024
#define KEEP 1024

// ---------------- scratch (device globals; no allocations) ----------------
__device__ __align__(16) float g_xn[Bb * Ss * Dd];
__device__ __align__(16) float g_h[Bb * Ss * Dd];
__device__ __align__(16) float g_memk[Bb * Ss * Kk];
__device__ __align__(16) float g_memv[Bb * Ss * Vv];
__device__ __align__(16) float g_memq[Bb * Ss * Kk];
__device__ __align__(16) float g_sig[Bb * Ss];
__device__ __align__(16) int   g_topidx[Bb * NWRITES];
__device__ __align__(16) float g_q[Bb * Ss * Dd];
__device__ __align__(16) float g_k[Bb * Ss * Dd];
__device__ __align__(16) float g_v[Bb * Ss * Dd];
__device__ __align__(16) float g_sim[(size_t)Bb * Ss * Mm];
__device__ __align__(16) float g_retr[Bb * Ss * Vv];
__device__ __align__(16) float g_memout[Bb * Ss * Dd];
__device__ __align__(16) float g_qmean[Bb * Dd];
__device__ __align__(16) float g_gctx[Bb * Dd];
__device__ __align__(16) float g_wt[3 * NGRP * 128 * 128];

// ---------------- mma / cp.async helpers ----------------
__device__ __forceinline__ void mma8(float* c, const uint32_t* a, const uint32_t* b) {
    asm volatile(
        "mma.sync.aligned.m16n8k8.row.col.f32.tf32.tf32.f32 "
        "{%0,%1,%2,%3}, {%4,%5,%6,%7}, {%8,%9}, {%0,%1,%2,%3};\n"
        : "+f"(c[0]), "+f"(c[1]), "+f"(c[2]), "+f"(c[3])
        : "r"(a[0]), "r"(a[1]), "r"(a[2]), "r"(a[3]), "r"(b[0]), "r"(b[1]));
}
__device__ __forceinline__ void cpa16(uint32_t dst, const float* src) {
    asm volatile("cp.async.cg.shared.global [%0], [%1], 16;\n" :: "r"(dst), "l"(src));
}
__device__ __forceinline__ void cpa4(uint32_t dst, const float* src) {
    asm volatile("cp.async.ca.shared.global [%0], [%1], 4;\n" :: "r"(dst), "l"(src));
}
#define CP_COMMIT asm volatile("cp.async.commit_group;\n" ::: "memory")
#define CP_WAIT0  asm volatile("cp.async.wait_group 0;\n" ::: "memory")

// gemm tile geometry
#define GTM 128
#define GTN 128
#define GTK 16
#define ASTR 20          // [m][k] row stride: banks 4g+tg -> conflict-free
#define BSTR 136         // [k][n] row stride: banks 8tg+g -> conflict-free
#define ASTAGE (128 * ASTR)    // 2560 words
#define BSTAGE 2560            // max(128*20, 16*136)

// staging: A always 16B cp.async (scratch); B: 16B if B16 else 4B
template <int TRANSB, int B16>
__device__ __forceinline__ void stage_tile(
    const float* __restrict__ A, int lda, int m0,
    const float* __restrict__ Bm, int ldb, int n0,
    uint32_t asb, uint32_t bsb, int tid, int k0, int st)
{
    uint32_t ad = asb + st * (ASTAGE * 4);
    int c = tid;
#pragma unroll
    for (int p = 0; p < 2; p++, c += 256) {
        int m = c >> 2, ko = (c & 3) * 4;
        cpa16(ad + (uint32_t)(m * ASTR + ko) * 4, A + (long)(m0 + m) * lda + k0 + ko);
    }
    uint32_t bd = bsb + st * (BSTAGE * 4);
    if (TRANSB) {                 // B rows are N: shared [n][k] stride ASTR
        int c2 = tid;
#pragma unroll
        for (int p = 0; p < 2; p++, c2 += 256) {
            int n = c2 >> 2, ko = (c2 & 3) * 4;
            cpa16(bd + (uint32_t)(n * ASTR + ko) * 4, Bm + (long)(n0 + n) * ldb + k0 + ko);
        }
    } else if (B16) {             // shared [k][n] stride BSTR
        int c2 = tid;
#pragma unroll
        for (int p = 0; p < 2; p++, c2 += 256) {
            int k = c2 >> 5, no = (c2 & 31) * 4;
            cpa16(bd + (uint32_t)(k * BSTR + no) * 4, Bm + (long)(k0 + k) * ldb + n0 + no);
        }
    } else {
        int e = tid;
#pragma unroll
        for (int p = 0; p < 8; p++, e += 256) {
            int k = e >> 7, n = e & 127;
            cpa4(bd + (uint32_t)(k * BSTR + n) * 4, Bm + (long)(k0 + k) * ldb + n0 + n);
        }
    }
    CP_COMMIT;
}

// ---------------- tf32 tensor-core GEMM, cp.async double-buffered ----------------
// C = act(alpha*A@op(B) + bias) [+ resid].  M%128==0, N%128==0, K%16==0.
template <int TRANSB, int ACT, int RESID, int B16>
__global__ void __launch_bounds__(256, 2) gemm_tc(
    const float* __restrict__ A, int lda, long sA,
    const float* __restrict__ Bm, int ldb, long sB,
    const float* __restrict__ bias,
    const float* __restrict__ resid,
    float* __restrict__ C, int ldc, long sC,
    int Kd, float alpha)
{
    __shared__ __align__(16) float sh[2 * ASTAGE + 2 * BSTAGE];   // 40 KB
    __shared__ __align__(16) float sbias[GTN];
    long bz = blockIdx.z;
    A += bz * sA; Bm += bz * sB; C += bz * sC;
    if (RESID) resid += bz * sC;
    int n0 = blockIdx.x * GTN, m0 = blockIdx.y * GTM;
    int tid = threadIdx.x;
    int warp = tid >> 5, lane = tid & 31;
    int g = lane >> 2, tg = lane & 3;
    int wm = (warp & 1) * 64, wn = (warp >> 1) * 32;

    if (tid < GTN) sbias[tid] = bias ? bias[n0 + tid] : 0.f;

    uint32_t asb = (uint32_t)__cvta_generic_to_shared(sh);
    uint32_t bsb = asb + 2 * ASTAGE * 4;

    float c[4][4][4];
#pragma unroll
    for (int a = 0; a < 4; a++)
#pragma unroll
        for (int b = 0; b < 4; b++)
#pragma unroll
            for (int e = 0; e < 4; e++) c[a][b][e] = 0.f;

    int nt = Kd >> 4;
    stage_tile<TRANSB, B16>(A, lda, m0, Bm, ldb, n0, asb, bsb, tid, 0, 0);

    for (int t = 0; t < nt; t++) {
        CP_WAIT0;
        __syncthreads();
        if (t + 1 < nt)
            stage_tile<TRANSB, B16>(A, lda, m0, Bm, ldb, n0, asb, bsb, tid,
                                    (t + 1) * GTK, (t + 1) & 1);
        const float* Ast = sh + (t & 1) * ASTAGE;
        const float* Bst = sh + 2 * ASTAGE + (t & 1) * BSTAGE;
#pragma unroll
        for (int ks = 0; ks < 2; ks++) {
            const int kk = ks * 8;
            uint32_t af[4][4], bf[4][2];
#pragma unroll
            for (int mi = 0; mi < 4; mi++) {
                const float* ap = Ast + (wm + mi * 16 + g) * ASTR + kk + tg;
                af[mi][0] = __float_as_uint(ap[0]);
                af[mi][1] = __float_as_uint(ap[8 * ASTR]);
                af[mi][2] = __float_as_uint(ap[4]);
                af[mi][3] = __float_as_uint(ap[8 * ASTR + 4]);
            }
#pragma unroll
            for (int ni = 0; ni < 4; ni++) {
                if (TRANSB) {
                    const float* bp = Bst + (wn + ni * 8 + g) * ASTR + kk + tg;
                    bf[ni][0] = __float_as_uint(bp[0]);
                    bf[ni][1] = __float_as_uint(bp[4]);
                } else {
                    const float* bp = Bst + (kk + tg) * BSTR + wn + ni * 8 + g;
                    bf[ni][0] = __float_as_uint(bp[0]);
                    bf[ni][1] = __float_as_uint(bp[4 * BSTR]);
                }
            }
#pragma unroll
            for (int mi = 0; mi < 4; mi++)
#pragma unroll
                for (int ni = 0; ni < 4; ni++) mma8(c[mi][ni], af[mi], bf[ni]);
        }
        __syncthreads();
    }

#pragma unroll
    for (int mi = 0; mi < 4; mi++) {
#pragma unroll
        for (int ni = 0; ni < 4; ni++) {
            int row = m0 + wm + mi * 16 + g;
            int cb = wn + ni * 8 + 2 * tg;
            int col = n0 + cb;
            float v[4];
#pragma unroll
            for (int e = 0; e < 4; e++) v[e] = c[mi][ni][e] * alpha;
            v[0] += sbias[cb];     v[1] += sbias[cb + 1];
            v[2] += sbias[cb];     v[3] += sbias[cb + 1];
            if (ACT == 1) {
#pragma unroll
                for (int e = 0; e < 4; e++)
                    v[e] = 0.5f * v[e] * (1.f + erff(v[e] * 0.7071067811865475f));
            }
            if (RESID) {
                v[0] += resid[(long)row * ldc + col];
                v[1] += resid[(long)row * ldc + col + 1];
                v[2] += resid[(long)(row + 8) * ldc + col];
                v[3] += resid[(long)(row + 8) * ldc + col + 1];
            }
            *(float2*)&C[(long)row * ldc + col] = make_float2(v[0], v[1]);
            *(float2*)&C[(long)(row + 8) * ldc + col] = make_float2(v[2], v[3]);
        }
    }
}

// ---------------- conv (unchanged from R6, known-good) ----------------
#define TBK 32
#define TSTR 136
__device__ __forceinline__ int swz(int k, int m) { return m ^ (((k >> 2) & 7) << 2); }
__device__ __forceinline__ uint32_t f2tf32(float f) {
    uint32_t u;
    asm("cvt.rna.tf32.f32 %0, %1;" : "=r"(u) : "f"(f));
    return u;
}

__global__ void wt_kernel(const float* __restrict__ cw) {
    int idx = blockIdx.x * 256 + threadIdx.x;
    if (idx >= 3 * NGRP * 128 * 128) return;
    int o = idx & 127;
    int k = (idx >> 7) & 127;
    int hg = idx >> 14;
    int h = hg >> 3, grp = hg & 7;
    g_wt[idx] = cw[(((size_t)(grp * 128 + o)) * 128 + k) * 3 + h];
}

__global__ void __launch_bounds__(256, 2) conv_tc(const float* __restrict__ cb) {
    __shared__ __align__(16) uint32_t As[TBK * TSTR];
    __shared__ __align__(16) uint32_t Bs[TBK * TSTR];
    __shared__ __align__(16) float cbs[128];
    int b = blockIdx.z, grp = blockIdx.y, s0 = blockIdx.x * 128;
    int tid = threadIdx.x;
    int warp = tid >> 5, lane = tid & 31;
    int g = lane >> 2, tg = lane & 3;
    int wm = (warp & 1) * 64, wn = (warp >> 1) * 32;

    if (tid < 128) cbs[tid] = cb[grp * 128 + tid];

    float c[4][4][4];
#pragma unroll
    for (int a = 0; a < 4; a++)
#pragma unroll
        for (int d = 0; d < 4; d++)
#pragma unroll
            for (int e = 0; e < 4; e++) c[a][d][e] = 0.f;

    int arow = tid >> 3, acol = (tid & 7) * 4;

    for (int h = 0; h < 3; h++) {
        for (int k0 = 0; k0 < 128; k0 += TBK) {
#pragma unroll
            for (int p = 0; p < 4; p++) {
                int m = arow + p * 32;
                int s = s0 + m + h - 1;
                float4 v = make_float4(0.f, 0.f, 0.f, 0.f);
                if (s >= 0 && s < Ss)
                    v = *(const float4*)&g_v[((size_t)(b * Ss) + s) * Dd + grp * 128 + k0 + acol];
                As[(acol + 0) * TSTR + swz(acol + 0, m)] = f2tf32(v.x);
                As[(acol + 1) * TSTR + swz(acol + 1, m)] = f2tf32(v.y);
                As[(acol + 2) * TSTR + swz(acol + 2, m)] = f2tf32(v.z);
                As[(acol + 3) * TSTR + swz(acol + 3, m)] = f2tf32(v.w);
            }
            {
                int n = tid & 127, kb = tid >> 7;
#pragma unroll
                for (int p = 0; p < 16; p++) {
                    int k = kb + p * 2;
                    Bs[k * TSTR + swz(k, n)] =
                        f2tf32(g_wt[(((size_t)(h * NGRP + grp)) * 128 + k0 + k) * 128 + n]);
                }
            }
            __syncthreads();
#pragma unroll
            for (int ks = 0; ks < 4; ks++) {
                int kk = ks * 8;
                uint32_t af[4][4], bf[4][2];
#pragma unroll
                for (int mi = 0; mi < 4; mi++) {
                    int m = wm + mi * 16;
                    af[mi][0] = As[(kk + tg) * TSTR + swz(kk + tg, m + g)];
                    af[mi][1] = As[(kk + tg) * TSTR + swz(kk + tg, m + g + 8)];
                    af[mi][2] = As[(kk + tg + 4) * TSTR + swz(kk + tg + 4, m + g)];
                    af[mi][3] = As[(kk + tg + 4) * TSTR + swz(kk + tg + 4, m + g + 8)];
                }
#pragma unroll
                for (int ni = 0; ni < 4; ni++) {
                    int n = wn + ni * 8;
                    bf[ni][0] = Bs[(kk + tg) * TSTR + swz(kk + tg, n + g)];
                    bf[ni][1] = Bs[(kk + tg + 4) * TSTR + swz(kk + tg + 4, n + g)];
                }
#pragma unroll
                for (int mi = 0; mi < 4; mi++)
#pragma unroll
                    for (int ni = 0; ni < 4; ni++) mma8(c[mi][ni], af[mi], bf[ni]);
            }
            __syncthreads();
        }
    }

#pragma unroll
    for (int mi = 0; mi < 4; mi++) {
#pragma unroll
        for (int ni = 0; ni < 4; ni++) {
            int cbcol = wn + ni * 8 + 2 * tg;
            int o = grp * 128 + cbcol;
#pragma unroll
            for (int half = 0; half < 2; half++) {
                int s = s0 + wm + mi * 16 + g + half * 8;
                size_t idx = ((size_t)(b * Ss) + s) * Dd + o;
                float2 mo = *(const float2*)&g_memout[idx];
                float2 kv = *(const float2*)&g_k[idx];
                float gc0 = g_gctx[b * Dd + o], gc1 = g_gctx[b * Dd + o + 1];
                float l0 = c[mi][ni][half * 2 + 0] + cbs[cbcol];
                float l1 = c[mi][ni][half * 2 + 1] + cbs[cbcol + 1];
                float p0 = 1.f / (1.f + expf(-kv.x));
                float p1 = 1.f / (1.f + expf(-kv.y));
                float r0 = (l0 + 0.1f * gc0 + 0.5f * mo.x) * p0;
                float r1 = (l1 + 0.1f * gc1 + 0.5f * mo.y) * p1;
                *(float2*)&g_h[idx] = make_float2(r0, r1);
            }
        }
    }
}

// ---------------- LayerNorm + write-gate ----------------
__global__ void ln_imp_kernel(const float* __restrict__ x,
                              const float* __restrict__ lng,
                              const float* __restrict__ lnb,
                              const float* __restrict__ wgw,
                              const float* __restrict__ wgb) {
    int row = blockIdx.x;
    int tid = threadIdx.x;
    const float* xr = x + (size_t)row * Dd + tid * 4;
    float x0 = xr[0], x1 = xr[1], x2 = xr[2], x3 = xr[3];
    __shared__ float red[256];

    red[tid] = x0 + x1 + x2 + x3; __syncthreads();
    for (int o = 128; o > 0; o >>= 1) { if (tid < o) red[tid] += red[tid + o]; __syncthreads(); }
    float mu = red[0] * (1.f / Dd);
    __syncthreads();

    float d0 = x0 - mu, d1 = x1 - mu, d2 = x2 - mu, d3 = x3 - mu;
    red[tid] = d0 * d0 + d1 * d1 + d2 * d2 + d3 * d3; __syncthreads();
    for (int o = 128; o > 0; o >>= 1) { if (tid < o) red[tid] += red[tid + o]; __syncthreads(); }
    float var = red[0] * (1.f / Dd);
    float rs = rsqrtf(var + 1e-5f);
    __syncthreads();

    float y0 = d0 * rs * lng[tid * 4 + 0] + lnb[tid * 4 + 0];
    float y1 = d1 * rs * lng[tid * 4 + 1] + lnb[tid * 4 + 1];
    float y2 = d2 * rs * lng[tid * 4 + 2] + lnb[tid * 4 + 2];
    float y3 = d3 * rs * lng[tid * 4 + 3] + lnb[tid * 4 + 3];
    ((float4*)(g_xn + (size_t)row * Dd))[tid] = make_float4(y0, y1, y2, y3);

    red[tid] = y0 * wgw[tid * 4 + 0] + y1 * wgw[tid * 4 + 1]
             + y2 * wgw[tid * 4 + 2] + y3 * wgw[tid * 4 + 3];
    __syncthreads();
    for (int o = 128; o > 0; o >>= 1) { if (tid < o) red[tid] += red[tid + o]; __syncthreads(); }
    if (tid == 0) {
        double l = (double)(red[0] + wgb[0]);
        g_sig[row] = (float)(1.0 / (1.0 + exp(-l)));
    }
}

// ---------------- top-k ----------------
__global__ void topk_kernel() {
    __shared__ __align__(16) unsigned long long sk[Ss];
    int b = blockIdx.x, tid = threadIdx.x;
    for (int i = tid; i < Ss; i += 1024) {
        unsigned u = __float_as_uint(g_sig[b * Ss + i]);
        u = (u & 0x80000000u) ? ~u : (u | 0x80000000u);
        sk[i] = ((unsigned long long)u << 32) | (unsigned)(0xFFFFFFFFu - i);
    }
    __syncthreads();
    for (int k = 2; k <= Ss; k <<= 1) {
        for (int j = k >> 1; j > 0; j >>= 1) {
            for (int i = tid; i < Ss; i += 1024) {
                int ixj = i ^ j;
                if (ixj > i) {
                    bool desc = ((i & k) == 0);
                    unsigned long long a = sk[i], c = sk[ixj];
                    if ((a < c) == desc) { sk[i] = c; sk[ixj] = a; }
                }
            }
            __syncthreads();
        }
    }
    for (int i = tid; i < NWRITES; i += 1024)
        g_topidx[b * NWRITES + i] = (int)(0xFFFFFFFFu - (unsigned)sk[i]);
}

// ---------------- splice memory -> d_out ----------------
__global__ void assemble_kernel(const float* __restrict__ md, float* __restrict__ om) {
    int idx = blockIdx.x * blockDim.x + threadIdx.x;
    if (idx >= Bb * Mm * 256) return;
    int c = idx & 255;
    int m = (idx >> 8) & (Mm - 1);
    int b = idx >> 19;
    float val;
    if (m < KEEP) val = md[idx];
    else {
        int id = g_topidx[b * NWRITES + (m - KEEP)];
        val = (c < Kk) ? g_memk[((size_t)(b * Ss) + id) * Kk + c]
                       : g_memv[((size_t)(b * Ss) + id) * Vv + (c - Kk)];
    }
    om[idx] = val;
}

// ---------------- small SIMT GEMM (M=4 gctx only) ----------------
#define BM 64
#define BN 64
#define BKg 16
template <int TRANSB, int ACT, int RESID>
__global__ void gemm_k(const float* __restrict__ A, int lda, long sA,
                       const float* __restrict__ Bm, int ldb, long sB,
                       const float* __restrict__ bias,
                       const float* __restrict__ resid,
                       float* __restrict__ C, int ldc, long sC,
                       int Mr, int Kd, float alpha) {
    __shared__ __align__(16) float As[BKg][BM + 4];
    __shared__ __align__(16) float Bs[BKg][BN + 4];
    __shared__ __align__(16) float sbias[BN];
    long bz = blockIdx.z;
    A += bz * sA; Bm += bz * sB; C += bz * sC;
    if (RESID) resid += bz * sC;
    int n0 = blockIdx.x * BN, m0 = blockIdx.y * BM;
    int tid = threadIdx.x;
    int tx = tid & 15, ty = tid >> 4;

    if (tid < BN) sbias[tid] = bias ? bias[n0 + tid] : 0.f;

    float acc[4][4];
#pragma unroll
    for (int i = 0; i < 4; i++)
#pragma unroll
        for (int j = 0; j < 4; j++) acc[i][j] = 0.f;

    int aRow = tid >> 2, aCol = (tid & 3) * 4;

    for (int k0 = 0; k0 < Kd; k0 += BKg) {
        float4 av = make_float4(0.f, 0.f, 0.f, 0.f);
        if (m0 + aRow < Mr)
            av = *(const float4*)&A[(long)(m0 + aRow) * lda + k0 + aCol];
        As[aCol + 0][aRow] = av.x; As[aCol + 1][aRow] = av.y;
        As[aCol + 2][aRow] = av.z; As[aCol + 3][aRow] = av.w;

        if (TRANSB) {
            int n = tid >> 2, kc = (tid & 3) * 4;
            const float* bp = &Bm[(long)(n0 + n) * ldb + k0 + kc];
            Bs[kc + 0][n] = bp[0]; Bs[kc + 1][n] = bp[1];
            Bs[kc + 2][n] = bp[2]; Bs[kc + 3][n] = bp[3];
        } else {
            int kr = tid >> 4, n = (tid & 15) * 4;
            const float* bp = &Bm[(long)(k0 + kr) * ldb + n0 + n];
            Bs[kr][n + 0] = bp[0]; Bs[kr][n + 1] = bp[1];
            Bs[kr][n + 2] = bp[2]; Bs[kr][n + 3] = bp[3];
        }
        __syncthreads();

#pragma unroll
        for (int kk = 0; kk < BKg; kk++) {
            const float4 a = *(const float4*)&As[kk][ty * 4];
            const float4 b4 = *(const float4*)&Bs[kk][tx * 4];
            float ar[4] = {a.x, a.y, a.z, a.w};
            float br[4] = {b4.x, b4.y, b4.z, b4.w};
#pragma unroll
            for (int ii = 0; ii < 4; ii++)
#pragma unroll
                for (int jj = 0; jj < 4; jj++) acc[ii][jj] += ar[ii] * br[jj];
        }
        __syncthreads();
    }

#pragma unroll
    for (int i = 0; i < 4; i++) {
        int m = m0 + ty * 4 + i;
        if (m >= Mr) break;
#pragma unroll
        for (int j = 0; j < 4; j++) {
            int n = n0 + tx * 4 + j;
            float v = acc[i][j] * alpha + sbias[tx * 4 + j];
            if (ACT == 1) v = 0.5f * v * (1.f + erff(v * 0.7071067811865475f));
            if (RESID) v += resid[(long)m * ldc + n];
            C[(long)m * ldc + n] = v;
        }
    }
}

// ---------------- row softmax over M=2048 ----------------
__global__ void softmax_kernel(float* __restrict__ sim) {
    long row = blockIdx.x;
    float* p = sim + row * (long)Mm;
    int tid = threadIdx.x;
    float v[8];
    float mx = -3.4e38f;
#pragma unroll
    for (int t = 0; t < 8; t++) { v[t] = p[tid + t * 256]; mx = fmaxf(mx, v[t]); }
    __shared__ float red[256];
    red[tid] = mx; __syncthreads();
    for (int o = 128; o > 0; o >>= 1) { if (tid < o) red[tid] = fmaxf(red[tid], red[tid + o]); __syncthreads(); }
    mx = red[0]; __syncthreads();
    float s = 0.f;
#pragma unroll
    for (int t = 0; t < 8; t++) { v[t] = expf(v[t] - mx); s += v[t]; }
    red[tid] = s; __syncthreads();
    for (int o = 128; o > 0; o >>= 1) { if (tid < o) red[tid] += red[tid + o]; __syncthreads(); }
    float inv = 1.f / red[0];
#pragma unroll
    for (int t = 0; t < 8; t++) p[tid + t * 256] = v[t] * inv;
}

// ---------------- mean over S of queries ----------------
__global__ void qmean_kernel() {
    int d = blockIdx.x * 256 + threadIdx.x;
    int b = blockIdx.y;
    const float* p = g_q + (size_t)b * Ss * Dd + d;
    double s = 0.0;
    for (int t = 0; t < Ss; t++) s += p[(size_t)t * Dd];
    g_qmean[b * Dd + d] = (float)(s * (1.0 / Ss));
}

// ---------------- host-side launch helpers ----------------
template <int TRANSB, int ACT, int RESID>
static void launch_tc(dim3 grid, const float* A, int lda, long sA,
                      const float* B, int ldb, long sB,
                      const float* bias, const float* resid,
                      float* C, int ldc, long sC, int Kd, float alpha) {
    if ((((uintptr_t)B) & 15) == 0)
        gemm_tc<TRANSB, ACT, RESID, 1><<<grid, 256>>>(A, lda, sA, B, ldb, sB, bias, resid, C, ldc, sC, Kd, alpha);
    else
        gemm_tc<TRANSB, ACT, RESID, 0><<<grid, 256>>>(A, lda, sA, B, ldb, sB, bias, resid, C, ldc, sC, Kd, alpha);
}

extern "C" void kernel_launch(void* const* d_in, const int* in_sizes, int n_in,
                              void* d_out, int out_size) {
    const float* x      = (const float*)d_in[0];
    const float* memdict= (const float*)d_in[1];
    const float* ln_g   = (const float*)d_in[2];
    const float* ln_b   = (const float*)d_in[3];
    const float* mk_w1  = (const float*)d_in[4];
    const float* mk_b1  = (const float*)d_in[5];
    const float* mk_w2  = (const float*)d_in[6];
    const float* mk_b2  = (const float*)d_in[7];
    const float* mv_w1  = (const float*)d_in[8];
    const float* mv_b1  = (const float*)d_in[9];
    const float* mv_w2  = (const float*)d_in[10];
    const float* mv_b2  = (const float*)d_in[11];
    const float* mq_w1  = (const float*)d_in[12];
    const float* mq_b1  = (const float*)d_in[13];
    const float* mq_w2  = (const float*)d_in[14];
    const float* mq_b2  = (const float*)d_in[15];
    const float* wg_w   = (const float*)d_in[16];
    const float* wg_b   = (const float*)d_in[17];
    const float* q_w    = (const float*)d_in[18];
    const float* k_w    = (const float*)d_in[19];
    const float* v_w    = (const float*)d_in[20];
    const float* conv_w = (const float*)d_in[21];
    const float* conv_b = (const float*)d_in[22];
    const float* gp_w   = (const float*)d_in[23];
    const float* gp_b   = (const float*)d_in[24];
    const float* mr_w   = (const float*)d_in[25];
    const float* mr_b   = (const float*)d_in[26];
    const float* out_w  = (const float*)d_in[27];
    const float* out_b  = (const float*)d_in[28];

    float* out_main = (float*)d_out;
    float* out_mem  = out_main + (size_t)Bb * Ss * Dd;

    float *p_xn, *p_h, *p_memk, *p_memv, *p_memq, *p_q, *p_k, *p_v, *p_sim, *p_retr, *p_memout, *p_qmean, *p_gctx;
    cudaGetSymbolAddress((void**)&p_xn, g_xn);
    cudaGetSymbolAddress((void**)&p_h, g_h);
    cudaGetSymbolAddress((void**)&p_memk, g_memk);
    cudaGetSymbolAddress((void**)&p_memv, g_memv);
    cudaGetSymbolAddress((void**)&p_memq, g_memq);
    cudaGetSymbolAddress((void**)&p_q, g_q);
    cudaGetSymbolAddress((void**)&p_k, g_k);
    cudaGetSymbolAddress((void**)&p_v, g_v);
    cudaGetSymbolAddress((void**)&p_sim, g_sim);
    cudaGetSymbolAddress((void**)&p_retr, g_retr);
    cudaGetSymbolAddress((void**)&p_memout, g_memout);
    cudaGetSymbolAddress((void**)&p_qmean, g_qmean);
    cudaGetSymbolAddress((void**)&p_gctx, g_gctx);

    const int ROWS = Bb * Ss;   // 16384

    // 1) LN + write-gate; conv weight transpose
    ln_imp_kernel<<<ROWS, 256>>>(x, ln_g, ln_b, wg_w, wg_b);
    wt_kernel<<<(3 * NGRP * 128 * 128 + 255) / 256, 256>>>(conv_w);
    // 2) top-k per batch
    topk_kernel<<<Bb, 1024>>>();

    // 3) mem_keys MLP
    launch_tc<0, 1, 0>(dim3(8, 128), p_xn, Dd, 0, mk_w1, Dd, 0, mk_b1, nullptr, p_h, Dd, 0, Dd, 1.f);
    launch_tc<0, 0, 0>(dim3(1, 128), p_h, Dd, 0, mk_w2, Kk, 0, mk_b2, nullptr, p_memk, Kk, 0, Dd, 1.f);
    // 4) mem_values MLP
    launch_tc<0, 1, 0>(dim3(8, 128), p_xn, Dd, 0, mv_w1, Dd, 0, mv_b1, nullptr, p_h, Dd, 0, Dd, 1.f);
    launch_tc<0, 0, 0>(dim3(1, 128), p_h, Dd, 0, mv_w2, Vv, 0, mv_b2, nullptr, p_memv, Vv, 0, Dd, 1.f);
    // 5) splice memory into d_out
    assemble_kernel<<<(Bb * Mm * 256 + 255) / 256, 256>>>(memdict, out_mem);
    // 6) mem_queries MLP
    launch_tc<0, 1, 0>(dim3(8, 128), p_xn, Dd, 0, mq_w1, Dd, 0, mq_b1, nullptr, p_h, Dd, 0, Dd, 1.f);
    launch_tc<0, 0, 0>(dim3(1, 128), p_h, Dd, 0, mq_w2, Kk, 0, mq_b2, nullptr, p_memq, Kk, 0, Dd, 1.f);

    // 7) sim = q @ K^T / sqrt(K)
    launch_tc<1, 0, 0>(dim3(16, 32, Bb), p_memq, Kk, (long)Ss * Kk,
                       out_mem, 256, (long)Mm * 256, nullptr, nullptr,
                       p_sim, Mm, (long)Ss * Mm, Kk, 0.08838834764831845f);
    // 8) softmax rows
    softmax_kernel<<<ROWS, 256>>>(p_sim);
    // 9) retrieved = attn @ V
    launch_tc<0, 0, 0>(dim3(1, 32, Bb), p_sim, Mm, (long)Ss * Mm,
                       out_mem + Kk, 256, (long)Mm * 256, nullptr, nullptr,
                       p_retr, Vv, (long)Ss * Vv, Mm, 1.f);
    // 10) memory_output = retrieved @ mr_w + mr_b
    launch_tc<0, 0, 0>(dim3(8, 128), p_retr, Vv, 0, mr_w, Dd, 0, mr_b, nullptr, p_memout, Dd, 0, Vv, 1.f);

    // 11) q, k, v projections
    launch_tc<0, 0, 0>(dim3(8, 128), p_xn, Dd, 0, q_w, Dd, 0, nullptr, nullptr, p_q, Dd, 0, Dd, 1.f);
    launch_tc<0, 0, 0>(dim3(8, 128), p_xn, Dd, 0, k_w, Dd, 0, nullptr, nullptr, p_k, Dd, 0, Dd, 1.f);
    launch_tc<0, 0, 0>(dim3(8, 128), p_xn, Dd, 0, v_w, Dd, 0, nullptr, nullptr, p_v, Dd, 0, Dd, 1.f);

    // 12) mean(queries); 13) global ctx projection (M=4, SIMT)
    qmean_kernel<<<dim3(Dd / 256, Bb), 256>>>();
    gemm_k<0, 0, 0><<<dim3(Dd / BN, 1, 1), 256>>>(p_qmean, Dd, 0, gp_w, Dd, 0, gp_b, nullptr, p_gctx, Dd, 0, Bb, Dd, 1.f);

    // 14) conv + combine -> g_h
    conv_tc<<<dim3(Ss / 128, NGRP, Bb), 256>>>(conv_b);

    // 15) output = combined @ out_w + out_b + residual(x)
    launch_tc<0, 0, 1>(dim3(8, 128), p_h, Dd, 0, out_w, Dd, 0, out_b, x, out_main, Dd, 0, Dd, 1.f);
}

// round 8
// speedup vs baseline: 3.2818x; 1.0386x over previous
#include <cuda_runtime.h>
#include <math.h>
#include <stdint.h>

#define Bb 4
#define Ss 4096
#define Dd 1024
#define Mm 2048
#define Kk 128
#define Vv 128
#define NGRP 8
#define NWRITES 1024
#define KEEP 1024

// ---------------- scratch ----------------
__device__ __align__(16) float g_xn[Bb * Ss * Dd];
__device__ __align__(16) float g_h[Bb * Ss * Dd];                 // combined
__device__ __align__(16) float g_hpack[(size_t)Bb * Ss * 3072];   // MLP1 hidden (3 chains)
__device__ __align__(16) float g_qkv[(size_t)Bb * Ss * 3072];     // q|k|v packed
__device__ __align__(16) float g_mem2[Bb * Ss * 384];             // memk|memv|memq packed
__device__ __align__(16) float g_sig[Bb * Ss];
__device__ __align__(16) int   g_topidx[Bb * NWRITES];
__device__ __align__(16) float g_sim[(size_t)Bb * Ss * Mm];
__device__ __align__(16) float g_retr[Bb * Ss * Vv];
__device__ __align__(16) float g_memout[Bb * Ss * Dd];
__device__ __align__(16) float g_qmean[Bb * Dd];
__device__ __align__(16) float g_gctx[Bb * Dd];
__device__ __align__(16) float g_wt[3 * NGRP * 128 * 128];
__device__ __align__(16) float g_w1pack[Dd * 3072];
__device__ __align__(16) float g_b1pack[3072];
__device__ __align__(16) float g_qkvw[Dd * 3072];
__device__ __align__(16) float g_w2pack[3 * Dd * 128];
__device__ __align__(16) float g_b2pack[384];

// ---------------- mma / cp.async helpers ----------------
__device__ __forceinline__ void mma8(float* c, const uint32_t* a, const uint32_t* b) {
    asm volatile(
        "mma.sync.aligned.m16n8k8.row.col.f32.tf32.tf32.f32 "
        "{%0,%1,%2,%3}, {%4,%5,%6,%7}, {%8,%9}, {%0,%1,%2,%3};\n"
        : "+f"(c[0]), "+f"(c[1]), "+f"(c[2]), "+f"(c[3])
        : "r"(a[0]), "r"(a[1]), "r"(a[2]), "r"(a[3]), "r"(b[0]), "r"(b[1]));
}
__device__ __forceinline__ void cpa16(uint32_t dst, const float* src) {
    asm volatile("cp.async.cg.shared.global [%0], [%1], 16;\n" :: "r"(dst), "l"(src));
}
__device__ __forceinline__ void cpa4(uint32_t dst, const float* src) {
    asm volatile("cp.async.ca.shared.global [%0], [%1], 4;\n" :: "r"(dst), "l"(src));
}
#define CP_COMMIT asm volatile("cp.async.commit_group;\n" ::: "memory")
#define CP_WAIT0  asm volatile("cp.async.wait_group 0;\n" ::: "memory")

#define GTM 128
#define GTN 128
#define GTK 16
#define ASTR 20
#define BSTR 136
#define ASTAGE (128 * ASTR)
#define BSTAGE 2560

template <int TRANSB, int B16>
__device__ __forceinline__ void stage_tile(
    const float* __restrict__ A, int lda, int m0,
    const float* __restrict__ Bm, int ldb, int n0,
    uint32_t asb, uint32_t bsb, int tid, int k0, int st)
{
    uint32_t ad = asb + st * (ASTAGE * 4);
    int c = tid;
#pragma unroll
    for (int p = 0; p < 2; p++, c += 256) {
        int m = c >> 2, ko = (c & 3) * 4;
        cpa16(ad + (uint32_t)(m * ASTR + ko) * 4, A + (long)(m0 + m) * lda + k0 + ko);
    }
    uint32_t bd = bsb + st * (BSTAGE * 4);
    if (TRANSB) {
        int c2 = tid;
#pragma unroll
        for (int p = 0; p < 2; p++, c2 += 256) {
            int n = c2 >> 2, ko = (c2 & 3) * 4;
            cpa16(bd + (uint32_t)(n * ASTR + ko) * 4, Bm + (long)(n0 + n) * ldb + k0 + ko);
        }
    } else if (B16) {
        int c2 = tid;
#pragma unroll
        for (int p = 0; p < 2; p++, c2 += 256) {
            int k = c2 >> 5, no = (c2 & 31) * 4;
            cpa16(bd + (uint32_t)(k * BSTR + no) * 4, Bm + (long)(k0 + k) * ldb + n0 + no);
        }
    } else {
        int e = tid;
#pragma unroll
        for (int p = 0; p < 8; p++, e += 256) {
            int k = e >> 7, n = e & 127;
            cpa4(bd + (uint32_t)(k * BSTR + n) * 4, Bm + (long)(k0 + k) * ldb + n0 + n);
        }
    }
    CP_COMMIT;
}

// ---------------- tf32 GEMM, cp.async double-buffered, optional split-K ----------------
// SPLITK: blockIdx.x = split index (N must equal GTN); Kd = per-split chunk; atomic C.
template <int TRANSB, int ACT, int RESID, int B16, int SPLITK>
__global__ void __launch_bounds__(256, 2) gemm_tc(
    const float* __restrict__ A, int lda, long sA,
    const float* __restrict__ Bm, int ldb, long sB,
    const float* __restrict__ bias, long sBias,
    const float* __restrict__ resid,
    float* __restrict__ C, int ldc, long sC,
    int Kd, float alpha)
{
    __shared__ __align__(16) float sh[2 * ASTAGE + 2 * BSTAGE];
    __shared__ __align__(16) float sbias[GTN];
    long bz = blockIdx.z;
    A += bz * sA; Bm += bz * sB; C += bz * sC;
    if (RESID) resid += bz * sC;
    int n0 = SPLITK ? 0 : blockIdx.x * GTN;
    int m0 = blockIdx.y * GTM;
    int kbase = SPLITK ? blockIdx.x * Kd : 0;
    int tid = threadIdx.x;
    int warp = tid >> 5, lane = tid & 31;
    int g = lane >> 2, tg = lane & 3;
    int wm = (warp & 1) * 64, wn = (warp >> 1) * 32;

    if (!SPLITK && tid < GTN) sbias[tid] = bias ? bias[bz * sBias + n0 + tid] : 0.f;

    uint32_t asb = (uint32_t)__cvta_generic_to_shared(sh);
    uint32_t bsb = asb + 2 * ASTAGE * 4;

    float c[4][4][4];
#pragma unroll
    for (int a = 0; a < 4; a++)
#pragma unroll
        for (int b = 0; b < 4; b++)
#pragma unroll
            for (int e = 0; e < 4; e++) c[a][b][e] = 0.f;

    int nt = Kd >> 4;
    stage_tile<TRANSB, B16>(A, lda, m0, Bm, ldb, n0, asb, bsb, tid, kbase, 0);

    for (int t = 0; t < nt; t++) {
        CP_WAIT0;
        __syncthreads();
        if (t + 1 < nt)
            stage_tile<TRANSB, B16>(A, lda, m0, Bm, ldb, n0, asb, bsb, tid,
                                    kbase + (t + 1) * GTK, (t + 1) & 1);
        const float* Ast = sh + (t & 1) * ASTAGE;
        const float* Bst = sh + 2 * ASTAGE + (t & 1) * BSTAGE;
#pragma unroll
        for (int ks = 0; ks < 2; ks++) {
            const int kk = ks * 8;
            uint32_t af[4][4], bf[4][2];
#pragma unroll
            for (int mi = 0; mi < 4; mi++) {
                const float* ap = Ast + (wm + mi * 16 + g) * ASTR + kk + tg;
                af[mi][0] = __float_as_uint(ap[0]);
                af[mi][1] = __float_as_uint(ap[8 * ASTR]);
                af[mi][2] = __float_as_uint(ap[4]);
                af[mi][3] = __float_as_uint(ap[8 * ASTR + 4]);
            }
#pragma unroll
            for (int ni = 0; ni < 4; ni++) {
                if (TRANSB) {
                    const float* bp = Bst + (wn + ni * 8 + g) * ASTR + kk + tg;
                    bf[ni][0] = __float_as_uint(bp[0]);
                    bf[ni][1] = __float_as_uint(bp[4]);
                } else {
                    const float* bp = Bst + (kk + tg) * BSTR + wn + ni * 8 + g;
                    bf[ni][0] = __float_as_uint(bp[0]);
                    bf[ni][1] = __float_as_uint(bp[4 * BSTR]);
                }
            }
#pragma unroll
            for (int mi = 0; mi < 4; mi++)
#pragma unroll
                for (int ni = 0; ni < 4; ni++) mma8(c[mi][ni], af[mi], bf[ni]);
        }
    }

#pragma unroll
    for (int mi = 0; mi < 4; mi++) {
#pragma unroll
        for (int ni = 0; ni < 4; ni++) {
            int row = m0 + wm + mi * 16 + g;
            int cb = wn + ni * 8 + 2 * tg;
            int col = n0 + cb;
            float v[4];
#pragma unroll
            for (int e = 0; e < 4; e++) v[e] = c[mi][ni][e] * alpha;
            if (SPLITK) {
                atomicAdd(&C[(long)row * ldc + col],     v[0]);
                atomicAdd(&C[(long)row * ldc + col + 1], v[1]);
                atomicAdd(&C[(long)(row + 8) * ldc + col],     v[2]);
                atomicAdd(&C[(long)(row + 8) * ldc + col + 1], v[3]);
            } else {
                v[0] += sbias[cb];     v[1] += sbias[cb + 1];
                v[2] += sbias[cb];     v[3] += sbias[cb + 1];
                if (ACT == 1) {
#pragma unroll
                    for (int e = 0; e < 4; e++)
                        v[e] = 0.5f * v[e] * (1.f + erff(v[e] * 0.7071067811865475f));
                }
                if (RESID) {
                    v[0] += resid[(long)row * ldc + col];
                    v[1] += resid[(long)row * ldc + col + 1];
                    v[2] += resid[(long)(row + 8) * ldc + col];
                    v[3] += resid[(long)(row + 8) * ldc + col + 1];
                }
                *(float2*)&C[(long)row * ldc + col] = make_float2(v[0], v[1]);
                *(float2*)&C[(long)(row + 8) * ldc + col] = make_float2(v[2], v[3]);
            }
        }
    }
}

// ---------------- weight packing ----------------
__global__ void pack_w1(const float* __restrict__ mk, const float* __restrict__ mv,
                        const float* __restrict__ mq, const float* __restrict__ bk,
                        const float* __restrict__ bv, const float* __restrict__ bq) {
    int i = blockIdx.x * 256 + threadIdx.x;
    if (i >= Dd * 3072) return;
    int n = i % 3072, k = i / 3072;
    int ch = n >> 10, col = n & 1023;
    const float* w = ch == 0 ? mk : ch == 1 ? mv : mq;
    g_w1pack[(size_t)k * 3072 + n] = w[(size_t)k * Dd + col];
    if (k == 0) {
        const float* bb = ch == 0 ? bk : ch == 1 ? bv : bq;
        g_b1pack[n] = bb[col];
    }
}
__global__ void pack_qkv(const float* __restrict__ qw, const float* __restrict__ kw,
                         const float* __restrict__ vw) {
    int i = blockIdx.x * 256 + threadIdx.x;
    if (i >= Dd * 3072) return;
    int n = i % 3072, k = i / 3072;
    int ch = n >> 10, col = n & 1023;
    const float* w = ch == 0 ? qw : ch == 1 ? kw : vw;
    g_qkvw[(size_t)k * 3072 + n] = w[(size_t)k * Dd + col];
}
__global__ void pack_w2(const float* __restrict__ wk, const float* __restrict__ wv,
                        const float* __restrict__ wq, const float* __restrict__ bk,
                        const float* __restrict__ bv, const float* __restrict__ bq) {
    int i = blockIdx.x * 256 + threadIdx.x;
    if (i >= 3 * Dd * 128) return;
    int z = i / (Dd * 128), r = i % (Dd * 128);
    const float* w = z == 0 ? wk : z == 1 ? wv : wq;
    g_w2pack[i] = w[r];
    if (i < 384) {
        int zz = i >> 7, cc = i & 127;
        const float* bb = zz == 0 ? bk : zz == 1 ? bv : bq;
        g_b2pack[i] = bb[cc];
    }
}

// ---------------- conv ----------------
#define TBK 32
#define TSTR 136
__device__ __forceinline__ int swz(int k, int m) { return m ^ (((k >> 2) & 7) << 2); }
__device__ __forceinline__ uint32_t f2tf32(float f) {
    uint32_t u;
    asm("cvt.rna.tf32.f32 %0, %1;" : "=r"(u) : "f"(f));
    return u;
}

__global__ void wt_kernel(const float* __restrict__ cw) {
    int idx = blockIdx.x * 256 + threadIdx.x;
    if (idx >= 3 * NGRP * 128 * 128) return;
    int o = idx & 127;
    int k = (idx >> 7) & 127;
    int hg = idx >> 14;
    int h = hg >> 3, grp = hg & 7;
    g_wt[idx] = cw[(((size_t)(grp * 128 + o)) * 128 + k) * 3 + h];
}

__global__ void __launch_bounds__(256, 2) conv_tc(const float* __restrict__ cb) {
    __shared__ __align__(16) uint32_t As[TBK * TSTR];
    __shared__ __align__(16) uint32_t Bs[TBK * TSTR];
    __shared__ __align__(16) float cbs[128];
    int b = blockIdx.z, grp = blockIdx.y, s0 = blockIdx.x * 128;
    int tid = threadIdx.x;
    int warp = tid >> 5, lane = tid & 31;
    int g = lane >> 2, tg = lane & 3;
    int wm = (warp & 1) * 64, wn = (warp >> 1) * 32;

    if (tid < 128) cbs[tid] = cb[grp * 128 + tid];

    float c[4][4][4];
#pragma unroll
    for (int a = 0; a < 4; a++)
#pragma unroll
        for (int d = 0; d < 4; d++)
#pragma unroll
            for (int e = 0; e < 4; e++) c[a][d][e] = 0.f;

    int arow = tid >> 3, acol = (tid & 7) * 4;

    for (int h = 0; h < 3; h++) {
        for (int k0 = 0; k0 < 128; k0 += TBK) {
#pragma unroll
            for (int p = 0; p < 4; p++) {
                int m = arow + p * 32;
                int s = s0 + m + h - 1;
                float4 v = make_float4(0.f, 0.f, 0.f, 0.f);
                if (s >= 0 && s < Ss)
                    v = *(const float4*)&g_qkv[((size_t)(b * Ss) + s) * 3072 + 2048 + grp * 128 + k0 + acol];
                As[(acol + 0) * TSTR + swz(acol + 0, m)] = f2tf32(v.x);
                As[(acol + 1) * TSTR + swz(acol + 1, m)] = f2tf32(v.y);
                As[(acol + 2) * TSTR + swz(acol + 2, m)] = f2tf32(v.z);
                As[(acol + 3) * TSTR + swz(acol + 3, m)] = f2tf32(v.w);
            }
            {
                int n = tid & 127, kb = tid >> 7;
#pragma unroll
                for (int p = 0; p < 16; p++) {
                    int k = kb + p * 2;
                    Bs[k * TSTR + swz(k, n)] =
                        f2tf32(g_wt[(((size_t)(h * NGRP + grp)) * 128 + k0 + k) * 128 + n]);
                }
            }
            __syncthreads();
#pragma unroll
            for (int ks = 0; ks < 4; ks++) {
                int kk = ks * 8;
                uint32_t af[4][4], bf[4][2];
#pragma unroll
                for (int mi = 0; mi < 4; mi++) {
                    int m = wm + mi * 16;
                    af[mi][0] = As[(kk + tg) * TSTR + swz(kk + tg, m + g)];
                    af[mi][1] = As[(kk + tg) * TSTR + swz(kk + tg, m + g + 8)];
                    af[mi][2] = As[(kk + tg + 4) * TSTR + swz(kk + tg + 4, m + g)];
                    af[mi][3] = As[(kk + tg + 4) * TSTR + swz(kk + tg + 4, m + g + 8)];
                }
#pragma unroll
                for (int ni = 0; ni < 4; ni++) {
                    int n = wn + ni * 8;
                    bf[ni][0] = Bs[(kk + tg) * TSTR + swz(kk + tg, n + g)];
                    bf[ni][1] = Bs[(kk + tg + 4) * TSTR + swz(kk + tg + 4, n + g)];
                }
#pragma unroll
                for (int mi = 0; mi < 4; mi++)
#pragma unroll
                    for (int ni = 0; ni < 4; ni++) mma8(c[mi][ni], af[mi], bf[ni]);
            }
            __syncthreads();
        }
    }

#pragma unroll
    for (int mi = 0; mi < 4; mi++) {
#pragma unroll
        for (int ni = 0; ni < 4; ni++) {
            int cbcol = wn + ni * 8 + 2 * tg;
            int o = grp * 128 + cbcol;
#pragma unroll
            for (int half = 0; half < 2; half++) {
                int s = s0 + wm + mi * 16 + g + half * 8;
                size_t idx = ((size_t)(b * Ss) + s) * Dd + o;
                size_t kidx = ((size_t)(b * Ss) + s) * 3072 + 1024 + o;
                float2 mo = *(const float2*)&g_memout[idx];
                float2 kv = *(const float2*)&g_qkv[kidx];
                float gc0 = g_gctx[b * Dd + o], gc1 = g_gctx[b * Dd + o + 1];
                float l0 = c[mi][ni][half * 2 + 0] + cbs[cbcol];
                float l1 = c[mi][ni][half * 2 + 1] + cbs[cbcol + 1];
                float p0 = 1.f / (1.f + expf(-kv.x));
                float p1 = 1.f / (1.f + expf(-kv.y));
                float r0 = (l0 + 0.1f * gc0 + 0.5f * mo.x) * p0;
                float r1 = (l1 + 0.1f * gc1 + 0.5f * mo.y) * p1;
                *(float2*)&g_h[idx] = make_float2(r0, r1);
            }
        }
    }
}

// ---------------- LayerNorm + write-gate ----------------
__global__ void ln_imp_kernel(const float* __restrict__ x,
                              const float* __restrict__ lng,
                              const float* __restrict__ lnb,
                              const float* __restrict__ wgw,
                              const float* __restrict__ wgb) {
    int row = blockIdx.x;
    int tid = threadIdx.x;
    const float* xr = x + (size_t)row * Dd + tid * 4;
    float x0 = xr[0], x1 = xr[1], x2 = xr[2], x3 = xr[3];
    __shared__ float red[256];

    red[tid] = x0 + x1 + x2 + x3; __syncthreads();
    for (int o = 128; o > 0; o >>= 1) { if (tid < o) red[tid] += red[tid + o]; __syncthreads(); }
    float mu = red[0] * (1.f / Dd);
    __syncthreads();

    float d0 = x0 - mu, d1 = x1 - mu, d2 = x2 - mu, d3 = x3 - mu;
    red[tid] = d0 * d0 + d1 * d1 + d2 * d2 + d3 * d3; __syncthreads();
    for (int o = 128; o > 0; o >>= 1) { if (tid < o) red[tid] += red[tid + o]; __syncthreads(); }
    float var = red[0] * (1.f / Dd);
    float rs = rsqrtf(var + 1e-5f);
    __syncthreads();

    float y0 = d0 * rs * lng[tid * 4 + 0] + lnb[tid * 4 + 0];
    float y1 = d1 * rs * lng[tid * 4 + 1] + lnb[tid * 4 + 1];
    float y2 = d2 * rs * lng[tid * 4 + 2] + lnb[tid * 4 + 2];
    float y3 = d3 * rs * lng[tid * 4 + 3] + lnb[tid * 4 + 3];
    ((float4*)(g_xn + (size_t)row * Dd))[tid] = make_float4(y0, y1, y2, y3);

    red[tid] = y0 * wgw[tid * 4 + 0] + y1 * wgw[tid * 4 + 1]
             + y2 * wgw[tid * 4 + 2] + y3 * wgw[tid * 4 + 3];
    __syncthreads();
    for (int o = 128; o > 0; o >>= 1) { if (tid < o) red[tid] += red[tid + o]; __syncthreads(); }
    if (tid == 0) {
        double l = (double)(red[0] + wgb[0]);
        g_sig[row] = (float)(1.0 / (1.0 + exp(-l)));
    }
}

// ---------------- top-k ----------------
__global__ void topk_kernel() {
    __shared__ __align__(16) unsigned long long sk[Ss];
    int b = blockIdx.x, tid = threadIdx.x;
    for (int i = tid; i < Ss; i += 1024) {
        unsigned u = __float_as_uint(g_sig[b * Ss + i]);
        u = (u & 0x80000000u) ? ~u : (u | 0x80000000u);
        sk[i] = ((unsigned long long)u << 32) | (unsigned)(0xFFFFFFFFu - i);
    }
    __syncthreads();
    for (int k = 2; k <= Ss; k <<= 1) {
        for (int j = k >> 1; j > 0; j >>= 1) {
            for (int i = tid; i < Ss; i += 1024) {
                int ixj = i ^ j;
                if (ixj > i) {
                    bool desc = ((i & k) == 0);
                    unsigned long long a = sk[i], c = sk[ixj];
                    if ((a < c) == desc) { sk[i] = c; sk[ixj] = a; }
                }
            }
            __syncthreads();
        }
    }
    for (int i = tid; i < NWRITES; i += 1024)
        g_topidx[b * NWRITES + i] = (int)(0xFFFFFFFFu - (unsigned)sk[i]);
}

// ---------------- splice memory -> d_out (reads packed mem2) ----------------
__global__ void assemble_kernel(const float* __restrict__ md, float* __restrict__ om) {
    int idx = blockIdx.x * blockDim.x + threadIdx.x;
    if (idx >= Bb * Mm * 256) return;
    int c = idx & 255;
    int m = (idx >> 8) & (Mm - 1);
    int b = idx >> 19;
    float val;
    if (m < KEEP) val = md[idx];
    else {
        int id = g_topidx[b * NWRITES + (m - KEEP)];
        val = g_mem2[((size_t)(b * Ss) + id) * 384 + c];   // memk cols 0-127, memv 128-255
    }
    om[idx] = val;
}

__global__ void zero_retr() {
    int i = blockIdx.x * 256 + threadIdx.x;
    if (i < Bb * Ss * Vv) g_retr[i] = 0.f;
}

// ---------------- small SIMT GEMM (M=4 gctx only) ----------------
#define BM 64
#define BN 64
#define BKg 16
__global__ void gemm_small(const float* __restrict__ A, int lda,
                           const float* __restrict__ Bm, int ldb,
                           const float* __restrict__ bias,
                           float* __restrict__ C, int ldc, int Mr, int Kd) {
    __shared__ __align__(16) float As[BKg][BM + 4];
    __shared__ __align__(16) float Bs[BKg][BN + 4];
    __shared__ __align__(16) float sbias[BN];
    int n0 = blockIdx.x * BN, m0 = blockIdx.y * BM;
    int tid = threadIdx.x;
    int tx = tid & 15, ty = tid >> 4;
    if (tid < BN) sbias[tid] = bias ? bias[n0 + tid] : 0.f;
    float acc[4][4];
#pragma unroll
    for (int i = 0; i < 4; i++)
#pragma unroll
        for (int j = 0; j < 4; j++) acc[i][j] = 0.f;
    int aRow = tid >> 2, aCol = (tid & 3) * 4;
    for (int k0 = 0; k0 < Kd; k0 += BKg) {
        float4 av = make_float4(0.f, 0.f, 0.f, 0.f);
        if (m0 + aRow < Mr)
            av = *(const float4*)&A[(long)(m0 + aRow) * lda + k0 + aCol];
        As[aCol + 0][aRow] = av.x; As[aCol + 1][aRow] = av.y;
        As[aCol + 2][aRow] = av.z; As[aCol + 3][aRow] = av.w;
        int kr = tid >> 4, n = (tid & 15) * 4;
        const float* bp = &Bm[(long)(k0 + kr) * ldb + n0 + n];
        Bs[kr][n + 0] = bp[0]; Bs[kr][n + 1] = bp[1];
        Bs[kr][n + 2] = bp[2]; Bs[kr][n + 3] = bp[3];
        __syncthreads();
#pragma unroll
        for (int kk = 0; kk < BKg; kk++) {
            const float4 a = *(const float4*)&As[kk][ty * 4];
            const float4 b4 = *(const float4*)&Bs[kk][tx * 4];
            float ar[4] = {a.x, a.y, a.z, a.w};
            float br[4] = {b4.x, b4.y, b4.z, b4.w};
#pragma unroll
            for (int ii = 0; ii < 4; ii++)
#pragma unroll
                for (int jj = 0; jj < 4; jj++) acc[ii][jj] += ar[ii] * br[jj];
        }
        __syncthreads();
    }
#pragma unroll
    for (int i = 0; i < 4; i++) {
        int m = m0 + ty * 4 + i;
        if (m >= Mr) break;
#pragma unroll
        for (int j = 0; j < 4; j++) {
            int n = n0 + tx * 4 + j;
            C[(long)m * ldc + n] = acc[i][j] + sbias[tx * 4 + j];
        }
    }
}

// ---------------- row softmax over M=2048 ----------------
__global__ void softmax_kernel(float* __restrict__ sim) {
    long row = blockIdx.x;
    float* p = sim + row * (long)Mm;
    int tid = threadIdx.x;
    float v[8];
    float mx = -3.4e38f;
#pragma unroll
    for (int t = 0; t < 8; t++) { v[t] = p[tid + t * 256]; mx = fmaxf(mx, v[t]); }
    __shared__ float red[256];
    red[tid] = mx; __syncthreads();
    for (int o = 128; o > 0; o >>= 1) { if (tid < o) red[tid] = fmaxf(red[tid], red[tid + o]); __syncthreads(); }
    mx = red[0]; __syncthreads();
    float s = 0.f;
#pragma unroll
    for (int t = 0; t < 8; t++) { v[t] = expf(v[t] - mx); s += v[t]; }
    red[tid] = s; __syncthreads();
    for (int o = 128; o > 0; o >>= 1) { if (tid < o) red[tid] += red[tid + o]; __syncthreads(); }
    float inv = 1.f / red[0];
#pragma unroll
    for (int t = 0; t < 8; t++) p[tid + t * 256] = v[t] * inv;
}

// ---------------- mean over S of queries (packed qkv, stride 3072) ----------------
__global__ void qmean_kernel() {
    int d = blockIdx.x * 256 + threadIdx.x;
    int b = blockIdx.y;
    const float* p = g_qkv + (size_t)b * Ss * 3072 + d;
    double s = 0.0;
    for (int t = 0; t < Ss; t++) s += p[(size_t)t * 3072];
    g_qmean[b * Dd + d] = (float)(s * (1.0 / Ss));
}

// ---------------- launch ----------------
template <int TRANSB, int ACT, int RESID, int SPLITK>
static void launch_tc(dim3 grid, const float* A, int lda, long sA,
                      const float* B, int ldb, long sB,
                      const float* bias, long sBias, const float* resid,
                      float* C, int ldc, long sC, int Kd, float alpha) {
    if ((((uintptr_t)B) & 15) == 0)
        gemm_tc<TRANSB, ACT, RESID, 1, SPLITK><<<grid, 256>>>(A, lda, sA, B, ldb, sB, bias, sBias, resid, C, ldc, sC, Kd, alpha);
    else
        gemm_tc<TRANSB, ACT, RESID, 0, SPLITK><<<grid, 256>>>(A, lda, sA, B, ldb, sB, bias, sBias, resid, C, ldc, sC, Kd, alpha);
}

extern "C" void kernel_launch(void* const* d_in, const int* in_sizes, int n_in,
                              void* d_out, int out_size) {
    const float* x      = (const float*)d_in[0];
    const float* memdict= (const float*)d_in[1];
    const float* ln_g   = (const float*)d_in[2];
    const float* ln_b   = (const float*)d_in[3];
    const float* mk_w1  = (const float*)d_in[4];
    const float* mk_b1  = (const float*)d_in[5];
    const float* mk_w2  = (const float*)d_in[6];
    const float* mk_b2  = (const float*)d_in[7];
    const float* mv_w1  = (const float*)d_in[8];
    const float* mv_b1  = (const float*)d_in[9];
    const float* mv_w2  = (const float*)d_in[10];
    const float* mv_b2  = (const float*)d_in[11];
    const float* mq_w1  = (const float*)d_in[12];
    const float* mq_b1  = (const float*)d_in[13];
    const float* mq_w2  = (const float*)d_in[14];
    const float* mq_b2  = (const float*)d_in[15];
    const float* wg_w   = (const float*)d_in[16];
    const float* wg_b   = (const float*)d_in[17];
    const float* q_w    = (const float*)d_in[18];
    const float* k_w    = (const float*)d_in[19];
    const float* v_w    = (const float*)d_in[20];
    const float* conv_w = (const float*)d_in[21];
    const float* conv_b = (const float*)d_in[22];
    const float* gp_w   = (const float*)d_in[23];
    const float* gp_b   = (const float*)d_in[24];
    const float* mr_w   = (const float*)d_in[25];
    const float* mr_b   = (const float*)d_in[26];
    const float* out_w  = (const float*)d_in[27];
    const float* out_b  = (const float*)d_in[28];

    float* out_main = (float*)d_out;
    float* out_mem  = out_main + (size_t)Bb * Ss * Dd;

    float *p_xn, *p_h, *p_hpack, *p_qkv, *p_mem2, *p_sim, *p_retr, *p_memout, *p_qmean, *p_gctx;
    float *p_w1, *p_b1, *p_qkvw, *p_w2, *p_b2;
    cudaGetSymbolAddress((void**)&p_xn, g_xn);
    cudaGetSymbolAddress((void**)&p_h, g_h);
    cudaGetSymbolAddress((void**)&p_hpack, g_hpack);
    cudaGetSymbolAddress((void**)&p_qkv, g_qkv);
    cudaGetSymbolAddress((void**)&p_mem2, g_mem2);
    cudaGetSymbolAddress((void**)&p_sim, g_sim);
    cudaGetSymbolAddress((void**)&p_retr, g_retr);
    cudaGetSymbolAddress((void**)&p_memout, g_memout);
    cudaGetSymbolAddress((void**)&p_qmean, g_qmean);
    cudaGetSymbolAddress((void**)&p_gctx, g_gctx);
    cudaGetSymbolAddress((void**)&p_w1, g_w1pack);
    cudaGetSymbolAddress((void**)&p_b1, g_b1pack);
    cudaGetSymbolAddress((void**)&p_qkvw, g_qkvw);
    cudaGetSymbolAddress((void**)&p_w2, g_w2pack);
    cudaGetSymbolAddress((void**)&p_b2, g_b2pack);

    const int ROWS = Bb * Ss;   // 16384

    // prep
    ln_imp_kernel<<<ROWS, 256>>>(x, ln_g, ln_b, wg_w, wg_b);
    wt_kernel<<<(3 * NGRP * 128 * 128 + 255) / 256, 256>>>(conv_w);
    pack_w1<<<(Dd * 3072 + 255) / 256, 256>>>(mk_w1, mv_w1, mq_w1, mk_b1, mv_b1, mq_b1);
    pack_qkv<<<(Dd * 3072 + 255) / 256, 256>>>(q_w, k_w, v_w);
    pack_w2<<<(3 * Dd * 128 + 255) / 256, 256>>>(mk_w2, mv_w2, mq_w2, mk_b2, mv_b2, mq_b2);
    topk_kernel<<<Bb, 1024>>>();

    // fused MLP1 (3 chains): hpack = gelu(xn @ w1pack + b1pack)
    launch_tc<0, 1, 0, 0>(dim3(24, 128), p_xn, Dd, 0, p_w1, 3072, 0, p_b1, 0, nullptr,
                          p_hpack, 3072, 0, Dd, 1.f);
    // fused MLP2 (grid.z selects chain): mem2[:, z*128:(z+1)*128]
    launch_tc<0, 0, 0, 0>(dim3(1, 128, 3), p_hpack, 3072, 1024, p_w2, 128, (long)Dd * 128,
                          p_b2, 128, nullptr, p_mem2, 384, 128, Dd, 1.f);
    // splice memory into d_out
    assemble_kernel<<<(Bb * Mm * 256 + 255) / 256, 256>>>(memdict, out_mem);

    // sim = memq @ K^T / sqrt(K)
    launch_tc<1, 0, 0, 0>(dim3(16, 32, Bb), p_mem2 + 256, 384, (long)Ss * 384,
                          out_mem, 256, (long)Mm * 256, nullptr, 0, nullptr,
                          p_sim, Mm, (long)Ss * Mm, Kk, 0.08838834764831845f);
    softmax_kernel<<<ROWS, 256>>>(p_sim);
    // retrieved = attn @ V  (split-K x8, atomic)
    zero_retr<<<(Bb * Ss * Vv + 255) / 256, 256>>>();
    launch_tc<0, 0, 0, 1>(dim3(8, 32, Bb), p_sim, Mm, (long)Ss * Mm,
                          out_mem + Kk, 256, (long)Mm * 256, nullptr, 0, nullptr,
                          p_retr, Vv, (long)Ss * Vv, Mm / 8, 1.f);
    // memory_output = retrieved @ mr_w + mr_b
    launch_tc<0, 0, 0, 0>(dim3(8, 128), p_retr, Vv, 0, mr_w, Dd, 0, mr_b, 0, nullptr,
                          p_memout, Dd, 0, Vv, 1.f);

    // fused QKV: qkv = xn @ qkvw
    launch_tc<0, 0, 0, 0>(dim3(24, 128), p_xn, Dd, 0, p_qkvw, 3072, 0, nullptr, 0, nullptr,
                          p_qkv, 3072, 0, Dd, 1.f);

    // mean(queries); global ctx projection (M=4, SIMT)
    qmean_kernel<<<dim3(Dd / 256, Bb), 256>>>();
    gemm_small<<<dim3(Dd / BN, 1), 256>>>(p_qmean, Dd, gp_w, Dd, gp_b, p_gctx, Dd, Bb, Dd);

    // conv + combine -> g_h
    conv_tc<<<dim3(Ss / 128, NGRP, Bb), 256>>>(conv_b);

    // output = combined @ out_w + out_b + residual(x)
    launch_tc<0, 0, 1, 0>(dim3(8, 128), p_h, Dd, 0, out_w, Dd, 0, out_b, 0, x,
                          out_main, Dd, 0, Dd, 1.f);
}

// round 9
// speedup vs baseline: 3.4832x; 1.0614x over previous
#include <cuda_runtime.h>
#include <math.h>
#include <stdint.h>

#define Bb 4
#define Ss 4096
#define Dd 1024
#define Mm 2048
#define Kk 128
#define Vv 128
#define NGRP 8
#define NWRITES 1024
#define KEEP 1024

// ---------------- scratch ----------------
__device__ __align__(16) float g_xn[Bb * Ss * Dd];
__device__ __align__(16) float g_h[Bb * Ss * Dd];                 // combined
__device__ __align__(16) float g_hpack[(size_t)Bb * Ss * 3072];   // MLP1 hidden (3 chains)
__device__ __align__(16) float g_qkv[(size_t)Bb * Ss * 3072];     // q|k|v packed
__device__ __align__(16) float g_mem2[Bb * Ss * 384];             // memk|memv|memq packed
__device__ __align__(16) float g_sig[Bb * Ss];
__device__ __align__(16) int   g_topidx[Bb * NWRITES];
__device__ __align__(16) float g_sim[(size_t)Bb * Ss * Mm];
__device__ __align__(16) float g_retr[Bb * Ss * Vv];
__device__ __align__(16) float g_memout[Bb * Ss * Dd];
__device__ __align__(16) float g_qmean[Bb * Dd];
__device__ __align__(16) float g_gctx[Bb * Dd];
__device__ __align__(16) float g_wt[3 * NGRP * 128 * 128];
__device__ __align__(16) float g_w1pack[Dd * 3072];
__device__ __align__(16) float g_b1pack[3072];
__device__ __align__(16) float g_qkvw[Dd * 3072];
__device__ __align__(16) float g_w2pack[3 * Dd * 128];
__device__ __align__(16) float g_b2pack[384];

// ---------------- mma / cp.async helpers ----------------
__device__ __forceinline__ void mma8(float* c, const uint32_t* a, const uint32_t* b) {
    asm volatile(
        "mma.sync.aligned.m16n8k8.row.col.f32.tf32.tf32.f32 "
        "{%0,%1,%2,%3}, {%4,%5,%6,%7}, {%8,%9}, {%0,%1,%2,%3};\n"
        : "+f"(c[0]), "+f"(c[1]), "+f"(c[2]), "+f"(c[3])
        : "r"(a[0]), "r"(a[1]), "r"(a[2]), "r"(a[3]), "r"(b[0]), "r"(b[1]));
}
__device__ __forceinline__ void cpa16(uint32_t dst, const float* src) {
    asm volatile("cp.async.cg.shared.global [%0], [%1], 16;\n" :: "r"(dst), "l"(src));
}
__device__ __forceinline__ void cpa4(uint32_t dst, const float* src) {
    asm volatile("cp.async.ca.shared.global [%0], [%1], 4;\n" :: "r"(dst), "l"(src));
}
#define CP_COMMIT asm volatile("cp.async.commit_group;\n" ::: "memory")
#define CP_WAIT0  asm volatile("cp.async.wait_group 0;\n" ::: "memory")

// gemm tile geometry: 128x128 block, K-tile 32, double-buffered dynamic smem
#define GTM 128
#define GTN 128
#define GTK 32
#define ASTR 36          // [m][k] stride: 36g mod 32 = 4g -> banks 4g+tg, conflict-free
#define BSTR 136         // [k][n] stride
#define ASTAGE (128 * ASTR)     // 4608 words
#define BSTAGE 4608             // max(32*136=4352, 128*36=4608)
#define GEMM_SMEM ((2 * ASTAGE + 2 * BSTAGE) * 4)   // 73728 bytes

template <int TRANSB, int B16>
__device__ __forceinline__ void stage_tile(
    const float* __restrict__ A, int lda, int m0,
    const float* __restrict__ Bm, int ldb, int n0,
    uint32_t asb, uint32_t bsb, int tid, int k0, int st)
{
    uint32_t ad = asb + st * (ASTAGE * 4);
    int c = tid;
#pragma unroll
    for (int p = 0; p < 4; p++, c += 256) {
        int m = c >> 3, ko = (c & 7) * 4;
        cpa16(ad + (uint32_t)(m * ASTR + ko) * 4, A + (long)(m0 + m) * lda + k0 + ko);
    }
    uint32_t bd = bsb + st * (BSTAGE * 4);
    if (TRANSB) {                 // shared [n][k] stride ASTR
        int c2 = tid;
#pragma unroll
        for (int p = 0; p < 4; p++, c2 += 256) {
            int n = c2 >> 3, ko = (c2 & 7) * 4;
            cpa16(bd + (uint32_t)(n * ASTR + ko) * 4, Bm + (long)(n0 + n) * ldb + k0 + ko);
        }
    } else if (B16) {             // shared [k][n] stride BSTR
        int c2 = tid;
#pragma unroll
        for (int p = 0; p < 4; p++, c2 += 256) {
            int k = c2 >> 5, no = (c2 & 31) * 4;
            cpa16(bd + (uint32_t)(k * BSTR + no) * 4, Bm + (long)(k0 + k) * ldb + n0 + no);
        }
    } else {
        int e = tid;
#pragma unroll
        for (int p = 0; p < 16; p++, e += 256) {
            int k = e >> 7, n = e & 127;
            cpa4(bd + (uint32_t)(k * BSTR + n) * 4, Bm + (long)(k0 + k) * ldb + n0 + n);
        }
    }
    CP_COMMIT;
}

// ---------------- tf32 GEMM, GTK=32 double-buffered, optional split-K ----------------
template <int TRANSB, int ACT, int RESID, int B16, int SPLITK>
__global__ void __launch_bounds__(256, 2) gemm_tc(
    const float* __restrict__ A, int lda, long sA,
    const float* __restrict__ Bm, int ldb, long sB,
    const float* __restrict__ bias, long sBias,
    const float* __restrict__ resid,
    float* __restrict__ C, int ldc, long sC,
    int Kd, float alpha)
{
    extern __shared__ __align__(16) float sh[];
    __shared__ __align__(16) float sbias[GTN];
    long bz = blockIdx.z;
    A += bz * sA; Bm += bz * sB; C += bz * sC;
    if (RESID) resid += bz * sC;
    int n0 = SPLITK ? 0 : blockIdx.x * GTN;
    int m0 = blockIdx.y * GTM;
    int kbase = SPLITK ? blockIdx.x * Kd : 0;
    int tid = threadIdx.x;
    int warp = tid >> 5, lane = tid & 31;
    int g = lane >> 2, tg = lane & 3;
    int wm = (warp & 1) * 64, wn = (warp >> 1) * 32;

    if (!SPLITK && tid < GTN) sbias[tid] = bias ? bias[bz * sBias + n0 + tid] : 0.f;

    uint32_t asb = (uint32_t)__cvta_generic_to_shared(sh);
    uint32_t bsb = asb + 2 * ASTAGE * 4;

    float c[4][4][4];
#pragma unroll
    for (int a = 0; a < 4; a++)
#pragma unroll
        for (int b = 0; b < 4; b++)
#pragma unroll
            for (int e = 0; e < 4; e++) c[a][b][e] = 0.f;

    int nt = Kd >> 5;
    stage_tile<TRANSB, B16>(A, lda, m0, Bm, ldb, n0, asb, bsb, tid, kbase, 0);

    for (int t = 0; t < nt; t++) {
        CP_WAIT0;
        __syncthreads();
        if (t + 1 < nt)
            stage_tile<TRANSB, B16>(A, lda, m0, Bm, ldb, n0, asb, bsb, tid,
                                    kbase + (t + 1) * GTK, (t + 1) & 1);
        const float* Ast = sh + (t & 1) * ASTAGE;
        const float* Bst = sh + 2 * ASTAGE + (t & 1) * BSTAGE;
#pragma unroll
        for (int ks = 0; ks < 4; ks++) {
            const int kk = ks * 8;
            uint32_t af[4][4], bf[4][2];
#pragma unroll
            for (int mi = 0; mi < 4; mi++) {
                const float* ap = Ast + (wm + mi * 16 + g) * ASTR + kk + tg;
                af[mi][0] = __float_as_uint(ap[0]);
                af[mi][1] = __float_as_uint(ap[8 * ASTR]);
                af[mi][2] = __float_as_uint(ap[4]);
                af[mi][3] = __float_as_uint(ap[8 * ASTR + 4]);
            }
#pragma unroll
            for (int ni = 0; ni < 4; ni++) {
                if (TRANSB) {
                    const float* bp = Bst + (wn + ni * 8 + g) * ASTR + kk + tg;
                    bf[ni][0] = __float_as_uint(bp[0]);
                    bf[ni][1] = __float_as_uint(bp[4]);
                } else {
                    const float* bp = Bst + (kk + tg) * BSTR + wn + ni * 8 + g;
                    bf[ni][0] = __float_as_uint(bp[0]);
                    bf[ni][1] = __float_as_uint(bp[4 * BSTR]);
                }
            }
#pragma unroll
            for (int mi = 0; mi < 4; mi++)
#pragma unroll
                for (int ni = 0; ni < 4; ni++) mma8(c[mi][ni], af[mi], bf[ni]);
        }
    }

#pragma unroll
    for (int mi = 0; mi < 4; mi++) {
#pragma unroll
        for (int ni = 0; ni < 4; ni++) {
            int row = m0 + wm + mi * 16 + g;
            int cb = wn + ni * 8 + 2 * tg;
            int col = n0 + cb;
            float v[4];
#pragma unroll
            for (int e = 0; e < 4; e++) v[e] = c[mi][ni][e] * alpha;
            if (SPLITK) {
                atomicAdd(&C[(long)row * ldc + col],     v[0]);
                atomicAdd(&C[(long)row * ldc + col + 1], v[1]);
                atomicAdd(&C[(long)(row + 8) * ldc + col],     v[2]);
                atomicAdd(&C[(long)(row + 8) * ldc + col + 1], v[3]);
            } else {
                v[0] += sbias[cb];     v[1] += sbias[cb + 1];
                v[2] += sbias[cb];     v[3] += sbias[cb + 1];
                if (ACT == 1) {
#pragma unroll
                    for (int e = 0; e < 4; e++)
                        v[e] = 0.5f * v[e] * (1.f + erff(v[e] * 0.7071067811865475f));
                }
                if (RESID) {
                    v[0] += resid[(long)row * ldc + col];
                    v[1] += resid[(long)row * ldc + col + 1];
                    v[2] += resid[(long)(row + 8) * ldc + col];
                    v[3] += resid[(long)(row + 8) * ldc + col + 1];
                }
                *(float2*)&C[(long)row * ldc + col] = make_float2(v[0], v[1]);
                *(float2*)&C[(long)(row + 8) * ldc + col] = make_float2(v[2], v[3]);
            }
        }
    }
}

// ---------------- weight packing ----------------
__global__ void pack_w1(const float* __restrict__ mk, const float* __restrict__ mv,
                        const float* __restrict__ mq, const float* __restrict__ bk,
                        const float* __restrict__ bv, const float* __restrict__ bq) {
    int i = blockIdx.x * 256 + threadIdx.x;
    if (i >= Dd * 3072) return;
    int n = i % 3072, k = i / 3072;
    int ch = n >> 10, col = n & 1023;
    const float* w = ch == 0 ? mk : ch == 1 ? mv : mq;
    g_w1pack[(size_t)k * 3072 + n] = w[(size_t)k * Dd + col];
    if (k == 0) {
        const float* bb = ch == 0 ? bk : ch == 1 ? bv : bq;
        g_b1pack[n] = bb[col];
    }
}
__global__ void pack_qkv(const float* __restrict__ qw, const float* __restrict__ kw,
                         const float* __restrict__ vw) {
    int i = blockIdx.x * 256 + threadIdx.x;
    if (i >= Dd * 3072) return;
    int n = i % 3072, k = i / 3072;
    int ch = n >> 10, col = n & 1023;
    const float* w = ch == 0 ? qw : ch == 1 ? kw : vw;
    g_qkvw[(size_t)k * 3072 + n] = w[(size_t)k * Dd + col];
}
__global__ void pack_w2(const float* __restrict__ wk, const float* __restrict__ wv,
                        const float* __restrict__ wq, const float* __restrict__ bk,
                        const float* __restrict__ bv, const float* __restrict__ bq) {
    int i = blockIdx.x * 256 + threadIdx.x;
    if (i >= 3 * Dd * 128) return;
    int z = i / (Dd * 128), r = i % (Dd * 128);
    const float* w = z == 0 ? wk : z == 1 ? wv : wq;
    g_w2pack[i] = w[r];
    if (i < 384) {
        int zz = i >> 7, cc = i & 127;
        const float* bb = zz == 0 ? bk : zz == 1 ? bv : bq;
        g_b2pack[i] = bb[cc];
    }
}

// ---------------- conv ----------------
#define TBK 32
#define TSTR 136
__device__ __forceinline__ int swz(int k, int m) { return m ^ (((k >> 2) & 7) << 2); }
__device__ __forceinline__ uint32_t f2tf32(float f) {
    uint32_t u;
    asm("cvt.rna.tf32.f32 %0, %1;" : "=r"(u) : "f"(f));
    return u;
}

__global__ void wt_kernel(const float* __restrict__ cw) {
    int idx = blockIdx.x * 256 + threadIdx.x;
    if (idx >= 3 * NGRP * 128 * 128) return;
    int o = idx & 127;
    int k = (idx >> 7) & 127;
    int hg = idx >> 14;
    int h = hg >> 3, grp = hg & 7;
    g_wt[idx] = cw[(((size_t)(grp * 128 + o)) * 128 + k) * 3 + h];
}

__global__ void __launch_bounds__(256, 2) conv_tc(const float* __restrict__ cb) {
    __shared__ __align__(16) uint32_t As[TBK * TSTR];
    __shared__ __align__(16) uint32_t Bs[TBK * TSTR];
    __shared__ __align__(16) float cbs[128];
    int b = blockIdx.z, grp = blockIdx.y, s0 = blockIdx.x * 128;
    int tid = threadIdx.x;
    int warp = tid >> 5, lane = tid & 31;
    int g = lane >> 2, tg = lane & 3;
    int wm = (warp & 1) * 64, wn = (warp >> 1) * 32;

    if (tid < 128) cbs[tid] = cb[grp * 128 + tid];

    float c[4][4][4];
#pragma unroll
    for (int a = 0; a < 4; a++)
#pragma unroll
        for (int d = 0; d < 4; d++)
#pragma unroll
            for (int e = 0; e < 4; e++) c[a][d][e] = 0.f;

    int arow = tid >> 3, acol = (tid & 7) * 4;

    for (int h = 0; h < 3; h++) {
        for (int k0 = 0; k0 < 128; k0 += TBK) {
#pragma unroll
            for (int p = 0; p < 4; p++) {
                int m = arow + p * 32;
                int s = s0 + m + h - 1;
                float4 v = make_float4(0.f, 0.f, 0.f, 0.f);
                if (s >= 0 && s < Ss)
                    v = *(const float4*)&g_qkv[((size_t)(b * Ss) + s) * 3072 + 2048 + grp * 128 + k0 + acol];
                As[(acol + 0) * TSTR + swz(acol + 0, m)] = f2tf32(v.x);
                As[(acol + 1) * TSTR + swz(acol + 1, m)] = f2tf32(v.y);
                As[(acol + 2) * TSTR + swz(acol + 2, m)] = f2tf32(v.z);
                As[(acol + 3) * TSTR + swz(acol + 3, m)] = f2tf32(v.w);
            }
            {
                int n = tid & 127, kb = tid >> 7;
#pragma unroll
                for (int p = 0; p < 16; p++) {
                    int k = kb + p * 2;
                    Bs[k * TSTR + swz(k, n)] =
                        f2tf32(g_wt[(((size_t)(h * NGRP + grp)) * 128 + k0 + k) * 128 + n]);
                }
            }
            __syncthreads();
#pragma unroll
            for (int ks = 0; ks < 4; ks++) {
                int kk = ks * 8;
                uint32_t af[4][4], bf[4][2];
#pragma unroll
                for (int mi = 0; mi < 4; mi++) {
                    int m = wm + mi * 16;
                    af[mi][0] = As[(kk + tg) * TSTR + swz(kk + tg, m + g)];
                    af[mi][1] = As[(kk + tg) * TSTR + swz(kk + tg, m + g + 8)];
                    af[mi][2] = As[(kk + tg + 4) * TSTR + swz(kk + tg + 4, m + g)];
                    af[mi][3] = As[(kk + tg + 4) * TSTR + swz(kk + tg + 4, m + g + 8)];
                }
#pragma unroll
                for (int ni = 0; ni < 4; ni++) {
                    int n = wn + ni * 8;
                    bf[ni][0] = Bs[(kk + tg) * TSTR + swz(kk + tg, n + g)];
                    bf[ni][1] = Bs[(kk + tg + 4) * TSTR + swz(kk + tg + 4, n + g)];
                }
#pragma unroll
                for (int mi = 0; mi < 4; mi++)
#pragma unroll
                    for (int ni = 0; ni < 4; ni++) mma8(c[mi][ni], af[mi], bf[ni]);
            }
            __syncthreads();
        }
    }

#pragma unroll
    for (int mi = 0; mi < 4; mi++) {
#pragma unroll
        for (int ni = 0; ni < 4; ni++) {
            int cbcol = wn + ni * 8 + 2 * tg;
            int o = grp * 128 + cbcol;
#pragma unroll
            for (int half = 0; half < 2; half++) {
                int s = s0 + wm + mi * 16 + g + half * 8;
                size_t idx = ((size_t)(b * Ss) + s) * Dd + o;
                size_t kidx = ((size_t)(b * Ss) + s) * 3072 + 1024 + o;
                float2 mo = *(const float2*)&g_memout[idx];
                float2 kv = *(const float2*)&g_qkv[kidx];
                float gc0 = g_gctx[b * Dd + o], gc1 = g_gctx[b * Dd + o + 1];
                float l0 = c[mi][ni][half * 2 + 0] + cbs[cbcol];
                float l1 = c[mi][ni][half * 2 + 1] + cbs[cbcol + 1];
                float p0 = 1.f / (1.f + expf(-kv.x));
                float p1 = 1.f / (1.f + expf(-kv.y));
                float r0 = (l0 + 0.1f * gc0 + 0.5f * mo.x) * p0;
                float r1 = (l1 + 0.1f * gc1 + 0.5f * mo.y) * p1;
                *(float2*)&g_h[idx] = make_float2(r0, r1);
            }
        }
    }
}

// ---------------- LayerNorm + write-gate ----------------
__global__ void ln_imp_kernel(const float* __restrict__ x,
                              const float* __restrict__ lng,
                              const float* __restrict__ lnb,
                              const float* __restrict__ wgw,
                              const float* __restrict__ wgb) {
    int row = blockIdx.x;
    int tid = threadIdx.x;
    const float* xr = x + (size_t)row * Dd + tid * 4;
    float x0 = xr[0], x1 = xr[1], x2 = xr[2], x3 = xr[3];
    __shared__ float red[256];

    red[tid] = x0 + x1 + x2 + x3; __syncthreads();
    for (int o = 128; o > 0; o >>= 1) { if (tid < o) red[tid] += red[tid + o]; __syncthreads(); }
    float mu = red[0] * (1.f / Dd);
    __syncthreads();

    float d0 = x0 - mu, d1 = x1 - mu, d2 = x2 - mu, d3 = x3 - mu;
    red[tid] = d0 * d0 + d1 * d1 + d2 * d2 + d3 * d3; __syncthreads();
    for (int o = 128; o > 0; o >>= 1) { if (tid < o) red[tid] += red[tid + o]; __syncthreads(); }
    float var = red[0] * (1.f / Dd);
    float rs = rsqrtf(var + 1e-5f);
    __syncthreads();

    float y0 = d0 * rs * lng[tid * 4 + 0] + lnb[tid * 4 + 0];
    float y1 = d1 * rs * lng[tid * 4 + 1] + lnb[tid * 4 + 1];
    float y2 = d2 * rs * lng[tid * 4 + 2] + lnb[tid * 4 + 2];
    float y3 = d3 * rs * lng[tid * 4 + 3] + lnb[tid * 4 + 3];
    ((float4*)(g_xn + (size_t)row * Dd))[tid] = make_float4(y0, y1, y2, y3);

    red[tid] = y0 * wgw[tid * 4 + 0] + y1 * wgw[tid * 4 + 1]
             + y2 * wgw[tid * 4 + 2] + y3 * wgw[tid * 4 + 3];
    __syncthreads();
    for (int o = 128; o > 0; o >>= 1) { if (tid < o) red[tid] += red[tid + o]; __syncthreads(); }
    if (tid == 0) {
        double l = (double)(red[0] + wgb[0]);
        g_sig[row] = (float)(1.0 / (1.0 + exp(-l)));
    }
}

// ---------------- top-k ----------------
__global__ void topk_kernel() {
    __shared__ __align__(16) unsigned long long sk[Ss];
    int b = blockIdx.x, tid = threadIdx.x;
    for (int i = tid; i < Ss; i += 1024) {
        unsigned u = __float_as_uint(g_sig[b * Ss + i]);
        u = (u & 0x80000000u) ? ~u : (u | 0x80000000u);
        sk[i] = ((unsigned long long)u << 32) | (unsigned)(0xFFFFFFFFu - i);
    }
    __syncthreads();
    for (int k = 2; k <= Ss; k <<= 1) {
        for (int j = k >> 1; j > 0; j >>= 1) {
            for (int i = tid; i < Ss; i += 1024) {
                int ixj = i ^ j;
                if (ixj > i) {
                    bool desc = ((i & k) == 0);
                    unsigned long long a = sk[i], c = sk[ixj];
                    if ((a < c) == desc) { sk[i] = c; sk[ixj] = a; }
                }
            }
            __syncthreads();
        }
    }
    for (int i = tid; i < NWRITES; i += 1024)
        g_topidx[b * NWRITES + i] = (int)(0xFFFFFFFFu - (unsigned)sk[i]);
}

// ---------------- splice memory -> d_out ----------------
__global__ void assemble_kernel(const float* __restrict__ md, float* __restrict__ om) {
    int idx = blockIdx.x * blockDim.x + threadIdx.x;
    if (idx >= Bb * Mm * 256) return;
    int c = idx & 255;
    int m = (idx >> 8) & (Mm - 1);
    int b = idx >> 19;
    float val;
    if (m < KEEP) val = md[idx];
    else {
        int id = g_topidx[b * NWRITES + (m - KEEP)];
        val = g_mem2[((size_t)(b * Ss) + id) * 384 + c];
    }
    om[idx] = val;
}

__global__ void zero_retr() {
    int i = blockIdx.x * 256 + threadIdx.x;
    if (i < Bb * Ss * Vv) g_retr[i] = 0.f;
}

// ---------------- small SIMT GEMM (M=4 gctx only) ----------------
#define BM 64
#define BN 64
#define BKg 16
__global__ void gemm_small(const float* __restrict__ A, int lda,
                           const float* __restrict__ Bm, int ldb,
                           const float* __restrict__ bias,
                           float* __restrict__ C, int ldc, int Mr, int Kd) {
    __shared__ __align__(16) float As[BKg][BM + 4];
    __shared__ __align__(16) float Bs[BKg][BN + 4];
    __shared__ __align__(16) float sbias[BN];
    int n0 = blockIdx.x * BN, m0 = blockIdx.y * BM;
    int tid = threadIdx.x;
    int tx = tid & 15, ty = tid >> 4;
    if (tid < BN) sbias[tid] = bias ? bias[n0 + tid] : 0.f;
    float acc[4][4];
#pragma unroll
    for (int i = 0; i < 4; i++)
#pragma unroll
        for (int j = 0; j < 4; j++) acc[i][j] = 0.f;
    int aRow = tid >> 2, aCol = (tid & 3) * 4;
    for (int k0 = 0; k0 < Kd; k0 += BKg) {
        float4 av = make_float4(0.f, 0.f, 0.f, 0.f);
        if (m0 + aRow < Mr)
            av = *(const float4*)&A[(long)(m0 + aRow) * lda + k0 + aCol];
        As[aCol + 0][aRow] = av.x; As[aCol + 1][aRow] = av.y;
        As[aCol + 2][aRow] = av.z; As[aCol + 3][aRow] = av.w;
        int kr = tid >> 4, n = (tid & 15) * 4;
        const float* bp = &Bm[(long)(k0 + kr) * ldb + n0 + n];
        Bs[kr][n + 0] = bp[0]; Bs[kr][n + 1] = bp[1];
        Bs[kr][n + 2] = bp[2]; Bs[kr][n + 3] = bp[3];
        __syncthreads();
#pragma unroll
        for (int kk = 0; kk < BKg; kk++) {
            const float4 a = *(const float4*)&As[kk][ty * 4];
            const float4 b4 = *(const float4*)&Bs[kk][tx * 4];
            float ar[4] = {a.x, a.y, a.z, a.w};
            float br[4] = {b4.x, b4.y, b4.z, b4.w};
#pragma unroll
            for (int ii = 0; ii < 4; ii++)
#pragma unroll
                for (int jj = 0; jj < 4; jj++) acc[ii][jj] += ar[ii] * br[jj];
        }
        __syncthreads();
    }
#pragma unroll
    for (int i = 0; i < 4; i++) {
        int m = m0 + ty * 4 + i;
        if (m >= Mr) break;
#pragma unroll
        for (int j = 0; j < 4; j++) {
            int n = n0 + tx * 4 + j;
            C[(long)m * ldc + n] = acc[i][j] + sbias[tx * 4 + j];
        }
    }
}

// ---------------- row softmax over M=2048 ----------------
__global__ void softmax_kernel(float* __restrict__ sim) {
    long row = blockIdx.x;
    float* p = sim + row * (long)Mm;
    int tid = threadIdx.x;
    float v[8];
    float mx = -3.4e38f;
#pragma unroll
    for (int t = 0; t < 8; t++) { v[t] = p[tid + t * 256]; mx = fmaxf(mx, v[t]); }
    __shared__ float red[256];
    red[tid] = mx; __syncthreads();
    for (int o = 128; o > 0; o >>= 1) { if (tid < o) red[tid] = fmaxf(red[tid], red[tid + o]); __syncthreads(); }
    mx = red[0]; __syncthreads();
    float s = 0.f;
#pragma unroll
    for (int t = 0; t < 8; t++) { v[t] = expf(v[t] - mx); s += v[t]; }
    red[tid] = s; __syncthreads();
    for (int o = 128; o > 0; o >>= 1) { if (tid < o) red[tid] += red[tid + o]; __syncthreads(); }
    float inv = 1.f / red[0];
#pragma unroll
    for (int t = 0; t < 8; t++) p[tid + t * 256] = v[t] * inv;
}

// ---------------- mean over S of queries (packed qkv, stride 3072) ----------------
__global__ void qmean_kernel() {
    int d = blockIdx.x * 256 + threadIdx.x;
    int b = blockIdx.y;
    const float* p = g_qkv + (size_t)b * Ss * 3072 + d;
    double s = 0.0;
    for (int t = 0; t < Ss; t++) s += p[(size_t)t * 3072];
    g_qmean[b * Dd + d] = (float)(s * (1.0 / Ss));
}

// ---------------- launch ----------------
template <int TRANSB, int ACT, int RESID, int SPLITK>
static void launch_tc(dim3 grid, const float* A, int lda, long sA,
                      const float* B, int ldb, long sB,
                      const float* bias, long sBias, const float* resid,
                      float* C, int ldc, long sC, int Kd, float alpha) {
    if ((((uintptr_t)B) & 15) == 0) {
        cudaFuncSetAttribute(gemm_tc<TRANSB, ACT, RESID, 1, SPLITK>,
                             cudaFuncAttributeMaxDynamicSharedMemorySize, GEMM_SMEM);
        gemm_tc<TRANSB, ACT, RESID, 1, SPLITK><<<grid, 256, GEMM_SMEM>>>(
            A, lda, sA, B, ldb, sB, bias, sBias, resid, C, ldc, sC, Kd, alpha);
    } else {
        cudaFuncSetAttribute(gemm_tc<TRANSB, ACT, RESID, 0, SPLITK>,
                             cudaFuncAttributeMaxDynamicSharedMemorySize, GEMM_SMEM);
        gemm_tc<TRANSB, ACT, RESID, 0, SPLITK><<<grid, 256, GEMM_SMEM>>>(
            A, lda, sA, B, ldb, sB, bias, sBias, resid, C, ldc, sC, Kd, alpha);
    }
}

extern "C" void kernel_launch(void* const* d_in, const int* in_sizes, int n_in,
                              void* d_out, int out_size) {
    const float* x      = (const float*)d_in[0];
    const float* memdict= (const float*)d_in[1];
    const float* ln_g   = (const float*)d_in[2];
    const float* ln_b   = (const float*)d_in[3];
    const float* mk_w1  = (const float*)d_in[4];
    const float* mk_b1  = (const float*)d_in[5];
    const float* mk_w2  = (const float*)d_in[6];
    const float* mk_b2  = (const float*)d_in[7];
    const float* mv_w1  = (const float*)d_in[8];
    const float* mv_b1  = (const float*)d_in[9];
    const float* mv_w2  = (const float*)d_in[10];
    const float* mv_b2  = (const float*)d_in[11];
    const float* mq_w1  = (const float*)d_in[12];
    const float* mq_b1  = (const float*)d_in[13];
    const float* mq_w2  = (const float*)d_in[14];
    const float* mq_b2  = (const float*)d_in[15];
    const float* wg_w   = (const float*)d_in[16];
    const float* wg_b   = (const float*)d_in[17];
    const float* q_w    = (const float*)d_in[18];
    const float* k_w    = (const float*)d_in[19];
    const float* v_w    = (const float*)d_in[20];
    const float* conv_w = (const float*)d_in[21];
    const float* conv_b = (const float*)d_in[22];
    const float* gp_w   = (const float*)d_in[23];
    const float* gp_b   = (const float*)d_in[24];
    const float* mr_w   = (const float*)d_in[25];
    const float* mr_b   = (const float*)d_in[26];
    const float* out_w  = (const float*)d_in[27];
    const float* out_b  = (const float*)d_in[28];

    float* out_main = (float*)d_out;
    float* out_mem  = out_main + (size_t)Bb * Ss * Dd;

    float *p_xn, *p_h, *p_hpack, *p_qkv, *p_mem2, *p_sim, *p_retr, *p_memout, *p_qmean, *p_gctx;
    float *p_w1, *p_b1, *p_qkvw, *p_w2, *p_b2;
    cudaGetSymbolAddress((void**)&p_xn, g_xn);
    cudaGetSymbolAddress((void**)&p_h, g_h);
    cudaGetSymbolAddress((void**)&p_hpack, g_hpack);
    cudaGetSymbolAddress((void**)&p_qkv, g_qkv);
    cudaGetSymbolAddress((void**)&p_mem2, g_mem2);
    cudaGetSymbolAddress((void**)&p_sim, g_sim);
    cudaGetSymbolAddress((void**)&p_retr, g_retr);
    cudaGetSymbolAddress((void**)&p_memout, g_memout);
    cudaGetSymbolAddress((void**)&p_qmean, g_qmean);
    cudaGetSymbolAddress((void**)&p_gctx, g_gctx);
    cudaGetSymbolAddress((void**)&p_w1, g_w1pack);
    cudaGetSymbolAddress((void**)&p_b1, g_b1pack);
    cudaGetSymbolAddress((void**)&p_qkvw, g_qkvw);
    cudaGetSymbolAddress((void**)&p_w2, g_w2pack);
    cudaGetSymbolAddress((void**)&p_b2, g_b2pack);

    const int ROWS = Bb * Ss;   // 16384

    // prep
    ln_imp_kernel<<<ROWS, 256>>>(x, ln_g, ln_b, wg_w, wg_b);
    wt_kernel<<<(3 * NGRP * 128 * 128 + 255) / 256, 256>>>(conv_w);
    pack_w1<<<(Dd * 3072 + 255) / 256, 256>>>(mk_w1, mv_w1, mq_w1, mk_b1, mv_b1, mq_b1);
    pack_qkv<<<(Dd * 3072 + 255) / 256, 256>>>(q_w, k_w, v_w);
    pack_w2<<<(3 * Dd * 128 + 255) / 256, 256>>>(mk_w2, mv_w2, mq_w2, mk_b2, mv_b2, mq_b2);
    topk_kernel<<<Bb, 1024>>>();

    // fused MLP1 (3 chains)
    launch_tc<0, 1, 0, 0>(dim3(24, 128), p_xn, Dd, 0, p_w1, 3072, 0, p_b1, 0, nullptr,
                          p_hpack, 3072, 0, Dd, 1.f);
    // fused MLP2 (grid.z selects chain)
    launch_tc<0, 0, 0, 0>(dim3(1, 128, 3), p_hpack, 3072, 1024, p_w2, 128, (long)Dd * 128,
                          p_b2, 128, nullptr, p_mem2, 384, 128, Dd, 1.f);
    // splice memory into d_out
    assemble_kernel<<<(Bb * Mm * 256 + 255) / 256, 256>>>(memdict, out_mem);

    // sim = memq @ K^T / sqrt(K)
    launch_tc<1, 0, 0, 0>(dim3(16, 32, Bb), p_mem2 + 256, 384, (long)Ss * 384,
                          out_mem, 256, (long)Mm * 256, nullptr, 0, nullptr,
                          p_sim, Mm, (long)Ss * Mm, Kk, 0.08838834764831845f);
    softmax_kernel<<<ROWS, 256>>>(p_sim);
    // retrieved = attn @ V  (split-K x8, atomic)
    zero_retr<<<(Bb * Ss * Vv + 255) / 256, 256>>>();
    launch_tc<0, 0, 0, 1>(dim3(8, 32, Bb), p_sim, Mm, (long)Ss * Mm,
                          out_mem + Kk, 256, (long)Mm * 256, nullptr, 0, nullptr,
                          p_retr, Vv, (long)Ss * Vv, Mm / 8, 1.f);
    // memory_output = retrieved @ mr_w + mr_b
    launch_tc<0, 0, 0, 0>(dim3(8, 128), p_retr, Vv, 0, mr_w, Dd, 0, mr_b, 0, nullptr,
                          p_memout, Dd, 0, Vv, 1.f);

    // fused QKV
    launch_tc<0, 0, 0, 0>(dim3(24, 128), p_xn, Dd, 0, p_qkvw, 3072, 0, nullptr, 0, nullptr,
                          p_qkv, 3072, 0, Dd, 1.f);

    // mean(queries); global ctx projection
    qmean_kernel<<<dim3(Dd / 256, Bb), 256>>>();
    gemm_small<<<dim3(Dd / BN, 1), 256>>>(p_qmean, Dd, gp_w, Dd, gp_b, p_gctx, Dd, Bb, Dd);

    // conv + combine -> g_h
    conv_tc<<<dim3(Ss / 128, NGRP, Bb), 256>>>(conv_b);

    // output = combined @ out_w + out_b + residual(x)
    launch_tc<0, 0, 1, 0>(dim3(8, 128), p_h, Dd, 0, out_w, Dd, 0, out_b, 0, x,
                          out_main, Dd, 0, Dd, 1.f);
}

// round 10
// speedup vs baseline: 3.5335x; 1.0145x over previous
#include <cuda_runtime.h>
#include <math.h>
#include <stdint.h>

#define Bb 4
#define Ss 4096
#define Dd 1024
#define Mm 2048
#define Kk 128
#define Vv 128
#define NGRP 8
#define NWRITES 1024
#define KEEP 1024

// ---------------- scratch ----------------
__device__ __align__(16) float g_xn[Bb * Ss * Dd];
__device__ __align__(16) float g_h[Bb * Ss * Dd];                 // combined
__device__ __align__(16) float g_hpack[(size_t)Bb * Ss * 3072];   // MLP1 hidden (3 chains)
__device__ __align__(16) float g_qkv[(size_t)Bb * Ss * 3072];     // q|k|v packed
__device__ __align__(16) float g_mem2[Bb * Ss * 384];             // memk|memv|memq packed
__device__ __align__(16) float g_sig[Bb * Ss];
__device__ __align__(16) int   g_topidx[Bb * NWRITES];
__device__ __align__(16) float g_sim[(size_t)Bb * Ss * Mm];
__device__ __align__(16) float g_retr[Bb * Ss * Vv];
__device__ __align__(16) float g_memout[Bb * Ss * Dd];
__device__ __align__(16) float g_qmean[Bb * Dd];
__device__ __align__(16) float g_gctx[Bb * Dd];
__device__ __align__(16) float g_wt[3 * NGRP * 128 * 128];
// transposed ([n][k]) weights
__device__ __align__(16) float g_w1T[3 * Dd * Dd];      // 3 chains, each [1024][1024]
__device__ __align__(16) float g_qkvT[3 * Dd * Dd];
__device__ __align__(16) float g_w2T[3 * 128 * Dd];     // each [128][1024]
__device__ __align__(16) float g_mrwT[Dd * Vv];         // [1024][128]
__device__ __align__(16) float g_outT[Dd * Dd];
__device__ __align__(16) float g_b1pack[3072];
__device__ __align__(16) float g_b2pack[384];

// ---------------- mma / cp.async / ldmatrix helpers ----------------
__device__ __forceinline__ void mma8(float* c, const uint32_t* a, const uint32_t* b) {
    asm volatile(
        "mma.sync.aligned.m16n8k8.row.col.f32.tf32.tf32.f32 "
        "{%0,%1,%2,%3}, {%4,%5,%6,%7}, {%8,%9}, {%0,%1,%2,%3};\n"
        : "+f"(c[0]), "+f"(c[1]), "+f"(c[2]), "+f"(c[3])
        : "r"(a[0]), "r"(a[1]), "r"(a[2]), "r"(a[3]), "r"(b[0]), "r"(b[1]));
}
__device__ __forceinline__ void cpa16(uint32_t dst, const float* src) {
    asm volatile("cp.async.cg.shared.global [%0], [%1], 16;\n" :: "r"(dst), "l"(src));
}
#define CP_COMMIT asm volatile("cp.async.commit_group;\n" ::: "memory")
#define CP_WAIT0  asm volatile("cp.async.wait_group 0;\n" ::: "memory")
__device__ __forceinline__ void ldsm4(uint32_t* r, uint32_t addr) {
    asm volatile("ldmatrix.sync.aligned.m8n8.x4.shared.b16 {%0,%1,%2,%3}, [%4];\n"
                 : "=r"(r[0]), "=r"(r[1]), "=r"(r[2]), "=r"(r[3]) : "r"(addr));
}
__device__ __forceinline__ void ldsm2(uint32_t* r, uint32_t addr) {
    asm volatile("ldmatrix.sync.aligned.m8n8.x2.shared.b16 {%0,%1}, [%2];\n"
                 : "=r"(r[0]), "=r"(r[1]) : "r"(addr));
}

// gemm tile geometry
#define GTM 128
#define GTN 128
#define GTK 32
#define ASTR 36          // [m][k]/[n][k] stride: rows 4 banks apart -> conflict-free
#define BSTR 136         // [k][n] stride (scalar-B path)
#define ASTAGE (128 * ASTR)     // 4608 words
#define BSTAGE 4608
#define GEMM_SMEM ((2 * ASTAGE + 2 * BSTAGE) * 4)   // 73728 bytes

// BNK=1: B global+shared [n][k] (ldmatrix). BNK=0: B global+shared [k][n] (scalar).
template <int BNK>
__device__ __forceinline__ void stage_tile(
    const float* __restrict__ A, int lda, int m0,
    const float* __restrict__ Bm, int ldb, int n0,
    uint32_t asb, uint32_t bsb, int tid, int k0, int st)
{
    uint32_t ad = asb + st * (ASTAGE * 4);
    int c = tid;
#pragma unroll
    for (int p = 0; p < 4; p++, c += 256) {
        int m = c >> 3, ko = (c & 7) * 4;
        cpa16(ad + (uint32_t)(m * ASTR + ko) * 4, A + (long)(m0 + m) * lda + k0 + ko);
    }
    uint32_t bd = bsb + st * (BSTAGE * 4);
    if (BNK) {
        int c2 = tid;
#pragma unroll
        for (int p = 0; p < 4; p++, c2 += 256) {
            int n = c2 >> 3, ko = (c2 & 7) * 4;
            cpa16(bd + (uint32_t)(n * ASTR + ko) * 4, Bm + (long)(n0 + n) * ldb + k0 + ko);
        }
    } else {
        int c2 = tid;
#pragma unroll
        for (int p = 0; p < 4; p++, c2 += 256) {
            int k = c2 >> 5, no = (c2 & 31) * 4;
            cpa16(bd + (uint32_t)(k * BSTR + no) * 4, Bm + (long)(k0 + k) * ldb + n0 + no);
        }
    }
    CP_COMMIT;
}

// ---------------- tf32 GEMM, GTK=32, ldmatrix fragments ----------------
template <int BNK, int ACT, int RESID, int SPLITK>
__global__ void __launch_bounds__(256, 2) gemm_tc(
    const float* __restrict__ A, int lda, long sA,
    const float* __restrict__ Bm, int ldb, long sB,
    const float* __restrict__ bias, long sBias,
    const float* __restrict__ resid,
    float* __restrict__ C, int ldc, long sC,
    int Kd, float alpha)
{
    extern __shared__ __align__(16) float sh[];
    __shared__ __align__(16) float sbias[GTN];
    long bz = blockIdx.z;
    A += bz * sA; Bm += bz * sB; C += bz * sC;
    if (RESID) resid += bz * sC;
    int n0 = SPLITK ? 0 : blockIdx.x * GTN;
    int m0 = blockIdx.y * GTM;
    int kbase = SPLITK ? blockIdx.x * Kd : 0;
    int tid = threadIdx.x;
    int warp = tid >> 5, lane = tid & 31;
    int g = lane >> 2, tg = lane & 3;
    int wm = (warp & 1) * 64, wn = (warp >> 1) * 32;

    if (!SPLITK && tid < GTN) sbias[tid] = bias ? bias[bz * sBias + n0 + tid] : 0.f;

    uint32_t asb = (uint32_t)__cvta_generic_to_shared(sh);
    uint32_t bsb = asb + 2 * ASTAGE * 4;

    // ldmatrix per-thread address components
    int lr = lane & 7, ls = lane >> 3;                 // ls in 0..3
    int a_row = wm + lr + ((ls & 1) << 3);             // + mi*16
    int a_col = (ls >> 1) << 2;                        // 0 or 4; + kk
    int b_row = wn + lr;                               // + ni*8
    int b_col = (ls & 1) << 2;                         // 0 or 4 (x2: lanes<16 used)

    float c[4][4][4];
#pragma unroll
    for (int a = 0; a < 4; a++)
#pragma unroll
        for (int b = 0; b < 4; b++)
#pragma unroll
            for (int e = 0; e < 4; e++) c[a][b][e] = 0.f;

    int nt = Kd >> 5;
    stage_tile<BNK>(A, lda, m0, Bm, ldb, n0, asb, bsb, tid, kbase, 0);

    for (int t = 0; t < nt; t++) {
        CP_WAIT0;
        __syncthreads();
        if (t + 1 < nt)
            stage_tile<BNK>(A, lda, m0, Bm, ldb, n0, asb, bsb, tid,
                            kbase + (t + 1) * GTK, (t + 1) & 1);
        uint32_t abuf = asb + (t & 1) * (ASTAGE * 4);
        uint32_t bbuf = bsb + (t & 1) * (BSTAGE * 4);
        uint32_t aaddr = abuf + (uint32_t)(a_row * ASTR + a_col) * 4;
        uint32_t baddr = bbuf + (uint32_t)(b_row * ASTR + b_col) * 4;
        const float* BstKN = sh + 2 * ASTAGE + (t & 1) * BSTAGE;
#pragma unroll
        for (int ks = 0; ks < 4; ks++) {
            const int kk = ks * 8;
            uint32_t af[4][4], bf[4][2];
#pragma unroll
            for (int mi = 0; mi < 4; mi++)
                ldsm4(af[mi], aaddr + (uint32_t)(mi * 16 * ASTR + kk) * 4);
#pragma unroll
            for (int ni = 0; ni < 4; ni++) {
                if (BNK) {
                    ldsm2(bf[ni], baddr + (uint32_t)(ni * 8 * ASTR + kk) * 4);
                } else {
                    const float* bp = BstKN + (kk + tg) * BSTR + wn + ni * 8 + g;
                    bf[ni][0] = __float_as_uint(bp[0]);
                    bf[ni][1] = __float_as_uint(bp[4 * BSTR]);
                }
            }
#pragma unroll
            for (int mi = 0; mi < 4; mi++)
#pragma unroll
                for (int ni = 0; ni < 4; ni++) mma8(c[mi][ni], af[mi], bf[ni]);
        }
    }

#pragma unroll
    for (int mi = 0; mi < 4; mi++) {
#pragma unroll
        for (int ni = 0; ni < 4; ni++) {
            int row = m0 + wm + mi * 16 + g;
            int cb = wn + ni * 8 + 2 * tg;
            int col = n0 + cb;
            float v[4];
#pragma unroll
            for (int e = 0; e < 4; e++) v[e] = c[mi][ni][e] * alpha;
            if (SPLITK) {
                atomicAdd(&C[(long)row * ldc + col],     v[0]);
                atomicAdd(&C[(long)row * ldc + col + 1], v[1]);
                atomicAdd(&C[(long)(row + 8) * ldc + col],     v[2]);
                atomicAdd(&C[(long)(row + 8) * ldc + col + 1], v[3]);
            } else {
                v[0] += sbias[cb];     v[1] += sbias[cb + 1];
                v[2] += sbias[cb];     v[3] += sbias[cb + 1];
                if (ACT == 1) {
#pragma unroll
                    for (int e = 0; e < 4; e++)
                        v[e] = 0.5f * v[e] * (1.f + erff(v[e] * 0.7071067811865475f));
                }
                if (RESID) {
                    v[0] += resid[(long)row * ldc + col];
                    v[1] += resid[(long)row * ldc + col + 1];
                    v[2] += resid[(long)(row + 8) * ldc + col];
                    v[3] += resid[(long)(row + 8) * ldc + col + 1];
                }
                *(float2*)&C[(long)row * ldc + col] = make_float2(v[0], v[1]);
                *(float2*)&C[(long)(row + 8) * ldc + col] = make_float2(v[2], v[3]);
            }
        }
    }
}

// ---------------- tiled transpose: src [K][N] -> dst [N][K] ----------------
__global__ void tp32(const float* __restrict__ src, float* __restrict__ dst,
                     int K, int N) {
    __shared__ __align__(16) float t[32][33];
    int n0 = blockIdx.x * 32, k0 = blockIdx.y * 32;
    int tx = threadIdx.x, ty = threadIdx.y;
#pragma unroll
    for (int i = ty; i < 32; i += 8)
        t[i][tx] = src[(long)(k0 + i) * N + n0 + tx];
    __syncthreads();
#pragma unroll
    for (int i = ty; i < 32; i += 8)
        dst[(long)(n0 + i) * K + k0 + tx] = t[tx][i];
}

// ---------------- bias packing ----------------
__global__ void bias_pack(const float* __restrict__ b1k, const float* __restrict__ b1v,
                          const float* __restrict__ b1q, const float* __restrict__ b2k,
                          const float* __restrict__ b2v, const float* __restrict__ b2q) {
    int i = blockIdx.x * 256 + threadIdx.x;
    if (i < 3072) {
        int ch = i >> 10, col = i & 1023;
        g_b1pack[i] = (ch == 0 ? b1k : ch == 1 ? b1v : b1q)[col];
    } else if (i < 3072 + 384) {
        int j = i - 3072;
        int ch = j >> 7, col = j & 127;
        g_b2pack[j] = (ch == 0 ? b2k : ch == 1 ? b2v : b2q)[col];
    }
}

// ---------------- conv ----------------
#define TBK 32
#define TSTR 136
__device__ __forceinline__ int swz(int k, int m) { return m ^ (((k >> 2) & 7) << 2); }
__device__ __forceinline__ uint32_t f2tf32(float f) {
    uint32_t u;
    asm("cvt.rna.tf32.f32 %0, %1;" : "=r"(u) : "f"(f));
    return u;
}

__global__ void wt_kernel(const float* __restrict__ cw) {
    int idx = blockIdx.x * 256 + threadIdx.x;
    if (idx >= 3 * NGRP * 128 * 128) return;
    int o = idx & 127;
    int k = (idx >> 7) & 127;
    int hg = idx >> 14;
    int h = hg >> 3, grp = hg & 7;
    g_wt[idx] = cw[(((size_t)(grp * 128 + o)) * 128 + k) * 3 + h];
}

__global__ void __launch_bounds__(256, 2) conv_tc(const float* __restrict__ cb) {
    __shared__ __align__(16) uint32_t As[TBK * TSTR];
    __shared__ __align__(16) uint32_t Bs[TBK * TSTR];
    __shared__ __align__(16) float cbs[128];
    int b = blockIdx.z, grp = blockIdx.y, s0 = blockIdx.x * 128;
    int tid = threadIdx.x;
    int warp = tid >> 5, lane = tid & 31;
    int g = lane >> 2, tg = lane & 3;
    int wm = (warp & 1) * 64, wn = (warp >> 1) * 32;

    if (tid < 128) cbs[tid] = cb[grp * 128 + tid];

    float c[4][4][4];
#pragma unroll
    for (int a = 0; a < 4; a++)
#pragma unroll
        for (int d = 0; d < 4; d++)
#pragma unroll
            for (int e = 0; e < 4; e++) c[a][d][e] = 0.f;

    int arow = tid >> 3, acol = (tid & 7) * 4;

    for (int h = 0; h < 3; h++) {
        for (int k0 = 0; k0 < 128; k0 += TBK) {
#pragma unroll
            for (int p = 0; p < 4; p++) {
                int m = arow + p * 32;
                int s = s0 + m + h - 1;
                float4 v = make_float4(0.f, 0.f, 0.f, 0.f);
                if (s >= 0 && s < Ss)
                    v = *(const float4*)&g_qkv[((size_t)(b * Ss) + s) * 3072 + 2048 + grp * 128 + k0 + acol];
                As[(acol + 0) * TSTR + swz(acol + 0, m)] = f2tf32(v.x);
                As[(acol + 1) * TSTR + swz(acol + 1, m)] = f2tf32(v.y);
                As[(acol + 2) * TSTR + swz(acol + 2, m)] = f2tf32(v.z);
                As[(acol + 3) * TSTR + swz(acol + 3, m)] = f2tf32(v.w);
            }
            {
                int n = tid & 127, kb = tid >> 7;
#pragma unroll
                for (int p = 0; p < 16; p++) {
                    int k = kb + p * 2;
                    Bs[k * TSTR + swz(k, n)] =
                        f2tf32(g_wt[(((size_t)(h * NGRP + grp)) * 128 + k0 + k) * 128 + n]);
                }
            }
            __syncthreads();
#pragma unroll
            for (int ks = 0; ks < 4; ks++) {
                int kk = ks * 8;
                uint32_t af[4][4], bf[4][2];
#pragma unroll
                for (int mi = 0; mi < 4; mi++) {
                    int m = wm + mi * 16;
                    af[mi][0] = As[(kk + tg) * TSTR + swz(kk + tg, m + g)];
                    af[mi][1] = As[(kk + tg) * TSTR + swz(kk + tg, m + g + 8)];
                    af[mi][2] = As[(kk + tg + 4) * TSTR + swz(kk + tg + 4, m + g)];
                    af[mi][3] = As[(kk + tg + 4) * TSTR + swz(kk + tg + 4, m + g + 8)];
                }
#pragma unroll
                for (int ni = 0; ni < 4; ni++) {
                    int n = wn + ni * 8;
                    bf[ni][0] = Bs[(kk + tg) * TSTR + swz(kk + tg, n + g)];
                    bf[ni][1] = Bs[(kk + tg + 4) * TSTR + swz(kk + tg + 4, n + g)];
                }
#pragma unroll
                for (int mi = 0; mi < 4; mi++)
#pragma unroll
                    for (int ni = 0; ni < 4; ni++) mma8(c[mi][ni], af[mi], bf[ni]);
            }
            __syncthreads();
        }
    }

#pragma unroll
    for (int mi = 0; mi < 4; mi++) {
#pragma unroll
        for (int ni = 0; ni < 4; ni++) {
            int cbcol = wn + ni * 8 + 2 * tg;
            int o = grp * 128 + cbcol;
#pragma unroll
            for (int half = 0; half < 2; half++) {
                int s = s0 + wm + mi * 16 + g + half * 8;
                size_t idx = ((size_t)(b * Ss) + s) * Dd + o;
                size_t kidx = ((size_t)(b * Ss) + s) * 3072 + 1024 + o;
                float2 mo = *(const float2*)&g_memout[idx];
                float2 kv = *(const float2*)&g_qkv[kidx];
                float gc0 = g_gctx[b * Dd + o], gc1 = g_gctx[b * Dd + o + 1];
                float l0 = c[mi][ni][half * 2 + 0] + cbs[cbcol];
                float l1 = c[mi][ni][half * 2 + 1] + cbs[cbcol + 1];
                float p0 = 1.f / (1.f + expf(-kv.x));
                float p1 = 1.f / (1.f + expf(-kv.y));
                float r0 = (l0 + 0.1f * gc0 + 0.5f * mo.x) * p0;
                float r1 = (l1 + 0.1f * gc1 + 0.5f * mo.y) * p1;
                *(float2*)&g_h[idx] = make_float2(r0, r1);
            }
        }
    }
}

// ---------------- LayerNorm + write-gate ----------------
__global__ void ln_imp_kernel(const float* __restrict__ x,
                              const float* __restrict__ lng,
                              const float* __restrict__ lnb,
                              const float* __restrict__ wgw,
                              const float* __restrict__ wgb) {
    int row = blockIdx.x;
    int tid = threadIdx.x;
    const float* xr = x + (size_t)row * Dd + tid * 4;
    float x0 = xr[0], x1 = xr[1], x2 = xr[2], x3 = xr[3];
    __shared__ float red[256];

    red[tid] = x0 + x1 + x2 + x3; __syncthreads();
    for (int o = 128; o > 0; o >>= 1) { if (tid < o) red[tid] += red[tid + o]; __syncthreads(); }
    float mu = red[0] * (1.f / Dd);
    __syncthreads();

    float d0 = x0 - mu, d1 = x1 - mu, d2 = x2 - mu, d3 = x3 - mu;
    red[tid] = d0 * d0 + d1 * d1 + d2 * d2 + d3 * d3; __syncthreads();
    for (int o = 128; o > 0; o >>= 1) { if (tid < o) red[tid] += red[tid + o]; __syncthreads(); }
    float var = red[0] * (1.f / Dd);
    float rs = rsqrtf(var + 1e-5f);
    __syncthreads();

    float y0 = d0 * rs * lng[tid * 4 + 0] + lnb[tid * 4 + 0];
    float y1 = d1 * rs * lng[tid * 4 + 1] + lnb[tid * 4 + 1];
    float y2 = d2 * rs * lng[tid * 4 + 2] + lnb[tid * 4 + 2];
    float y3 = d3 * rs * lng[tid * 4 + 3] + lnb[tid * 4 + 3];
    ((float4*)(g_xn + (size_t)row * Dd))[tid] = make_float4(y0, y1, y2, y3);

    red[tid] = y0 * wgw[tid * 4 + 0] + y1 * wgw[tid * 4 + 1]
             + y2 * wgw[tid * 4 + 2] + y3 * wgw[tid * 4 + 3];
    __syncthreads();
    for (int o = 128; o > 0; o >>= 1) { if (tid < o) red[tid] += red[tid + o]; __syncthreads(); }
    if (tid == 0) {
        double l = (double)(red[0] + wgb[0]);
        g_sig[row] = (float)(1.0 / (1.0 + exp(-l)));
    }
}

// ---------------- top-k ----------------
__global__ void topk_kernel() {
    __shared__ __align__(16) unsigned long long sk[Ss];
    int b = blockIdx.x, tid = threadIdx.x;
    for (int i = tid; i < Ss; i += 1024) {
        unsigned u = __float_as_uint(g_sig[b * Ss + i]);
        u = (u & 0x80000000u) ? ~u : (u | 0x80000000u);
        sk[i] = ((unsigned long long)u << 32) | (unsigned)(0xFFFFFFFFu - i);
    }
    __syncthreads();
    for (int k = 2; k <= Ss; k <<= 1) {
        for (int j = k >> 1; j > 0; j >>= 1) {
            for (int i = tid; i < Ss; i += 1024) {
                int ixj = i ^ j;
                if (ixj > i) {
                    bool desc = ((i & k) == 0);
                    unsigned long long a = sk[i], c = sk[ixj];
                    if ((a < c) == desc) { sk[i] = c; sk[ixj] = a; }
                }
            }
            __syncthreads();
        }
    }
    for (int i = tid; i < NWRITES; i += 1024)
        g_topidx[b * NWRITES + i] = (int)(0xFFFFFFFFu - (unsigned)sk[i]);
}

// ---------------- splice memory -> d_out ----------------
__global__ void assemble_kernel(const float* __restrict__ md, float* __restrict__ om) {
    int idx = blockIdx.x * blockDim.x + threadIdx.x;
    if (idx >= Bb * Mm * 256) return;
    int c = idx & 255;
    int m = (idx >> 8) & (Mm - 1);
    int b = idx >> 19;
    float val;
    if (m < KEEP) val = md[idx];
    else {
        int id = g_topidx[b * NWRITES + (m - KEEP)];
        val = g_mem2[((size_t)(b * Ss) + id) * 384 + c];
    }
    om[idx] = val;
}

__global__ void zero_retr() {
    int i = blockIdx.x * 256 + threadIdx.x;
    if (i < Bb * Ss * Vv) g_retr[i] = 0.f;
}

// ---------------- small SIMT GEMM (M=4 gctx only) ----------------
#define BM 64
#define BN 64
#define BKg 16
__global__ void gemm_small(const float* __restrict__ A, int lda,
                           const float* __restrict__ Bm, int ldb,
                           const float* __restrict__ bias,
                           float* __restrict__ C, int ldc, int Mr, int Kd) {
    __shared__ __align__(16) float As[BKg][BM + 4];
    __shared__ __align__(16) float Bs[BKg][BN + 4];
    __shared__ __align__(16) float sbias[BN];
    int n0 = blockIdx.x * BN, m0 = blockIdx.y * BM;
    int tid = threadIdx.x;
    int tx = tid & 15, ty = tid >> 4;
    if (tid < BN) sbias[tid] = bias ? bias[n0 + tid] : 0.f;
    float acc[4][4];
#pragma unroll
    for (int i = 0; i < 4; i++)
#pragma unroll
        for (int j = 0; j < 4; j++) acc[i][j] = 0.f;
    int aRow = tid >> 2, aCol = (tid & 3) * 4;
    for (int k0 = 0; k0 < Kd; k0 += BKg) {
        float4 av = make_float4(0.f, 0.f, 0.f, 0.f);
        if (m0 + aRow < Mr)
            av = *(const float4*)&A[(long)(m0 + aRow) * lda + k0 + aCol];
        As[aCol + 0][aRow] = av.x; As[aCol + 1][aRow] = av.y;
        As[aCol + 2][aRow] = av.z; As[aCol + 3][aRow] = av.w;
        int kr = tid >> 4, n = (tid & 15) * 4;
        const float* bp = &Bm[(long)(k0 + kr) * ldb + n0 + n];
        Bs[kr][n + 0] = bp[0]; Bs[kr][n + 1] = bp[1];
        Bs[kr][n + 2] = bp[2]; Bs[kr][n + 3] = bp[3];
        __syncthreads();
#pragma unroll
        for (int kk = 0; kk < BKg; kk++) {
            const float4 a = *(const float4*)&As[kk][ty * 4];
            const float4 b4 = *(const float4*)&Bs[kk][tx * 4];
            float ar[4] = {a.x, a.y, a.z, a.w};
            float br[4] = {b4.x, b4.y, b4.z, b4.w};
#pragma unroll
            for (int ii = 0; ii < 4; ii++)
#pragma unroll
                for (int jj = 0; jj < 4; jj++) acc[ii][jj] += ar[ii] * br[jj];
        }
        __syncthreads();
    }
#pragma unroll
    for (int i = 0; i < 4; i++) {
        int m = m0 + ty * 4 + i;
        if (m >= Mr) break;
#pragma unroll
        for (int j = 0; j < 4; j++) {
            int n = n0 + tx * 4 + j;
            C[(long)m * ldc + n] = acc[i][j] + sbias[tx * 4 + j];
        }
    }
}

// ---------------- row softmax over M=2048 ----------------
__global__ void softmax_kernel(float* __restrict__ sim) {
    long row = blockIdx.x;
    float* p = sim + row * (long)Mm;
    int tid = threadIdx.x;
    float v[8];
    float mx = -3.4e38f;
#pragma unroll
    for (int t = 0; t < 8; t++) { v[t] = p[tid + t * 256]; mx = fmaxf(mx, v[t]); }
    __shared__ float red[256];
    red[tid] = mx; __syncthreads();
    for (int o = 128; o > 0; o >>= 1) { if (tid < o) red[tid] = fmaxf(red[tid], red[tid + o]); __syncthreads(); }
    mx = red[0]; __syncthreads();
    float s = 0.f;
#pragma unroll
    for (int t = 0; t < 8; t++) { v[t] = expf(v[t] - mx); s += v[t]; }
    red[tid] = s; __syncthreads();
    for (int o = 128; o > 0; o >>= 1) { if (tid < o) red[tid] += red[tid + o]; __syncthreads(); }
    float inv = 1.f / red[0];
#pragma unroll
    for (int t = 0; t < 8; t++) p[tid + t * 256] = v[t] * inv;
}

// ---------------- mean over S of queries (packed qkv, stride 3072) ----------------
__global__ void qmean_kernel() {
    int d = blockIdx.x * 256 + threadIdx.x;
    int b = blockIdx.y;
    const float* p = g_qkv + (size_t)b * Ss * 3072 + d;
    double s = 0.0;
    for (int t = 0; t < Ss; t++) s += p[(size_t)t * 3072];
    g_qmean[b * Dd + d] = (float)(s * (1.0 / Ss));
}

// ---------------- launch ----------------
template <int BNK, int ACT, int RESID, int SPLITK>
static void launch_tc(dim3 grid, const float* A, int lda, long sA,
                      const float* B, int ldb, long sB,
                      const float* bias, long sBias, const float* resid,
                      float* C, int ldc, long sC, int Kd, float alpha) {
    cudaFuncSetAttribute(gemm_tc<BNK, ACT, RESID, SPLITK>,
                         cudaFuncAttributeMaxDynamicSharedMemorySize, GEMM_SMEM);
    gemm_tc<BNK, ACT, RESID, SPLITK><<<grid, 256, GEMM_SMEM>>>(
        A, lda, sA, B, ldb, sB, bias, sBias, resid, C, ldc, sC, Kd, alpha);
}

extern "C" void kernel_launch(void* const* d_in, const int* in_sizes, int n_in,
                              void* d_out, int out_size) {
    const float* x      = (const float*)d_in[0];
    const float* memdict= (const float*)d_in[1];
    const float* ln_g   = (const float*)d_in[2];
    const float* ln_b   = (const float*)d_in[3];
    const float* mk_w1  = (const float*)d_in[4];
    const float* mk_b1  = (const float*)d_in[5];
    const float* mk_w2  = (const float*)d_in[6];
    const float* mk_b2  = (const float*)d_in[7];
    const float* mv_w1  = (const float*)d_in[8];
    const float* mv_b1  = (const float*)d_in[9];
    const float* mv_w2  = (const float*)d_in[10];
    const float* mv_b2  = (const float*)d_in[11];
    const float* mq_w1  = (const float*)d_in[12];
    const float* mq_b1  = (const float*)d_in[13];
    const float* mq_w2  = (const float*)d_in[14];
    const float* mq_b2  = (const float*)d_in[15];
    const float* wg_w   = (const float*)d_in[16];
    const float* wg_b   = (const float*)d_in[17];
    const float* q_w    = (const float*)d_in[18];
    const float* k_w    = (const float*)d_in[19];
    const float* v_w    = (const float*)d_in[20];
    const float* conv_w = (const float*)d_in[21];
    const float* conv_b = (const float*)d_in[22];
    const float* gp_w   = (const float*)d_in[23];
    const float* gp_b   = (const float*)d_in[24];
    const float* mr_w   = (const float*)d_in[25];
    const float* mr_b   = (const float*)d_in[26];
    const float* out_w  = (const float*)d_in[27];
    const float* out_b  = (const float*)d_in[28];

    float* out_main = (float*)d_out;
    float* out_mem  = out_main + (size_t)Bb * Ss * Dd;

    float *p_xn, *p_h, *p_hpack, *p_qkv, *p_mem2, *p_sim, *p_retr, *p_memout, *p_qmean, *p_gctx;
    float *p_w1T, *p_qkvT, *p_w2T, *p_mrwT, *p_outT, *p_b1, *p_b2;
    cudaGetSymbolAddress((void**)&p_xn, g_xn);
    cudaGetSymbolAddress((void**)&p_h, g_h);
    cudaGetSymbolAddress((void**)&p_hpack, g_hpack);
    cudaGetSymbolAddress((void**)&p_qkv, g_qkv);
    cudaGetSymbolAddress((void**)&p_mem2, g_mem2);
    cudaGetSymbolAddress((void**)&p_sim, g_sim);
    cudaGetSymbolAddress((void**)&p_retr, g_retr);
    cudaGetSymbolAddress((void**)&p_memout, g_memout);
    cudaGetSymbolAddress((void**)&p_qmean, g_qmean);
    cudaGetSymbolAddress((void**)&p_gctx, g_gctx);
    cudaGetSymbolAddress((void**)&p_w1T, g_w1T);
    cudaGetSymbolAddress((void**)&p_qkvT, g_qkvT);
    cudaGetSymbolAddress((void**)&p_w2T, g_w2T);
    cudaGetSymbolAddress((void**)&p_mrwT, g_mrwT);
    cudaGetSymbolAddress((void**)&p_outT, g_outT);
    cudaGetSymbolAddress((void**)&p_b1, g_b1pack);
    cudaGetSymbolAddress((void**)&p_b2, g_b2pack);

    const int ROWS = Bb * Ss;   // 16384
    dim3 tpb(32, 8);

    // prep: LN, conv-w transpose, weight transposes, bias packs, topk
    ln_imp_kernel<<<ROWS, 256>>>(x, ln_g, ln_b, wg_w, wg_b);
    wt_kernel<<<(3 * NGRP * 128 * 128 + 255) / 256, 256>>>(conv_w);
    tp32<<<dim3(32, 32), tpb>>>(mk_w1, p_w1T + 0 * Dd * Dd, Dd, Dd);
    tp32<<<dim3(32, 32), tpb>>>(mv_w1, p_w1T + 1 * Dd * Dd, Dd, Dd);
    tp32<<<dim3(32, 32), tpb>>>(mq_w1, p_w1T + 2 * Dd * Dd, Dd, Dd);
    tp32<<<dim3(32, 32), tpb>>>(q_w, p_qkvT + 0 * Dd * Dd, Dd, Dd);
    tp32<<<dim3(32, 32), tpb>>>(k_w, p_qkvT + 1 * Dd * Dd, Dd, Dd);
    tp32<<<dim3(32, 32), tpb>>>(v_w, p_qkvT + 2 * Dd * Dd, Dd, Dd);
    tp32<<<dim3(4, 32), tpb>>>(mk_w2, p_w2T + 0 * 128 * Dd, Dd, 128);
    tp32<<<dim3(4, 32), tpb>>>(mv_w2, p_w2T + 1 * 128 * Dd, Dd, 128);
    tp32<<<dim3(4, 32), tpb>>>(mq_w2, p_w2T + 2 * 128 * Dd, Dd, 128);
    tp32<<<dim3(32, 4), tpb>>>(mr_w, p_mrwT, 128, Dd);
    tp32<<<dim3(32, 32), tpb>>>(out_w, p_outT, Dd, Dd);
    bias_pack<<<(3456 + 255) / 256, 256>>>(mk_b1, mv_b1, mq_b1, mk_b2, mv_b2, mq_b2);
    topk_kernel<<<Bb, 1024>>>();

    // fused MLP1 (3 chains): blockIdx.x selects 128-col slab across 3072 (n0 = x*128;
    // chain = n0/1024, B chain base via ldb-row indexing works since w1T is [3*1024][1024])
    launch_tc<1, 1, 0, 0>(dim3(24, 128), p_xn, Dd, 0, p_w1T, Dd, 0, p_b1, 0, nullptr,
                          p_hpack, 3072, 0, Dd, 1.f);
    // fused MLP2 (grid.z selects chain)
    launch_tc<1, 0, 0, 0>(dim3(1, 128, 3), p_hpack, 3072, 1024, p_w2T, Dd, (long)128 * Dd,
                          p_b2, 128, nullptr, p_mem2, 384, 128, Dd, 1.f);
    // splice memory into d_out
    assemble_kernel<<<(Bb * Mm * 256 + 255) / 256, 256>>>(memdict, out_mem);

    // sim = memq @ K^T / sqrt(K)   (B = memory rows, n-major)
    launch_tc<1, 0, 0, 0>(dim3(16, 32, Bb), p_mem2 + 256, 384, (long)Ss * 384,
                          out_mem, 256, (long)Mm * 256, nullptr, 0, nullptr,
                          p_sim, Mm, (long)Ss * Mm, Kk, 0.08838834764831845f);
    softmax_kernel<<<ROWS, 256>>>(p_sim);
    // retrieved = attn @ V  (split-K x8, atomic; B [k][n] scalar path)
    zero_retr<<<(Bb * Ss * Vv + 255) / 256, 256>>>();
    launch_tc<0, 0, 0, 1>(dim3(8, 32, Bb), p_sim, Mm, (long)Ss * Mm,
                          out_mem + Kk, 256, (long)Mm * 256, nullptr, 0, nullptr,
                          p_retr, Vv, (long)Ss * Vv, Mm / 8, 1.f);
    // memory_output = retrieved @ mr_w + mr_b
    launch_tc<1, 0, 0, 0>(dim3(8, 128), p_retr, Vv, 0, p_mrwT, Vv, 0, mr_b, 0, nullptr,
                          p_memout, Dd, 0, Vv, 1.f);

    // fused QKV
    launch_tc<1, 0, 0, 0>(dim3(24, 128), p_xn, Dd, 0, p_qkvT, Dd, 0, nullptr, 0, nullptr,
                          p_qkv, 3072, 0, Dd, 1.f);

    // mean(queries); global ctx projection
    qmean_kernel<<<dim3(Dd / 256, Bb), 256>>>();
    gemm_small<<<dim3(Dd / BN, 1), 256>>>(p_qmean, Dd, gp_w, Dd, gp_b, p_gctx, Dd, Bb, Dd);

    // conv + combine -> g_h
    conv_tc<<<dim3(Ss / 128, NGRP, Bb), 256>>>(conv_b);

    // output = combined @ out_w + out_b + residual(x)
    launch_tc<1, 0, 1, 0>(dim3(8, 128), p_h, Dd, 0, p_outT, Dd, 0, out_b, 0, x,
                          out_main, Dd, 0, Dd, 1.f);
}

// round 11
// speedup vs baseline: 3.5458x; 1.0035x over previous
#include <cuda_runtime.h>
#include <math.h>
#include <stdint.h>

#define Bb 4
#define Ss 4096
#define Dd 1024
#define Mm 2048
#define Kk 128
#define Vv 128
#define NGRP 8
#define NWRITES 1024
#define KEEP 1024

// ---------------- scratch ----------------
__device__ __align__(16) float g_xn[Bb * Ss * Dd];
__device__ __align__(16) float g_h[Bb * Ss * Dd];                 // combined
__device__ __align__(16) float g_hpack[(size_t)Bb * Ss * 3072];   // MLP1 hidden (3 chains)
__device__ __align__(16) float g_qkv[(size_t)Bb * Ss * 3072];     // q|k|v packed
__device__ __align__(16) float g_mem2[Bb * Ss * 384];             // memk|memv|memq packed
__device__ __align__(16) float g_sig[Bb * Ss];
__device__ __align__(16) int   g_topidx[Bb * NWRITES];
__device__ __align__(16) float g_sim[(size_t)Bb * Ss * Mm];
__device__ __align__(16) float g_retr[Bb * Ss * Vv];
__device__ __align__(16) float g_memout[Bb * Ss * Dd];
__device__ __align__(16) float g_qmean[Bb * Dd];
__device__ __align__(16) float g_gctx[Bb * Dd];
__device__ __align__(16) float g_wt[3 * NGRP * 128 * 128];
// transposed ([n][k]) weights
__device__ __align__(16) float g_w1T[3 * Dd * Dd];
__device__ __align__(16) float g_qkvT[3 * Dd * Dd];
__device__ __align__(16) float g_w2T[3 * 128 * Dd];
__device__ __align__(16) float g_mrwT[Dd * Vv];
__device__ __align__(16) float g_outT[Dd * Dd];
__device__ __align__(16) float g_b1pack[3072];
__device__ __align__(16) float g_b2pack[384];

// ---------------- mma / cp.async / ldmatrix helpers ----------------
__device__ __forceinline__ void mma8(float* c, const uint32_t* a, const uint32_t* b) {
    asm volatile(
        "mma.sync.aligned.m16n8k8.row.col.f32.tf32.tf32.f32 "
        "{%0,%1,%2,%3}, {%4,%5,%6,%7}, {%8,%9}, {%0,%1,%2,%3};\n"
        : "+f"(c[0]), "+f"(c[1]), "+f"(c[2]), "+f"(c[3])
        : "r"(a[0]), "r"(a[1]), "r"(a[2]), "r"(a[3]), "r"(b[0]), "r"(b[1]));
}
__device__ __forceinline__ void cpa16(uint32_t dst, const float* src) {
    asm volatile("cp.async.cg.shared.global [%0], [%1], 16;\n" :: "r"(dst), "l"(src));
}
#define CP_COMMIT asm volatile("cp.async.commit_group;\n" ::: "memory")
#define CP_WAIT1  asm volatile("cp.async.wait_group 1;\n" ::: "memory")
__device__ __forceinline__ void ldsm4(uint32_t* r, uint32_t addr) {
    asm volatile("ldmatrix.sync.aligned.m8n8.x4.shared.b16 {%0,%1,%2,%3}, [%4];\n"
                 : "=r"(r[0]), "=r"(r[1]), "=r"(r[2]), "=r"(r[3]) : "r"(addr));
}
__device__ __forceinline__ void ldsm2(uint32_t* r, uint32_t addr) {
    asm volatile("ldmatrix.sync.aligned.m8n8.x2.shared.b16 {%0,%1}, [%2];\n"
                 : "=r"(r[0]), "=r"(r[1]) : "r"(addr));
}

// gemm tile geometry: 128x128 block, K-tile 32, 3-stage pipeline
#define GTM 128
#define GTN 128
#define GTK 32
#define ASTR 36
#define BSTR 136
#define ASTAGE (128 * ASTR)     // 4608 words
#define BSTAGE 4608
#define NSTAGE 3
#define GEMM_SMEM ((NSTAGE * ASTAGE + NSTAGE * BSTAGE) * 4)   // 110592 bytes

// BNK=1: B global+shared [n][k] (ldmatrix). BNK=0: B global+shared [k][n] (scalar).
template <int BNK>
__device__ __forceinline__ void stage_tile(
    const float* __restrict__ A, int lda, int m0,
    const float* __restrict__ Bm, int ldb, int n0,
    uint32_t asb, uint32_t bsb, int tid, int k0, int st)
{
    uint32_t ad = asb + st * (ASTAGE * 4);
    int c = tid;
#pragma unroll
    for (int p = 0; p < 4; p++, c += 256) {
        int m = c >> 3, ko = (c & 7) * 4;
        cpa16(ad + (uint32_t)(m * ASTR + ko) * 4, A + (long)(m0 + m) * lda + k0 + ko);
    }
    uint32_t bd = bsb + st * (BSTAGE * 4);
    if (BNK) {
        int c2 = tid;
#pragma unroll
        for (int p = 0; p < 4; p++, c2 += 256) {
            int n = c2 >> 3, ko = (c2 & 7) * 4;
            cpa16(bd + (uint32_t)(n * ASTR + ko) * 4, Bm + (long)(n0 + n) * ldb + k0 + ko);
        }
    } else {
        int c2 = tid;
#pragma unroll
        for (int p = 0; p < 4; p++, c2 += 256) {
            int k = c2 >> 5, no = (c2 & 31) * 4;
            cpa16(bd + (uint32_t)(k * BSTR + no) * 4, Bm + (long)(k0 + k) * ldb + n0 + no);
        }
    }
    CP_COMMIT;
}

// ---------------- tf32 GEMM, 3-stage cp.async, ldmatrix fragments ----------------
template <int BNK, int ACT, int RESID, int SPLITK>
__global__ void __launch_bounds__(256, 2) gemm_tc(
    const float* __restrict__ A, int lda, long sA,
    const float* __restrict__ Bm, int ldb, long sB,
    const float* __restrict__ bias, long sBias,
    const float* __restrict__ resid,
    float* __restrict__ C, int ldc, long sC,
    int Kd, float alpha)
{
    extern __shared__ __align__(16) float sh[];
    __shared__ __align__(16) float sbias[GTN];
    long bz = blockIdx.z;
    A += bz * sA; Bm += bz * sB; C += bz * sC;
    if (RESID) resid += bz * sC;
    int n0 = SPLITK ? 0 : blockIdx.x * GTN;
    int m0 = blockIdx.y * GTM;
    int kbase = SPLITK ? blockIdx.x * Kd : 0;
    int tid = threadIdx.x;
    int warp = tid >> 5, lane = tid & 31;
    int g = lane >> 2, tg = lane & 3;
    int wm = (warp & 1) * 64, wn = (warp >> 1) * 32;

    if (!SPLITK && tid < GTN) sbias[tid] = bias ? bias[bz * sBias + n0 + tid] : 0.f;

    uint32_t asb = (uint32_t)__cvta_generic_to_shared(sh);
    uint32_t bsb = asb + NSTAGE * ASTAGE * 4;

    // ldmatrix per-thread address components
    int lr = lane & 7, ls = lane >> 3;
    int a_row = wm + lr + ((ls & 1) << 3);
    int a_col = (ls >> 1) << 2;
    int b_row = wn + lr;
    int b_col = (ls & 1) << 2;

    float c[4][4][4];
#pragma unroll
    for (int a = 0; a < 4; a++)
#pragma unroll
        for (int b = 0; b < 4; b++)
#pragma unroll
            for (int e = 0; e < 4; e++) c[a][b][e] = 0.f;

    int nt = Kd >> 5;
    stage_tile<BNK>(A, lda, m0, Bm, ldb, n0, asb, bsb, tid, kbase, 0);
    if (nt > 1)
        stage_tile<BNK>(A, lda, m0, Bm, ldb, n0, asb, bsb, tid, kbase + GTK, 1);
    else
        CP_COMMIT;   // keep group alignment

    for (int t = 0; t < nt; t++) {
        CP_WAIT1;                 // tile t landed; t+1 may still be in flight
        __syncthreads();
        if (t + 2 < nt)
            stage_tile<BNK>(A, lda, m0, Bm, ldb, n0, asb, bsb, tid,
                            kbase + (t + 2) * GTK, (t + 2) % NSTAGE);
        else
            CP_COMMIT;            // empty group keeps wait index aligned
        int st = t % NSTAGE;
        uint32_t abuf = asb + st * (ASTAGE * 4);
        uint32_t bbuf = bsb + st * (BSTAGE * 4);
        uint32_t aaddr = abuf + (uint32_t)(a_row * ASTR + a_col) * 4;
        uint32_t baddr = bbuf + (uint32_t)(b_row * ASTR + b_col) * 4;
        const float* BstKN = sh + NSTAGE * ASTAGE + st * BSTAGE;
#pragma unroll
        for (int ks = 0; ks < 4; ks++) {
            const int kk = ks * 8;
            uint32_t af[4][4], bf[4][2];
#pragma unroll
            for (int mi = 0; mi < 4; mi++)
                ldsm4(af[mi], aaddr + (uint32_t)(mi * 16 * ASTR + kk) * 4);
#pragma unroll
            for (int ni = 0; ni < 4; ni++) {
                if (BNK) {
                    ldsm2(bf[ni], baddr + (uint32_t)(ni * 8 * ASTR + kk) * 4);
                } else {
                    const float* bp = BstKN + (kk + tg) * BSTR + wn + ni * 8 + g;
                    bf[ni][0] = __float_as_uint(bp[0]);
                    bf[ni][1] = __float_as_uint(bp[4 * BSTR]);
                }
            }
#pragma unroll
            for (int mi = 0; mi < 4; mi++)
#pragma unroll
                for (int ni = 0; ni < 4; ni++) mma8(c[mi][ni], af[mi], bf[ni]);
        }
    }

#pragma unroll
    for (int mi = 0; mi < 4; mi++) {
#pragma unroll
        for (int ni = 0; ni < 4; ni++) {
            int row = m0 + wm + mi * 16 + g;
            int cb = wn + ni * 8 + 2 * tg;
            int col = n0 + cb;
            float v[4];
#pragma unroll
            for (int e = 0; e < 4; e++) v[e] = c[mi][ni][e] * alpha;
            if (SPLITK) {
                atomicAdd(&C[(long)row * ldc + col],     v[0]);
                atomicAdd(&C[(long)row * ldc + col + 1], v[1]);
                atomicAdd(&C[(long)(row + 8) * ldc + col],     v[2]);
                atomicAdd(&C[(long)(row + 8) * ldc + col + 1], v[3]);
            } else {
                v[0] += sbias[cb];     v[1] += sbias[cb + 1];
                v[2] += sbias[cb];     v[3] += sbias[cb + 1];
                if (ACT == 1) {
#pragma unroll
                    for (int e = 0; e < 4; e++)
                        v[e] = 0.5f * v[e] * (1.f + erff(v[e] * 0.7071067811865475f));
                }
                if (RESID) {
                    v[0] += resid[(long)row * ldc + col];
                    v[1] += resid[(long)row * ldc + col + 1];
                    v[2] += resid[(long)(row + 8) * ldc + col];
                    v[3] += resid[(long)(row + 8) * ldc + col + 1];
                }
                *(float2*)&C[(long)row * ldc + col] = make_float2(v[0], v[1]);
                *(float2*)&C[(long)(row + 8) * ldc + col] = make_float2(v[2], v[3]);
            }
        }
    }
}

// ---------------- tiled transpose: src [K][N] -> dst [N][K] ----------------
__global__ void tp32(const float* __restrict__ src, float* __restrict__ dst,
                     int K, int N) {
    __shared__ __align__(16) float t[32][33];
    int n0 = blockIdx.x * 32, k0 = blockIdx.y * 32;
    int tx = threadIdx.x, ty = threadIdx.y;
#pragma unroll
    for (int i = ty; i < 32; i += 8)
        t[i][tx] = src[(long)(k0 + i) * N + n0 + tx];
    __syncthreads();
#pragma unroll
    for (int i = ty; i < 32; i += 8)
        dst[(long)(n0 + i) * K + k0 + tx] = t[tx][i];
}

// ---------------- bias packing ----------------
__global__ void bias_pack(const float* __restrict__ b1k, const float* __restrict__ b1v,
                          const float* __restrict__ b1q, const float* __restrict__ b2k,
                          const float* __restrict__ b2v, const float* __restrict__ b2q) {
    int i = blockIdx.x * 256 + threadIdx.x;
    if (i < 3072) {
        int ch = i >> 10, col = i & 1023;
        g_b1pack[i] = (ch == 0 ? b1k : ch == 1 ? b1v : b1q)[col];
    } else if (i < 3072 + 384) {
        int j = i - 3072;
        int ch = j >> 7, col = j & 127;
        g_b2pack[j] = (ch == 0 ? b2k : ch == 1 ? b2v : b2q)[col];
    }
}

// ---------------- conv ----------------
#define TBK 32
#define TSTR 136
__device__ __forceinline__ int swz(int k, int m) { return m ^ (((k >> 2) & 7) << 2); }
__device__ __forceinline__ uint32_t f2tf32(float f) {
    uint32_t u;
    asm("cvt.rna.tf32.f32 %0, %1;" : "=r"(u) : "f"(f));
    return u;
}

__global__ void wt_kernel(const float* __restrict__ cw) {
    int idx = blockIdx.x * 256 + threadIdx.x;
    if (idx >= 3 * NGRP * 128 * 128) return;
    int o = idx & 127;
    int k = (idx >> 7) & 127;
    int hg = idx >> 14;
    int h = hg >> 3, grp = hg & 7;
    g_wt[idx] = cw[(((size_t)(grp * 128 + o)) * 128 + k) * 3 + h];
}

__global__ void __launch_bounds__(256, 2) conv_tc(const float* __restrict__ cb) {
    __shared__ __align__(16) uint32_t As[TBK * TSTR];
    __shared__ __align__(16) uint32_t Bs[TBK * TSTR];
    __shared__ __align__(16) float cbs[128];
    int b = blockIdx.z, grp = blockIdx.y, s0 = blockIdx.x * 128;
    int tid = threadIdx.x;
    int warp = tid >> 5, lane = tid & 31;
    int g = lane >> 2, tg = lane & 3;
    int wm = (warp & 1) * 64, wn = (warp >> 1) * 32;

    if (tid < 128) cbs[tid] = cb[grp * 128 + tid];

    float c[4][4][4];
#pragma unroll
    for (int a = 0; a < 4; a++)
#pragma unroll
        for (int d = 0; d < 4; d++)
#pragma unroll
            for (int e = 0; e < 4; e++) c[a][d][e] = 0.f;

    int arow = tid >> 3, acol = (tid & 7) * 4;

    for (int h = 0; h < 3; h++) {
        for (int k0 = 0; k0 < 128; k0 += TBK) {
#pragma unroll
            for (int p = 0; p < 4; p++) {
                int m = arow + p * 32;
                int s = s0 + m + h - 1;
                float4 v = make_float4(0.f, 0.f, 0.f, 0.f);
                if (s >= 0 && s < Ss)
                    v = *(const float4*)&g_qkv[((size_t)(b * Ss) + s) * 3072 + 2048 + grp * 128 + k0 + acol];
                As[(acol + 0) * TSTR + swz(acol + 0, m)] = f2tf32(v.x);
                As[(acol + 1) * TSTR + swz(acol + 1, m)] = f2tf32(v.y);
                As[(acol + 2) * TSTR + swz(acol + 2, m)] = f2tf32(v.z);
                As[(acol + 3) * TSTR + swz(acol + 3, m)] = f2tf32(v.w);
            }
            {
                int n = tid & 127, kb = tid >> 7;
#pragma unroll
                for (int p = 0; p < 16; p++) {
                    int k = kb + p * 2;
                    Bs[k * TSTR + swz(k, n)] =
                        f2tf32(g_wt[(((size_t)(h * NGRP + grp)) * 128 + k0 + k) * 128 + n]);
                }
            }
            __syncthreads();
#pragma unroll
            for (int ks = 0; ks < 4; ks++) {
                int kk = ks * 8;
                uint32_t af[4][4], bf[4][2];
#pragma unroll
                for (int mi = 0; mi < 4; mi++) {
                    int m = wm + mi * 16;
                    af[mi][0] = As[(kk + tg) * TSTR + swz(kk + tg, m + g)];
                    af[mi][1] = As[(kk + tg) * TSTR + swz(kk + tg, m + g + 8)];
                    af[mi][2] = As[(kk + tg + 4) * TSTR + swz(kk + tg + 4, m + g)];
                    af[mi][3] = As[(kk + tg + 4) * TSTR + swz(kk + tg + 4, m + g + 8)];
                }
#pragma unroll
                for (int ni = 0; ni < 4; ni++) {
                    int n = wn + ni * 8;
                    bf[ni][0] = Bs[(kk + tg) * TSTR + swz(kk + tg, n + g)];
                    bf[ni][1] = Bs[(kk + tg + 4) * TSTR + swz(kk + tg + 4, n + g)];
                }
#pragma unroll
                for (int mi = 0; mi < 4; mi++)
#pragma unroll
                    for (int ni = 0; ni < 4; ni++) mma8(c[mi][ni], af[mi], bf[ni]);
            }
            __syncthreads();
        }
    }

#pragma unroll
    for (int mi = 0; mi < 4; mi++) {
#pragma unroll
        for (int ni = 0; ni < 4; ni++) {
            int cbcol = wn + ni * 8 + 2 * tg;
            int o = grp * 128 + cbcol;
#pragma unroll
            for (int half = 0; half < 2; half++) {
                int s = s0 + wm + mi * 16 + g + half * 8;
                size_t idx = ((size_t)(b * Ss) + s) * Dd + o;
                size_t kidx = ((size_t)(b * Ss) + s) * 3072 + 1024 + o;
                float2 mo = *(const float2*)&g_memout[idx];
                float2 kv = *(const float2*)&g_qkv[kidx];
                float gc0 = g_gctx[b * Dd + o], gc1 = g_gctx[b * Dd + o + 1];
                float l0 = c[mi][ni][half * 2 + 0] + cbs[cbcol];
                float l1 = c[mi][ni][half * 2 + 1] + cbs[cbcol + 1];
                float p0 = 1.f / (1.f + expf(-kv.x));
                float p1 = 1.f / (1.f + expf(-kv.y));
                float r0 = (l0 + 0.1f * gc0 + 0.5f * mo.x) * p0;
                float r1 = (l1 + 0.1f * gc1 + 0.5f * mo.y) * p1;
                *(float2*)&g_h[idx] = make_float2(r0, r1);
            }
        }
    }
}

// ---------------- LayerNorm + write-gate ----------------
__global__ void ln_imp_kernel(const float* __restrict__ x,
                              const float* __restrict__ lng,
                              const float* __restrict__ lnb,
                              const float* __restrict__ wgw,
                              const float* __restrict__ wgb) {
    int row = blockIdx.x;
    int tid = threadIdx.x;
    const float* xr = x + (size_t)row * Dd + tid * 4;
    float x0 = xr[0], x1 = xr[1], x2 = xr[2], x3 = xr[3];
    __shared__ float red[256];

    red[tid] = x0 + x1 + x2 + x3; __syncthreads();
    for (int o = 128; o > 0; o >>= 1) { if (tid < o) red[tid] += red[tid + o]; __syncthreads(); }
    float mu = red[0] * (1.f / Dd);
    __syncthreads();

    float d0 = x0 - mu, d1 = x1 - mu, d2 = x2 - mu, d3 = x3 - mu;
    red[tid] = d0 * d0 + d1 * d1 + d2 * d2 + d3 * d3; __syncthreads();
    for (int o = 128; o > 0; o >>= 1) { if (tid < o) red[tid] += red[tid + o]; __syncthreads(); }
    float var = red[0] * (1.f / Dd);
    float rs = rsqrtf(var + 1e-5f);
    __syncthreads();

    float y0 = d0 * rs * lng[tid * 4 + 0] + lnb[tid * 4 + 0];
    float y1 = d1 * rs * lng[tid * 4 + 1] + lnb[tid * 4 + 1];
    float y2 = d2 * rs * lng[tid * 4 + 2] + lnb[tid * 4 + 2];
    float y3 = d3 * rs * lng[tid * 4 + 3] + lnb[tid * 4 + 3];
    ((float4*)(g_xn + (size_t)row * Dd))[tid] = make_float4(y0, y1, y2, y3);

    red[tid] = y0 * wgw[tid * 4 + 0] + y1 * wgw[tid * 4 + 1]
             + y2 * wgw[tid * 4 + 2] + y3 * wgw[tid * 4 + 3];
    __syncthreads();
    for (int o = 128; o > 0; o >>= 1) { if (tid < o) red[tid] += red[tid + o]; __syncthreads(); }
    if (tid == 0) {
        double l = (double)(red[0] + wgb[0]);
        g_sig[row] = (float)(1.0 / (1.0 + exp(-l)));
    }
}

// ---------------- top-k ----------------
__global__ void topk_kernel() {
    __shared__ __align__(16) unsigned long long sk[Ss];
    int b = blockIdx.x, tid = threadIdx.x;
    for (int i = tid; i < Ss; i += 1024) {
        unsigned u = __float_as_uint(g_sig[b * Ss + i]);
        u = (u & 0x80000000u) ? ~u : (u | 0x80000000u);
        sk[i] = ((unsigned long long)u << 32) | (unsigned)(0xFFFFFFFFu - i);
    }
    __syncthreads();
    for (int k = 2; k <= Ss; k <<= 1) {
        for (int j = k >> 1; j > 0; j >>= 1) {
            for (int i = tid; i < Ss; i += 1024) {
                int ixj = i ^ j;
                if (ixj > i) {
                    bool desc = ((i & k) == 0);
                    unsigned long long a = sk[i], c = sk[ixj];
                    if ((a < c) == desc) { sk[i] = c; sk[ixj] = a; }
                }
            }
            __syncthreads();
        }
    }
    for (int i = tid; i < NWRITES; i += 1024)
        g_topidx[b * NWRITES + i] = (int)(0xFFFFFFFFu - (unsigned)sk[i]);
}

// ---------------- splice memory -> d_out ----------------
__global__ void assemble_kernel(const float* __restrict__ md, float* __restrict__ om) {
    int idx = blockIdx.x * blockDim.x + threadIdx.x;
    if (idx >= Bb * Mm * 256) return;
    int c = idx & 255;
    int m = (idx >> 8) & (Mm - 1);
    int b = idx >> 19;
    float val;
    if (m < KEEP) val = md[idx];
    else {
        int id = g_topidx[b * NWRITES + (m - KEEP)];
        val = g_mem2[((size_t)(b * Ss) + id) * 384 + c];
    }
    om[idx] = val;
}

__global__ void zero_retr() {
    int i = blockIdx.x * 256 + threadIdx.x;
    if (i < Bb * Ss * Vv) g_retr[i] = 0.f;
}

// ---------------- small SIMT GEMM (M=4 gctx only) ----------------
#define BM 64
#define BN 64
#define BKg 16
__global__ void gemm_small(const float* __restrict__ A, int lda,
                           const float* __restrict__ Bm, int ldb,
                           const float* __restrict__ bias,
                           float* __restrict__ C, int ldc, int Mr, int Kd) {
    __shared__ __align__(16) float As[BKg][BM + 4];
    __shared__ __align__(16) float Bs[BKg][BN + 4];
    __shared__ __align__(16) float sbias[BN];
    int n0 = blockIdx.x * BN, m0 = blockIdx.y * BM;
    int tid = threadIdx.x;
    int tx = tid & 15, ty = tid >> 4;
    if (tid < BN) sbias[tid] = bias ? bias[n0 + tid] : 0.f;
    float acc[4][4];
#pragma unroll
    for (int i = 0; i < 4; i++)
#pragma unroll
        for (int j = 0; j < 4; j++) acc[i][j] = 0.f;
    int aRow = tid >> 2, aCol = (tid & 3) * 4;
    for (int k0 = 0; k0 < Kd; k0 += BKg) {
        float4 av = make_float4(0.f, 0.f, 0.f, 0.f);
        if (m0 + aRow < Mr)
            av = *(const float4*)&A[(long)(m0 + aRow) * lda + k0 + aCol];
        As[aCol + 0][aRow] = av.x; As[aCol + 1][aRow] = av.y;
        As[aCol + 2][aRow] = av.z; As[aCol + 3][aRow] = av.w;
        int kr = tid >> 4, n = (tid & 15) * 4;
        const float* bp = &Bm[(long)(k0 + kr) * ldb + n0 + n];
        Bs[kr][n + 0] = bp[0]; Bs[kr][n + 1] = bp[1];
        Bs[kr][n + 2] = bp[2]; Bs[kr][n + 3] = bp[3];
        __syncthreads();
#pragma unroll
        for (int kk = 0; kk < BKg; kk++) {
            const float4 a = *(const float4*)&As[kk][ty * 4];
            const float4 b4 = *(const float4*)&Bs[kk][tx * 4];
            float ar[4] = {a.x, a.y, a.z, a.w};
            float br[4] = {b4.x, b4.y, b4.z, b4.w};
#pragma unroll
            for (int ii = 0; ii < 4; ii++)
#pragma unroll
                for (int jj = 0; jj < 4; jj++) acc[ii][jj] += ar[ii] * br[jj];
        }
        __syncthreads();
    }
#pragma unroll
    for (int i = 0; i < 4; i++) {
        int m = m0 + ty * 4 + i;
        if (m >= Mr) break;
#pragma unroll
        for (int j = 0; j < 4; j++) {
            int n = n0 + tx * 4 + j;
            C[(long)m * ldc + n] = acc[i][j] + sbias[tx * 4 + j];
        }
    }
}

// ---------------- row softmax over M=2048 ----------------
__global__ void softmax_kernel(float* __restrict__ sim) {
    long row = blockIdx.x;
    float* p = sim + row * (long)Mm;
    int tid = threadIdx.x;
    float v[8];
    float mx = -3.4e38f;
#pragma unroll
    for (int t = 0; t < 8; t++) { v[t] = p[tid + t * 256]; mx = fmaxf(mx, v[t]); }
    __shared__ float red[256];
    red[tid] = mx; __syncthreads();
    for (int o = 128; o > 0; o >>= 1) { if (tid < o) red[tid] = fmaxf(red[tid], red[tid + o]); __syncthreads(); }
    mx = red[0]; __syncthreads();
    float s = 0.f;
#pragma unroll
    for (int t = 0; t < 8; t++) { v[t] = expf(v[t] - mx); s += v[t]; }
    red[tid] = s; __syncthreads();
    for (int o = 128; o > 0; o >>= 1) { if (tid < o) red[tid] += red[tid + o]; __syncthreads(); }
    float inv = 1.f / red[0];
#pragma unroll
    for (int t = 0; t < 8; t++) p[tid + t * 256] = v[t] * inv;
}

// ---------------- mean over S of queries (packed qkv, stride 3072) ----------------
__global__ void qmean_kernel() {
    int d = blockIdx.x * 256 + threadIdx.x;
    int b = blockIdx.y;
    const float* p = g_qkv + (size_t)b * Ss * 3072 + d;
    double s = 0.0;
    for (int t = 0; t < Ss; t++) s += p[(size_t)t * 3072];
    g_qmean[b * Dd + d] = (float)(s * (1.0 / Ss));
}

// ---------------- launch ----------------
template <int BNK, int ACT, int RESID, int SPLITK>
static void launch_tc(dim3 grid, const float* A, int lda, long sA,
                      const float* B, int ldb, long sB,
                      const float* bias, long sBias, const float* resid,
                      float* C, int ldc, long sC, int Kd, float alpha) {
    cudaFuncSetAttribute(gemm_tc<BNK, ACT, RESID, SPLITK>,
                         cudaFuncAttributeMaxDynamicSharedMemorySize, GEMM_SMEM);
    gemm_tc<BNK, ACT, RESID, SPLITK><<<grid, 256, GEMM_SMEM>>>(
        A, lda, sA, B, ldb, sB, bias, sBias, resid, C, ldc, sC, Kd, alpha);
}

extern "C" void kernel_launch(void* const* d_in, const int* in_sizes, int n_in,
                              void* d_out, int out_size) {
    const float* x      = (const float*)d_in[0];
    const float* memdict= (const float*)d_in[1];
    const float* ln_g   = (const float*)d_in[2];
    const float* ln_b   = (const float*)d_in[3];
    const float* mk_w1  = (const float*)d_in[4];
    const float* mk_b1  = (const float*)d_in[5];
    const float* mk_w2  = (const float*)d_in[6];
    const float* mk_b2  = (const float*)d_in[7];
    const float* mv_w1  = (const float*)d_in[8];
    const float* mv_b1  = (const float*)d_in[9];
    const float* mv_w2  = (const float*)d_in[10];
    const float* mv_b2  = (const float*)d_in[11];
    const float* mq_w1  = (const float*)d_in[12];
    const float* mq_b1  = (const float*)d_in[13];
    const float* mq_w2  = (const float*)d_in[14];
    const float* mq_b2  = (const float*)d_in[15];
    const float* wg_w   = (const float*)d_in[16];
    const float* wg_b   = (const float*)d_in[17];
    const float* q_w    = (const float*)d_in[18];
    const float* k_w    = (const float*)d_in[19];
    const float* v_w    = (const float*)d_in[20];
    const float* conv_w = (const float*)d_in[21];
    const float* conv_b = (const float*)d_in[22];
    const float* gp_w   = (const float*)d_in[23];
    const float* gp_b   = (const float*)d_in[24];
    const float* mr_w   = (const float*)d_in[25];
    const float* mr_b   = (const float*)d_in[26];
    const float* out_w  = (const float*)d_in[27];
    const float* out_b  = (const float*)d_in[28];

    float* out_main = (float*)d_out;
    float* out_mem  = out_main + (size_t)Bb * Ss * Dd;

    float *p_xn, *p_h, *p_hpack, *p_qkv, *p_mem2, *p_sim, *p_retr, *p_memout, *p_qmean, *p_gctx;
    float *p_w1T, *p_qkvT, *p_w2T, *p_mrwT, *p_outT, *p_b1, *p_b2;
    cudaGetSymbolAddress((void**)&p_xn, g_xn);
    cudaGetSymbolAddress((void**)&p_h, g_h);
    cudaGetSymbolAddress((void**)&p_hpack, g_hpack);
    cudaGetSymbolAddress((void**)&p_qkv, g_qkv);
    cudaGetSymbolAddress((void**)&p_mem2, g_mem2);
    cudaGetSymbolAddress((void**)&p_sim, g_sim);
    cudaGetSymbolAddress((void**)&p_retr, g_retr);
    cudaGetSymbolAddress((void**)&p_memout, g_memout);
    cudaGetSymbolAddress((void**)&p_qmean, g_qmean);
    cudaGetSymbolAddress((void**)&p_gctx, g_gctx);
    cudaGetSymbolAddress((void**)&p_w1T, g_w1T);
    cudaGetSymbolAddress((void**)&p_qkvT, g_qkvT);
    cudaGetSymbolAddress((void**)&p_w2T, g_w2T);
    cudaGetSymbolAddress((void**)&p_mrwT, g_mrwT);
    cudaGetSymbolAddress((void**)&p_outT, g_outT);
    cudaGetSymbolAddress((void**)&p_b1, g_b1pack);
    cudaGetSymbolAddress((void**)&p_b2, g_b2pack);

    const int ROWS = Bb * Ss;   // 16384
    dim3 tpb(32, 8);

    // prep
    ln_imp_kernel<<<ROWS, 256>>>(x, ln_g, ln_b, wg_w, wg_b);
    wt_kernel<<<(3 * NGRP * 128 * 128 + 255) / 256, 256>>>(conv_w);
    tp32<<<dim3(32, 32), tpb>>>(mk_w1, p_w1T + 0 * Dd * Dd, Dd, Dd);
    tp32<<<dim3(32, 32), tpb>>>(mv_w1, p_w1T + 1 * Dd * Dd, Dd, Dd);
    tp32<<<dim3(32, 32), tpb>>>(mq_w1, p_w1T + 2 * Dd * Dd, Dd, Dd);
    tp32<<<dim3(32, 32), tpb>>>(q_w, p_qkvT + 0 * Dd * Dd, Dd, Dd);
    tp32<<<dim3(32, 32), tpb>>>(k_w, p_qkvT + 1 * Dd * Dd, Dd, Dd);
    tp32<<<dim3(32, 32), tpb>>>(v_w, p_qkvT + 2 * Dd * Dd, Dd, Dd);
    tp32<<<dim3(4, 32), tpb>>>(mk_w2, p_w2T + 0 * 128 * Dd, Dd, 128);
    tp32<<<dim3(4, 32), tpb>>>(mv_w2, p_w2T + 1 * 128 * Dd, Dd, 128);
    tp32<<<dim3(4, 32), tpb>>>(mq_w2, p_w2T + 2 * 128 * Dd, Dd, 128);
    tp32<<<dim3(32, 4), tpb>>>(mr_w, p_mrwT, 128, Dd);
    tp32<<<dim3(32, 32), tpb>>>(out_w, p_outT, Dd, Dd);
    bias_pack<<<(3456 + 255) / 256, 256>>>(mk_b1, mv_b1, mq_b1, mk_b2, mv_b2, mq_b2);
    topk_kernel<<<Bb, 1024>>>();

    // fused MLP1 (3 chains)
    launch_tc<1, 1, 0, 0>(dim3(24, 128), p_xn, Dd, 0, p_w1T, Dd, 0, p_b1, 0, nullptr,
                          p_hpack, 3072, 0, Dd, 1.f);
    // fused MLP2 (grid.z selects chain)
    launch_tc<1, 0, 0, 0>(dim3(1, 128, 3), p_hpack, 3072, 1024, p_w2T, Dd, (long)128 * Dd,
                          p_b2, 128, nullptr, p_mem2, 384, 128, Dd, 1.f);
    // splice memory into d_out
    assemble_kernel<<<(Bb * Mm * 256 + 255) / 256, 256>>>(memdict, out_mem);

    // sim = memq @ K^T / sqrt(K)
    launch_tc<1, 0, 0, 0>(dim3(16, 32, Bb), p_mem2 + 256, 384, (long)Ss * 384,
                          out_mem, 256, (long)Mm * 256, nullptr, 0, nullptr,
                          p_sim, Mm, (long)Ss * Mm, Kk, 0.08838834764831845f);
    softmax_kernel<<<ROWS, 256>>>(p_sim);
    // retrieved = attn @ V  (split-K x8, atomic)
    zero_retr<<<(Bb * Ss * Vv + 255) / 256, 256>>>();
    launch_tc<0, 0, 0, 1>(dim3(8, 32, Bb), p_sim, Mm, (long)Ss * Mm,
                          out_mem + Kk, 256, (long)Mm * 256, nullptr, 0, nullptr,
                          p_retr, Vv, (long)Ss * Vv, Mm / 8, 1.f);
    // memory_output = retrieved @ mr_w + mr_b
    launch_tc<1, 0, 0, 0>(dim3(8, 128), p_retr, Vv, 0, p_mrwT, Vv, 0, mr_b, 0, nullptr,
                          p_memout, Dd, 0, Vv, 1.f);

    // fused QKV
    launch_tc<1, 0, 0, 0>(dim3(24, 128), p_xn, Dd, 0, p_qkvT, Dd, 0, nullptr, 0, nullptr,
                          p_qkv, 3072, 0, Dd, 1.f);

    // mean(queries); global ctx projection
    qmean_kernel<<<dim3(Dd / 256, Bb), 256>>>();
    gemm_small<<<dim3(Dd / BN, 1), 256>>>(p_qmean, Dd, gp_w, Dd, gp_b, p_gctx, Dd, Bb, Dd);

    // conv + combine -> g_h
    conv_tc<<<dim3(Ss / 128, NGRP, Bb), 256>>>(conv_b);

    // output = combined @ out_w + out_b + residual(x)
    launch_tc<1, 0, 1, 0>(dim3(8, 128), p_h, Dd, 0, p_outT, Dd, 0, out_b, 0, x,
                          out_main, Dd, 0, Dd, 1.f);
}

// round 12
// speedup vs baseline: 4.6576x; 1.3135x over previous
#include <cuda_runtime.h>
#include <math.h>
#include <stdint.h>

#define Bb 4
#define Ss 4096
#define Dd 1024
#define Mm 2048
#define Kk 128
#define Vv 128
#define NGRP 8
#define NWRITES 1024
#define KEEP 1024

// ---------------- scratch ----------------
__device__ __align__(16) float g_xn[Bb * Ss * Dd];
__device__ __align__(16) float g_h[Bb * Ss * Dd];                 // combined
__device__ __align__(16) float g_hpack[(size_t)Bb * Ss * 3072];   // MLP1 hidden (3 chains)
__device__ __align__(16) float g_qkv[(size_t)Bb * Ss * 3072];     // q|k|v packed
__device__ __align__(16) float g_mem2[Bb * Ss * 384];             // memk|memv|memq packed
__device__ __align__(16) float g_sig[Bb * Ss];
__device__ __align__(16) int   g_topidx[Bb * NWRITES];
__device__ __align__(16) float g_sim[(size_t)Bb * Ss * Mm];
__device__ __align__(16) float g_retr[Bb * Ss * Vv];
__device__ __align__(16) float g_memout[Bb * Ss * Dd];
__device__ __align__(16) float g_qmean[Bb * Dd];
__device__ __align__(16) float g_gctx[Bb * Dd];
__device__ __align__(16) float g_wt[3 * NGRP * 128 * 128];
// transposed ([n][k]) weights
__device__ __align__(16) float g_w1T[3 * Dd * Dd];
__device__ __align__(16) float g_qkvT[3 * Dd * Dd];
__device__ __align__(16) float g_w2T[3 * 128 * Dd];
__device__ __align__(16) float g_mrwT[Dd * Vv];
__device__ __align__(16) float g_outT[Dd * Dd];
__device__ __align__(16) float g_b1pack[3072];
__device__ __align__(16) float g_b2pack[384];

// ---------------- mma / cp.async / ldmatrix helpers ----------------
__device__ __forceinline__ void mma8(float* c, const uint32_t* a, const uint32_t* b) {
    asm volatile(
        "mma.sync.aligned.m16n8k8.row.col.f32.tf32.tf32.f32 "
        "{%0,%1,%2,%3}, {%4,%5,%6,%7}, {%8,%9}, {%0,%1,%2,%3};\n"
        : "+f"(c[0]), "+f"(c[1]), "+f"(c[2]), "+f"(c[3])
        : "r"(a[0]), "r"(a[1]), "r"(a[2]), "r"(a[3]), "r"(b[0]), "r"(b[1]));
}
__device__ __forceinline__ void cpa16(uint32_t dst, const float* src) {
    asm volatile("cp.async.cg.shared.global [%0], [%1], 16;\n" :: "r"(dst), "l"(src));
}
#define CP_COMMIT asm volatile("cp.async.commit_group;\n" ::: "memory")
#define CP_WAIT1  asm volatile("cp.async.wait_group 1;\n" ::: "memory")
__device__ __forceinline__ void ldsm4(uint32_t* r, uint32_t addr) {
    asm volatile("ldmatrix.sync.aligned.m8n8.x4.shared.b16 {%0,%1,%2,%3}, [%4];\n"
                 : "=r"(r[0]), "=r"(r[1]), "=r"(r[2]), "=r"(r[3]) : "r"(addr));
}
__device__ __forceinline__ void ldsm2(uint32_t* r, uint32_t addr) {
    asm volatile("ldmatrix.sync.aligned.m8n8.x2.shared.b16 {%0,%1}, [%2];\n"
                 : "=r"(r[0]), "=r"(r[1]) : "r"(addr));
}

// gemm tile geometry: 128x128 block, K-tile 32, 3-stage pipeline
#define GTM 128
#define GTN 128
#define GTK 32
#define ASTR 36
#define BSTR 136
#define ASTAGE (128 * ASTR)
#define BSTAGE 4608
#define NSTAGE 3
#define GEMM_SMEM ((NSTAGE * ASTAGE + NSTAGE * BSTAGE) * 4)   // 110592 bytes

template <int BNK>
__device__ __forceinline__ void stage_tile(
    const float* __restrict__ A, int lda, int m0,
    const float* __restrict__ Bm, int ldb, int n0,
    uint32_t asb, uint32_t bsb, int tid, int k0, int st)
{
    uint32_t ad = asb + st * (ASTAGE * 4);
    int c = tid;
#pragma unroll
    for (int p = 0; p < 4; p++, c += 256) {
        int m = c >> 3, ko = (c & 7) * 4;
        cpa16(ad + (uint32_t)(m * ASTR + ko) * 4, A + (long)(m0 + m) * lda + k0 + ko);
    }
    uint32_t bd = bsb + st * (BSTAGE * 4);
    if (BNK) {
        int c2 = tid;
#pragma unroll
        for (int p = 0; p < 4; p++, c2 += 256) {
            int n = c2 >> 3, ko = (c2 & 7) * 4;
            cpa16(bd + (uint32_t)(n * ASTR + ko) * 4, Bm + (long)(n0 + n) * ldb + k0 + ko);
        }
    } else {
        int c2 = tid;
#pragma unroll
        for (int p = 0; p < 4; p++, c2 += 256) {
            int k = c2 >> 5, no = (c2 & 31) * 4;
            cpa16(bd + (uint32_t)(k * BSTR + no) * 4, Bm + (long)(k0 + k) * ldb + n0 + no);
        }
    }
    CP_COMMIT;
}

// ---------------- tf32 GEMM, 3-stage cp.async, ldmatrix fragments ----------------
template <int BNK, int ACT, int RESID, int SPLITK>
__global__ void __launch_bounds__(256, 2) gemm_tc(
    const float* __restrict__ A, int lda, long sA,
    const float* __restrict__ Bm, int ldb, long sB,
    const float* __restrict__ bias, long sBias,
    const float* __restrict__ resid,
    float* __restrict__ C, int ldc, long sC,
    int Kd, float alpha)
{
    extern __shared__ __align__(16) float sh[];
    __shared__ __align__(16) float sbias[GTN];
    long bz = blockIdx.z;
    A += bz * sA; Bm += bz * sB; C += bz * sC;
    if (RESID) resid += bz * sC;
    int n0 = SPLITK ? 0 : blockIdx.x * GTN;
    int m0 = blockIdx.y * GTM;
    int kbase = SPLITK ? blockIdx.x * Kd : 0;
    int tid = threadIdx.x;
    int warp = tid >> 5, lane = tid & 31;
    int g = lane >> 2, tg = lane & 3;
    int wm = (warp & 1) * 64, wn = (warp >> 1) * 32;

    if (!SPLITK && tid < GTN) sbias[tid] = bias ? bias[bz * sBias + n0 + tid] : 0.f;

    uint32_t asb = (uint32_t)__cvta_generic_to_shared(sh);
    uint32_t bsb = asb + NSTAGE * ASTAGE * 4;

    int lr = lane & 7, ls = lane >> 3;
    int a_row = wm + lr + ((ls & 1) << 3);
    int a_col = (ls >> 1) << 2;
    int b_row = wn + lr;
    int b_col = (ls & 1) << 2;

    float c[4][4][4];
#pragma unroll
    for (int a = 0; a < 4; a++)
#pragma unroll
        for (int b = 0; b < 4; b++)
#pragma unroll
            for (int e = 0; e < 4; e++) c[a][b][e] = 0.f;

    int nt = Kd >> 5;
    stage_tile<BNK>(A, lda, m0, Bm, ldb, n0, asb, bsb, tid, kbase, 0);
    if (nt > 1)
        stage_tile<BNK>(A, lda, m0, Bm, ldb, n0, asb, bsb, tid, kbase + GTK, 1);
    else
        CP_COMMIT;

    for (int t = 0; t < nt; t++) {
        CP_WAIT1;
        __syncthreads();
        if (t + 2 < nt)
            stage_tile<BNK>(A, lda, m0, Bm, ldb, n0, asb, bsb, tid,
                            kbase + (t + 2) * GTK, (t + 2) % NSTAGE);
        else
            CP_COMMIT;
        int st = t % NSTAGE;
        uint32_t abuf = asb + st * (ASTAGE * 4);
        uint32_t bbuf = bsb + st * (BSTAGE * 4);
        uint32_t aaddr = abuf + (uint32_t)(a_row * ASTR + a_col) * 4;
        uint32_t baddr = bbuf + (uint32_t)(b_row * ASTR + b_col) * 4;
        const float* BstKN = sh + NSTAGE * ASTAGE + st * BSTAGE;
#pragma unroll
        for (int ks = 0; ks < 4; ks++) {
            const int kk = ks * 8;
            uint32_t af[4][4], bf[4][2];
#pragma unroll
            for (int mi = 0; mi < 4; mi++)
                ldsm4(af[mi], aaddr + (uint32_t)(mi * 16 * ASTR + kk) * 4);
#pragma unroll
            for (int ni = 0; ni < 4; ni++) {
                if (BNK) {
                    ldsm2(bf[ni], baddr + (uint32_t)(ni * 8 * ASTR + kk) * 4);
                } else {
                    const float* bp = BstKN + (kk + tg) * BSTR + wn + ni * 8 + g;
                    bf[ni][0] = __float_as_uint(bp[0]);
                    bf[ni][1] = __float_as_uint(bp[4 * BSTR]);
                }
            }
#pragma unroll
            for (int mi = 0; mi < 4; mi++)
#pragma unroll
                for (int ni = 0; ni < 4; ni++) mma8(c[mi][ni], af[mi], bf[ni]);
        }
    }

#pragma unroll
    for (int mi = 0; mi < 4; mi++) {
#pragma unroll
        for (int ni = 0; ni < 4; ni++) {
            int row = m0 + wm + mi * 16 + g;
            int cb = wn + ni * 8 + 2 * tg;
            int col = n0 + cb;
            float v[4];
#pragma unroll
            for (int e = 0; e < 4; e++) v[e] = c[mi][ni][e] * alpha;
            if (SPLITK) {
                atomicAdd(&C[(long)row * ldc + col],     v[0]);
                atomicAdd(&C[(long)row * ldc + col + 1], v[1]);
                atomicAdd(&C[(long)(row + 8) * ldc + col],     v[2]);
                atomicAdd(&C[(long)(row + 8) * ldc + col + 1], v[3]);
            } else {
                v[0] += sbias[cb];     v[1] += sbias[cb + 1];
                v[2] += sbias[cb];     v[3] += sbias[cb + 1];
                if (ACT == 1) {
#pragma unroll
                    for (int e = 0; e < 4; e++)
                        v[e] = 0.5f * v[e] * (1.f + erff(v[e] * 0.7071067811865475f));
                }
                if (RESID) {
                    v[0] += resid[(long)row * ldc + col];
                    v[1] += resid[(long)row * ldc + col + 1];
                    v[2] += resid[(long)(row + 8) * ldc + col];
                    v[3] += resid[(long)(row + 8) * ldc + col + 1];
                }
                *(float2*)&C[(long)row * ldc + col] = make_float2(v[0], v[1]);
                *(float2*)&C[(long)(row + 8) * ldc + col] = make_float2(v[2], v[3]);
            }
        }
    }
}

// ---------------- tiled transpose: src [K][N] -> dst [N][K] ----------------
__global__ void tp32(const float* __restrict__ src, float* __restrict__ dst,
                     int K, int N) {
    __shared__ __align__(16) float t[32][33];
    int n0 = blockIdx.x * 32, k0 = blockIdx.y * 32;
    int tx = threadIdx.x, ty = threadIdx.y;
#pragma unroll
    for (int i = ty; i < 32; i += 8)
        t[i][tx] = src[(long)(k0 + i) * N + n0 + tx];
    __syncthreads();
#pragma unroll
    for (int i = ty; i < 32; i += 8)
        dst[(long)(n0 + i) * K + k0 + tx] = t[tx][i];
}

// ---------------- bias packing ----------------
__global__ void bias_pack(const float* __restrict__ b1k, const float* __restrict__ b1v,
                          const float* __restrict__ b1q, const float* __restrict__ b2k,
                          const float* __restrict__ b2v, const float* __restrict__ b2q) {
    int i = blockIdx.x * 256 + threadIdx.x;
    if (i < 3072) {
        int ch = i >> 10, col = i & 1023;
        g_b1pack[i] = (ch == 0 ? b1k : ch == 1 ? b1v : b1q)[col];
    } else if (i < 3072 + 384) {
        int j = i - 3072;
        int ch = j >> 7, col = j & 127;
        g_b2pack[j] = (ch == 0 ? b2k : ch == 1 ? b2v : b2q)[col];
    }
}

// ---------------- conv ----------------
#define TBK 32
#define TSTR 136
__device__ __forceinline__ int swz(int k, int m) { return m ^ (((k >> 2) & 7) << 2); }
__device__ __forceinline__ uint32_t f2tf32(float f) {
    uint32_t u;
    asm("cvt.rna.tf32.f32 %0, %1;" : "=r"(u) : "f"(f));
    return u;
}

__global__ void wt_kernel(const float* __restrict__ cw) {
    int idx = blockIdx.x * 256 + threadIdx.x;
    if (idx >= 3 * NGRP * 128 * 128) return;
    int o = idx & 127;
    int k = (idx >> 7) & 127;
    int hg = idx >> 14;
    int h = hg >> 3, grp = hg & 7;
    g_wt[idx] = cw[(((size_t)(grp * 128 + o)) * 128 + k) * 3 + h];
}

__global__ void __launch_bounds__(256, 2) conv_tc(const float* __restrict__ cb) {
    __shared__ __align__(16) uint32_t As[TBK * TSTR];
    __shared__ __align__(16) uint32_t Bs[TBK * TSTR];
    __shared__ __align__(16) float cbs[128];
    int b = blockIdx.z, grp = blockIdx.y, s0 = blockIdx.x * 128;
    int tid = threadIdx.x;
    int warp = tid >> 5, lane = tid & 31;
    int g = lane >> 2, tg = lane & 3;
    int wm = (warp & 1) * 64, wn = (warp >> 1) * 32;

    if (tid < 128) cbs[tid] = cb[grp * 128 + tid];

    float c[4][4][4];
#pragma unroll
    for (int a = 0; a < 4; a++)
#pragma unroll
        for (int d = 0; d < 4; d++)
#pragma unroll
            for (int e = 0; e < 4; e++) c[a][d][e] = 0.f;

    int arow = tid >> 3, acol = (tid & 7) * 4;

    for (int h = 0; h < 3; h++) {
        for (int k0 = 0; k0 < 128; k0 += TBK) {
#pragma unroll
            for (int p = 0; p < 4; p++) {
                int m = arow + p * 32;
                int s = s0 + m + h - 1;
                float4 v = make_float4(0.f, 0.f, 0.f, 0.f);
                if (s >= 0 && s < Ss)
                    v = *(const float4*)&g_qkv[((size_t)(b * Ss) + s) * 3072 + 2048 + grp * 128 + k0 + acol];
                As[(acol + 0) * TSTR + swz(acol + 0, m)] = f2tf32(v.x);
                As[(acol + 1) * TSTR + swz(acol + 1, m)] = f2tf32(v.y);
                As[(acol + 2) * TSTR + swz(acol + 2, m)] = f2tf32(v.z);
                As[(acol + 3) * TSTR + swz(acol + 3, m)] = f2tf32(v.w);
            }
            {
                int n = tid & 127, kb = tid >> 7;
#pragma unroll
                for (int p = 0; p < 16; p++) {
                    int k = kb + p * 2;
                    Bs[k * TSTR + swz(k, n)] =
                        f2tf32(g_wt[(((size_t)(h * NGRP + grp)) * 128 + k0 + k) * 128 + n]);
                }
            }
            __syncthreads();
#pragma unroll
            for (int ks = 0; ks < 4; ks++) {
                int kk = ks * 8;
                uint32_t af[4][4], bf[4][2];
#pragma unroll
                for (int mi = 0; mi < 4; mi++) {
                    int m = wm + mi * 16;
                    af[mi][0] = As[(kk + tg) * TSTR + swz(kk + tg, m + g)];
                    af[mi][1] = As[(kk + tg) * TSTR + swz(kk + tg, m + g + 8)];
                    af[mi][2] = As[(kk + tg + 4) * TSTR + swz(kk + tg + 4, m + g)];
                    af[mi][3] = As[(kk + tg + 4) * TSTR + swz(kk + tg + 4, m + g + 8)];
                }
#pragma unroll
                for (int ni = 0; ni < 4; ni++) {
                    int n = wn + ni * 8;
                    bf[ni][0] = Bs[(kk + tg) * TSTR + swz(kk + tg, n + g)];
                    bf[ni][1] = Bs[(kk + tg + 4) * TSTR + swz(kk + tg + 4, n + g)];
                }
#pragma unroll
                for (int mi = 0; mi < 4; mi++)
#pragma unroll
                    for (int ni = 0; ni < 4; ni++) mma8(c[mi][ni], af[mi], bf[ni]);
            }
            __syncthreads();
        }
    }

#pragma unroll
    for (int mi = 0; mi < 4; mi++) {
#pragma unroll
        for (int ni = 0; ni < 4; ni++) {
            int cbcol = wn + ni * 8 + 2 * tg;
            int o = grp * 128 + cbcol;
#pragma unroll
            for (int half = 0; half < 2; half++) {
                int s = s0 + wm + mi * 16 + g + half * 8;
                size_t idx = ((size_t)(b * Ss) + s) * Dd + o;
                size_t kidx = ((size_t)(b * Ss) + s) * 3072 + 1024 + o;
                float2 mo = *(const float2*)&g_memout[idx];
                float2 kv = *(const float2*)&g_qkv[kidx];
                float gc0 = g_gctx[b * Dd + o], gc1 = g_gctx[b * Dd + o + 1];
                float l0 = c[mi][ni][half * 2 + 0] + cbs[cbcol];
                float l1 = c[mi][ni][half * 2 + 1] + cbs[cbcol + 1];
                float p0 = 1.f / (1.f + expf(-kv.x));
                float p1 = 1.f / (1.f + expf(-kv.y));
                float r0 = (l0 + 0.1f * gc0 + 0.5f * mo.x) * p0;
                float r1 = (l1 + 0.1f * gc1 + 0.5f * mo.y) * p1;
                *(float2*)&g_h[idx] = make_float2(r0, r1);
            }
        }
    }
}

// ---------------- LayerNorm + write-gate ----------------
__global__ void ln_imp_kernel(const float* __restrict__ x,
                              const float* __restrict__ lng,
                              const float* __restrict__ lnb,
                              const float* __restrict__ wgw,
                              const float* __restrict__ wgb) {
    int row = blockIdx.x;
    int tid = threadIdx.x;
    const float* xr = x + (size_t)row * Dd + tid * 4;
    float x0 = xr[0], x1 = xr[1], x2 = xr[2], x3 = xr[3];
    __shared__ float red[256];

    red[tid] = x0 + x1 + x2 + x3; __syncthreads();
    for (int o = 128; o > 0; o >>= 1) { if (tid < o) red[tid] += red[tid + o]; __syncthreads(); }
    float mu = red[0] * (1.f / Dd);
    __syncthreads();

    float d0 = x0 - mu, d1 = x1 - mu, d2 = x2 - mu, d3 = x3 - mu;
    red[tid] = d0 * d0 + d1 * d1 + d2 * d2 + d3 * d3; __syncthreads();
    for (int o = 128; o > 0; o >>= 1) { if (tid < o) red[tid] += red[tid + o]; __syncthreads(); }
    float var = red[0] * (1.f / Dd);
    float rs = rsqrtf(var + 1e-5f);
    __syncthreads();

    float y0 = d0 * rs * lng[tid * 4 + 0] + lnb[tid * 4 + 0];
    float y1 = d1 * rs * lng[tid * 4 + 1] + lnb[tid * 4 + 1];
    float y2 = d2 * rs * lng[tid * 4 + 2] + lnb[tid * 4 + 2];
    float y3 = d3 * rs * lng[tid * 4 + 3] + lnb[tid * 4 + 3];
    ((float4*)(g_xn + (size_t)row * Dd))[tid] = make_float4(y0, y1, y2, y3);

    red[tid] = y0 * wgw[tid * 4 + 0] + y1 * wgw[tid * 4 + 1]
             + y2 * wgw[tid * 4 + 2] + y3 * wgw[tid * 4 + 3];
    __syncthreads();
    for (int o = 128; o > 0; o >>= 1) { if (tid < o) red[tid] += red[tid + o]; __syncthreads(); }
    if (tid == 0) {
        double l = (double)(red[0] + wgb[0]);
        g_sig[row] = (float)(1.0 / (1.0 + exp(-l)));
    }
}

// ---------------- top-k ----------------
__global__ void topk_kernel() {
    __shared__ __align__(16) unsigned long long sk[Ss];
    int b = blockIdx.x, tid = threadIdx.x;
    for (int i = tid; i < Ss; i += 1024) {
        unsigned u = __float_as_uint(g_sig[b * Ss + i]);
        u = (u & 0x80000000u) ? ~u : (u | 0x80000000u);
        sk[i] = ((unsigned long long)u << 32) | (unsigned)(0xFFFFFFFFu - i);
    }
    __syncthreads();
    for (int k = 2; k <= Ss; k <<= 1) {
        for (int j = k >> 1; j > 0; j >>= 1) {
            for (int i = tid; i < Ss; i += 1024) {
                int ixj = i ^ j;
                if (ixj > i) {
                    bool desc = ((i & k) == 0);
                    unsigned long long a = sk[i], c = sk[ixj];
                    if ((a < c) == desc) { sk[i] = c; sk[ixj] = a; }
                }
            }
            __syncthreads();
        }
    }
    for (int i = tid; i < NWRITES; i += 1024)
        g_topidx[b * NWRITES + i] = (int)(0xFFFFFFFFu - (unsigned)sk[i]);
}

// ---------------- splice memory -> d_out ----------------
__global__ void assemble_kernel(const float* __restrict__ md, float* __restrict__ om) {
    int idx = blockIdx.x * blockDim.x + threadIdx.x;
    if (idx >= Bb * Mm * 256) return;
    int c = idx & 255;
    int m = (idx >> 8) & (Mm - 1);
    int b = idx >> 19;
    float val;
    if (m < KEEP) val = md[idx];
    else {
        int id = g_topidx[b * NWRITES + (m - KEEP)];
        val = g_mem2[((size_t)(b * Ss) + id) * 384 + c];
    }
    om[idx] = val;
}

__global__ void zero_retr() {
    int i = blockIdx.x * 256 + threadIdx.x;
    if (i < Bb * Ss * Vv) g_retr[i] = 0.f;
}

// ---------------- small SIMT GEMM (M=4 gctx only) ----------------
#define BM 64
#define BN 64
#define BKg 16
__global__ void gemm_small(const float* __restrict__ A, int lda,
                           const float* __restrict__ Bm, int ldb,
                           const float* __restrict__ bias,
                           float* __restrict__ C, int ldc, int Mr, int Kd) {
    __shared__ __align__(16) float As[BKg][BM + 4];
    __shared__ __align__(16) float Bs[BKg][BN + 4];
    __shared__ __align__(16) float sbias[BN];
    int n0 = blockIdx.x * BN, m0 = blockIdx.y * BM;
    int tid = threadIdx.x;
    int tx = tid & 15, ty = tid >> 4;
    if (tid < BN) sbias[tid] = bias ? bias[n0 + tid] : 0.f;
    float acc[4][4];
#pragma unroll
    for (int i = 0; i < 4; i++)
#pragma unroll
        for (int j = 0; j < 4; j++) acc[i][j] = 0.f;
    int aRow = tid >> 2, aCol = (tid & 3) * 4;
    for (int k0 = 0; k0 < Kd; k0 += BKg) {
        float4 av = make_float4(0.f, 0.f, 0.f, 0.f);
        if (m0 + aRow < Mr)
            av = *(const float4*)&A[(long)(m0 + aRow) * lda + k0 + aCol];
        As[aCol + 0][aRow] = av.x; As[aCol + 1][aRow] = av.y;
        As[aCol + 2][aRow] = av.z; As[aCol + 3][aRow] = av.w;
        int kr = tid >> 4, n = (tid & 15) * 4;
        const float* bp = &Bm[(long)(k0 + kr) * ldb + n0 + n];
        Bs[kr][n + 0] = bp[0]; Bs[kr][n + 1] = bp[1];
        Bs[kr][n + 2] = bp[2]; Bs[kr][n + 3] = bp[3];
        __syncthreads();
#pragma unroll
        for (int kk = 0; kk < BKg; kk++) {
            const float4 a = *(const float4*)&As[kk][ty * 4];
            const float4 b4 = *(const float4*)&Bs[kk][tx * 4];
            float ar[4] = {a.x, a.y, a.z, a.w};
            float br[4] = {b4.x, b4.y, b4.z, b4.w};
#pragma unroll
            for (int ii = 0; ii < 4; ii++)
#pragma unroll
                for (int jj = 0; jj < 4; jj++) acc[ii][jj] += ar[ii] * br[jj];
        }
        __syncthreads();
    }
#pragma unroll
    for (int i = 0; i < 4; i++) {
        int m = m0 + ty * 4 + i;
        if (m >= Mr) break;
#pragma unroll
        for (int j = 0; j < 4; j++) {
            int n = n0 + tx * 4 + j;
            C[(long)m * ldc + n] = acc[i][j] + sbias[tx * 4 + j];
        }
    }
}

// ---------------- row softmax over M=2048 ----------------
__global__ void softmax_kernel(float* __restrict__ sim) {
    long row = blockIdx.x;
    float* p = sim + row * (long)Mm;
    int tid = threadIdx.x;
    float v[8];
    float mx = -3.4e38f;
#pragma unroll
    for (int t = 0; t < 8; t++) { v[t] = p[tid + t * 256]; mx = fmaxf(mx, v[t]); }
    __shared__ float red[256];
    red[tid] = mx; __syncthreads();
    for (int o = 128; o > 0; o >>= 1) { if (tid < o) red[tid] = fmaxf(red[tid], red[tid + o]); __syncthreads(); }
    mx = red[0]; __syncthreads();
    float s = 0.f;
#pragma unroll
    for (int t = 0; t < 8; t++) { v[t] = expf(v[t] - mx); s += v[t]; }
    red[tid] = s; __syncthreads();
    for (int o = 128; o > 0; o >>= 1) { if (tid < o) red[tid] += red[tid + o]; __syncthreads(); }
    float inv = 1.f / red[0];
#pragma unroll
    for (int t = 0; t < 8; t++) p[tid + t * 256] = v[t] * inv;
}

// ---------------- mean over S of queries (packed qkv, stride 3072) ----------------
__global__ void qmean_kernel() {
    int d = blockIdx.x * 256 + threadIdx.x;
    int b = blockIdx.y;
    const float* p = g_qkv + (size_t)b * Ss * 3072 + d;
    double s = 0.0;
    for (int t = 0; t < Ss; t++) s += p[(size_t)t * 3072];
    g_qmean[b * Dd + d] = (float)(s * (1.0 / Ss));
}

// ---------------- launch ----------------
template <int BNK, int ACT, int RESID, int SPLITK>
static void launch_tc(dim3 grid, cudaStream_t st, const float* A, int lda, long sA,
                      const float* B, int ldb, long sB,
                      const float* bias, long sBias, const float* resid,
                      float* C, int ldc, long sC, int Kd, float alpha) {
    cudaFuncSetAttribute(gemm_tc<BNK, ACT, RESID, SPLITK>,
                         cudaFuncAttributeMaxDynamicSharedMemorySize, GEMM_SMEM);
    gemm_tc<BNK, ACT, RESID, SPLITK><<<grid, 256, GEMM_SMEM, st>>>(
        A, lda, sA, B, ldb, sB, bias, sBias, resid, C, ldc, sC, Kd, alpha);
}

extern "C" void kernel_launch(void* const* d_in, const int* in_sizes, int n_in,
                              void* d_out, int out_size) {
    const float* x      = (const float*)d_in[0];
    const float* memdict= (const float*)d_in[1];
    const float* ln_g   = (const float*)d_in[2];
    const float* ln_b   = (const float*)d_in[3];
    const float* mk_w1  = (const float*)d_in[4];
    const float* mk_b1  = (const float*)d_in[5];
    const float* mk_w2  = (const float*)d_in[6];
    const float* mk_b2  = (const float*)d_in[7];
    const float* mv_w1  = (const float*)d_in[8];
    const float* mv_b1  = (const float*)d_in[9];
    const float* mv_w2  = (const float*)d_in[10];
    const float* mv_b2  = (const float*)d_in[11];
    const float* mq_w1  = (const float*)d_in[12];
    const float* mq_b1  = (const float*)d_in[13];
    const float* mq_w2  = (const float*)d_in[14];
    const float* mq_b2  = (const float*)d_in[15];
    const float* wg_w   = (const float*)d_in[16];
    const float* wg_b   = (const float*)d_in[17];
    const float* q_w    = (const float*)d_in[18];
    const float* k_w    = (const float*)d_in[19];
    const float* v_w    = (const float*)d_in[20];
    const float* conv_w = (const float*)d_in[21];
    const float* conv_b = (const float*)d_in[22];
    const float* gp_w   = (const float*)d_in[23];
    const float* gp_b   = (const float*)d_in[24];
    const float* mr_w   = (const float*)d_in[25];
    const float* mr_b   = (const float*)d_in[26];
    const float* out_w  = (const float*)d_in[27];
    const float* out_b  = (const float*)d_in[28];

    float* out_main = (float*)d_out;
    float* out_mem  = out_main + (size_t)Bb * Ss * Dd;

    float *p_xn, *p_h, *p_hpack, *p_qkv, *p_mem2, *p_sim, *p_retr, *p_memout, *p_qmean, *p_gctx;
    float *p_w1T, *p_qkvT, *p_w2T, *p_mrwT, *p_outT, *p_b1, *p_b2;
    cudaGetSymbolAddress((void**)&p_xn, g_xn);
    cudaGetSymbolAddress((void**)&p_h, g_h);
    cudaGetSymbolAddress((void**)&p_hpack, g_hpack);
    cudaGetSymbolAddress((void**)&p_qkv, g_qkv);
    cudaGetSymbolAddress((void**)&p_mem2, g_mem2);
    cudaGetSymbolAddress((void**)&p_sim, g_sim);
    cudaGetSymbolAddress((void**)&p_retr, g_retr);
    cudaGetSymbolAddress((void**)&p_memout, g_memout);
    cudaGetSymbolAddress((void**)&p_qmean, g_qmean);
    cudaGetSymbolAddress((void**)&p_gctx, g_gctx);
    cudaGetSymbolAddress((void**)&p_w1T, g_w1T);
    cudaGetSymbolAddress((void**)&p_qkvT, g_qkvT);
    cudaGetSymbolAddress((void**)&p_w2T, g_w2T);
    cudaGetSymbolAddress((void**)&p_mrwT, g_mrwT);
    cudaGetSymbolAddress((void**)&p_outT, g_outT);
    cudaGetSymbolAddress((void**)&p_b1, g_b1pack);
    cudaGetSymbolAddress((void**)&p_b2, g_b2pack);

    const int ROWS = Bb * Ss;   // 16384
    dim3 tpb(32, 8);
    cudaStream_t s0 = 0;        // capture-origin (default) stream

    // fork stream + events (host objects; created per call, not destroyed —
    // safe for capture, called only a handful of times)
    cudaStream_t s1;
    cudaEvent_t evLN, evQKV;
    cudaStreamCreateWithFlags(&s1, cudaStreamNonBlocking);
    cudaEventCreateWithFlags(&evLN, cudaEventDisableTiming);
    cudaEventCreateWithFlags(&evQKV, cudaEventDisableTiming);

    // ---- stream 0: LN (both branches depend on xn) ----
    ln_imp_kernel<<<ROWS, 256, 0, s0>>>(x, ln_g, ln_b, wg_w, wg_b);
    cudaEventRecord(evLN, s0);

    // ---- stream 1 (QKV branch): fork after LN ----
    cudaStreamWaitEvent(s1, evLN, 0);
    tp32<<<dim3(32, 32), tpb, 0, s1>>>(q_w, p_qkvT + 0 * Dd * Dd, Dd, Dd);
    tp32<<<dim3(32, 32), tpb, 0, s1>>>(k_w, p_qkvT + 1 * Dd * Dd, Dd, Dd);
    tp32<<<dim3(32, 32), tpb, 0, s1>>>(v_w, p_qkvT + 2 * Dd * Dd, Dd, Dd);
    wt_kernel<<<(3 * NGRP * 128 * 128 + 255) / 256, 256, 0, s1>>>(conv_w);
    tp32<<<dim3(32, 32), tpb, 0, s1>>>(out_w, p_outT, Dd, Dd);
    launch_tc<1, 0, 0, 0>(dim3(24, 128), s1, p_xn, Dd, 0, p_qkvT, Dd, 0, nullptr, 0, nullptr,
                          p_qkv, 3072, 0, Dd, 1.f);
    qmean_kernel<<<dim3(Dd / 256, Bb), 256, 0, s1>>>();
    gemm_small<<<dim3(Dd / BN, 1), 256, 0, s1>>>(p_qmean, Dd, gp_w, Dd, gp_b, p_gctx, Dd, Bb, Dd);
    cudaEventRecord(evQKV, s1);

    // ---- stream 0 (memory-attention branch) ----
    tp32<<<dim3(32, 32), tpb, 0, s0>>>(mk_w1, p_w1T + 0 * Dd * Dd, Dd, Dd);
    tp32<<<dim3(32, 32), tpb, 0, s0>>>(mv_w1, p_w1T + 1 * Dd * Dd, Dd, Dd);
    tp32<<<dim3(32, 32), tpb, 0, s0>>>(mq_w1, p_w1T + 2 * Dd * Dd, Dd, Dd);
    tp32<<<dim3(4, 32), tpb, 0, s0>>>(mk_w2, p_w2T + 0 * 128 * Dd, Dd, 128);
    tp32<<<dim3(4, 32), tpb, 0, s0>>>(mv_w2, p_w2T + 1 * 128 * Dd, Dd, 128);
    tp32<<<dim3(4, 32), tpb, 0, s0>>>(mq_w2, p_w2T + 2 * 128 * Dd, Dd, 128);
    tp32<<<dim3(32, 4), tpb, 0, s0>>>(mr_w, p_mrwT, 128, Dd);
    bias_pack<<<(3456 + 255) / 256, 256, 0, s0>>>(mk_b1, mv_b1, mq_b1, mk_b2, mv_b2, mq_b2);
    topk_kernel<<<Bb, 1024, 0, s0>>>();
    zero_retr<<<(Bb * Ss * Vv + 255) / 256, 256, 0, s0>>>();

    // fused MLP1 (3 chains)
    launch_tc<1, 1, 0, 0>(dim3(24, 128), s0, p_xn, Dd, 0, p_w1T, Dd, 0, p_b1, 0, nullptr,
                          p_hpack, 3072, 0, Dd, 1.f);
    // fused MLP2 (grid.z selects chain)
    launch_tc<1, 0, 0, 0>(dim3(1, 128, 3), s0, p_hpack, 3072, 1024, p_w2T, Dd, (long)128 * Dd,
                          p_b2, 128, nullptr, p_mem2, 384, 128, Dd, 1.f);
    // splice memory into d_out
    assemble_kernel<<<(Bb * Mm * 256 + 255) / 256, 256, 0, s0>>>(memdict, out_mem);
    // sim = memq @ K^T / sqrt(K)
    launch_tc<1, 0, 0, 0>(dim3(16, 32, Bb), s0, p_mem2 + 256, 384, (long)Ss * 384,
                          out_mem, 256, (long)Mm * 256, nullptr, 0, nullptr,
                          p_sim, Mm, (long)Ss * Mm, Kk, 0.08838834764831845f);
    softmax_kernel<<<ROWS, 256, 0, s0>>>(p_sim);
    // retrieved = attn @ V  (split-K x8, atomic)
    launch_tc<0, 0, 0, 1>(dim3(8, 32, Bb), s0, p_sim, Mm, (long)Ss * Mm,
                          out_mem + Kk, 256, (long)Mm * 256, nullptr, 0, nullptr,
                          p_retr, Vv, (long)Ss * Vv, Mm / 8, 1.f);
    // memory_output = retrieved @ mr_w + mr_b
    launch_tc<1, 0, 0, 0>(dim3(8, 128), s0, p_retr, Vv, 0, p_mrwT, Vv, 0, mr_b, 0, nullptr,
                          p_memout, Dd, 0, Vv, 1.f);

    // ---- join: conv needs QKV branch (qkv, gctx, wt) + memout ----
    cudaStreamWaitEvent(s0, evQKV, 0);
    conv_tc<<<dim3(Ss / 128, NGRP, Bb), 256, 0, s0>>>(conv_b);

    // output = combined @ out_w + out_b + residual(x)
    launch_tc<1, 0, 1, 0>(dim3(8, 128), s0, p_h, Dd, 0, p_outT, Dd, 0, out_b, 0, x,
                          out_main, Dd, 0, Dd, 1.f);
}

// round 15
// speedup vs baseline: 4.7834x; 1.0270x over previous
#include <cuda_runtime.h>
#include <math.h>
#include <stdint.h>

#define Bb 4
#define Ss 4096
#define Dd 1024
#define Mm 2048
#define Kk 128
#define Vv 128
#define NGRP 8
#define NWRITES 1024
#define KEEP 1024

// ---------------- scratch ----------------
__device__ __align__(16) float g_xn[Bb * Ss * Dd];
__device__ __align__(16) float g_h[Bb * Ss * Dd];
__device__ __align__(16) float g_hpack[(size_t)Bb * Ss * 3072];
__device__ __align__(16) float g_qkv[(size_t)Bb * Ss * 3072];
__device__ __align__(16) float g_mem2[Bb * Ss * 384];
__device__ __align__(16) float g_sig[Bb * Ss];
__device__ __align__(16) int   g_topidx[Bb * NWRITES];
__device__ __align__(16) float g_retr[Bb * Ss * Vv];
__device__ __align__(16) float g_memout[Bb * Ss * Dd];
__device__ __align__(16) float g_qmean[Bb * Dd];
__device__ __align__(16) float g_gctx[Bb * Dd];
__device__ __align__(16) float g_wt[3 * NGRP * 128 * 128];
__device__ __align__(16) float g_w1T[3 * Dd * Dd];
__device__ __align__(16) float g_qkvT[3 * Dd * Dd];
__device__ __align__(16) float g_w2T[3 * 128 * Dd];
__device__ __align__(16) float g_mrwT[Dd * Vv];
__device__ __align__(16) float g_outT[Dd * Dd];
__device__ __align__(16) float g_b1pack[3072];
__device__ __align__(16) float g_b2pack[384];

// ---------------- helpers ----------------
__device__ __forceinline__ void mma8(float* c, const uint32_t* a, const uint32_t* b) {
    asm volatile(
        "mma.sync.aligned.m16n8k8.row.col.f32.tf32.tf32.f32 "
        "{%0,%1,%2,%3}, {%4,%5,%6,%7}, {%8,%9}, {%0,%1,%2,%3};\n"
        : "+f"(c[0]), "+f"(c[1]), "+f"(c[2]), "+f"(c[3])
        : "r"(a[0]), "r"(a[1]), "r"(a[2]), "r"(a[3]), "r"(b[0]), "r"(b[1]));
}
__device__ __forceinline__ void cpa16(uint32_t dst, const float* src) {
    asm volatile("cp.async.cg.shared.global [%0], [%1], 16;\n" :: "r"(dst), "l"(src));
}
#define CP_COMMIT asm volatile("cp.async.commit_group;\n" ::: "memory")
#define CP_WAIT1  asm volatile("cp.async.wait_group 1;\n" ::: "memory")
__device__ __forceinline__ void ldsm4(uint32_t* r, uint32_t addr) {
    asm volatile("ldmatrix.sync.aligned.m8n8.x4.shared.b16 {%0,%1,%2,%3}, [%4];\n"
                 : "=r"(r[0]), "=r"(r[1]), "=r"(r[2]), "=r"(r[3]) : "r"(addr));
}
__device__ __forceinline__ void ldsm2(uint32_t* r, uint32_t addr) {
    asm volatile("ldmatrix.sync.aligned.m8n8.x2.shared.b16 {%0,%1}, [%2];\n"
                 : "=r"(r[0]), "=r"(r[1]) : "r"(addr));
}

// ================= fused flash attention (sim+softmax+retr) =================
// Per block: 128 query rows; stream 64-key KV tiles; warp owns 16 rows.
#define FA_QSTR 132
#define FA_PSTR 68
#define FA_VSTR 136
#define FA_QSZ (128 * 132)     // 16896 floats
#define FA_KP 8704             // K-tile [64][132] or P [128][68] (both <= 8704 floats)
#define FA_STAGE 17408         // KP + V (8704 each)
#define FA_SMEM ((FA_QSZ + 2 * FA_STAGE) * 4)   // 206848 B

__global__ void __launch_bounds__(256, 1) flash_attn(
    const float* __restrict__ memq,   // g_mem2 + 256 (row stride 384)
    const float* __restrict__ kv,     // out_mem (row stride 256; K 0-127, V 128-255)
    float* __restrict__ outr)         // g_retr (row stride 128)
{
    extern __shared__ __align__(16) float sh[];
    int tid = threadIdx.x, warp = tid >> 5, lane = tid & 31;
    int b = blockIdx.y, qm0 = blockIdx.x * 128;
    int g = lane >> 2, tg = lane & 3;
    int lr = lane & 7, ls = lane >> 3;
    int wr = warp * 16;

    uint32_t shb = (uint32_t)__cvta_generic_to_shared(sh);

    // stage Q once (folded into first commit group)
    const float* qsrc = memq + (size_t)(b * Ss + qm0) * 384;
#pragma unroll
    for (int p = 0; p < 16; p++) {
        int u = tid + p * 256;
        int r = u >> 5, c = u & 31;
        cpa16(shb + (uint32_t)(r * FA_QSTR + c * 4) * 4, qsrc + (size_t)r * 384 + c * 4);
    }

#define FA_STAGE_T(tt)                                                            \
    {                                                                             \
        int t_ = (tt);                                                            \
        uint32_t kpb_ = shb + (uint32_t)(FA_QSZ + (t_ & 1) * FA_STAGE) * 4;       \
        uint32_t vb_ = kpb_ + FA_KP * 4;                                          \
        const float* src_ = kv + ((size_t)(b * Mm) + t_ * 64) * 256;              \
        _Pragma("unroll")                                                         \
        for (int p_ = 0; p_ < 8; p_++) {                                          \
            int u_ = tid + p_ * 256;                                              \
            int n_ = u_ >> 5, c_ = u_ & 31;                                       \
            cpa16(kpb_ + (uint32_t)(n_ * FA_QSTR + c_ * 4) * 4,                   \
                  src_ + (size_t)n_ * 256 + c_ * 4);                              \
        }                                                                         \
        _Pragma("unroll")                                                         \
        for (int p_ = 0; p_ < 8; p_++) {                                          \
            int u_ = tid + p_ * 256;                                              \
            int n_ = u_ >> 5, c_ = u_ & 31;                                       \
            cpa16(vb_ + (uint32_t)(n_ * FA_VSTR + c_ * 4) * 4,                    \
                  src_ + (size_t)n_ * 256 + 128 + c_ * 4);                        \
        }                                                                         \
        CP_COMMIT;                                                                \
    }

    FA_STAGE_T(0);
    FA_STAGE_T(1);

    float o[16][4];
#pragma unroll
    for (int i = 0; i < 16; i++)
#pragma unroll
        for (int e = 0; e < 4; e++) o[i][e] = 0.f;
    float m0r = -3.4e38f, m1r = -3.4e38f, l0 = 0.f, l1 = 0.f;
    const float alpha = 0.08838834764831845f;

    uint32_t qaddr = shb + (uint32_t)((wr + lr + ((ls & 1) << 3)) * FA_QSTR
                                      + ((ls >> 1) << 2)) * 4;

    const int nt = Mm / 64;   // 32
    for (int t = 0; t < nt; t++) {
        CP_WAIT1;
        __syncthreads();
        uint32_t kpb = shb + (uint32_t)(FA_QSZ + (t & 1) * FA_STAGE) * 4;

        // ---- S = alpha * Q @ K^T  (warp rows wr..wr+15, 64 keys) ----
        float s[8][4];
#pragma unroll
        for (int ni = 0; ni < 8; ni++)
#pragma unroll
            for (int e = 0; e < 4; e++) s[ni][e] = 0.f;
        uint32_t kaddr = kpb + (uint32_t)(lr * FA_QSTR + ((ls & 1) << 2)) * 4;
#pragma unroll
        for (int ks = 0; ks < 16; ks++) {
            uint32_t af[4];
            ldsm4(af, qaddr + (uint32_t)(ks * 8) * 4);
#pragma unroll
            for (int ni = 0; ni < 8; ni++) {
                uint32_t bf[2];
                ldsm2(bf, kaddr + (uint32_t)(ni * 8 * FA_QSTR + ks * 8) * 4);
                mma8(s[ni], af, bf);
            }
        }
        __syncthreads();   // all warps done reading K before P overwrites it

        // ---- online softmax (rows wr+g, wr+g+8; warp-private) ----
        float rmax0 = -3.4e38f, rmax1 = -3.4e38f;
#pragma unroll
        for (int ni = 0; ni < 8; ni++) {
#pragma unroll
            for (int e = 0; e < 4; e++) s[ni][e] *= alpha;
            rmax0 = fmaxf(rmax0, fmaxf(s[ni][0], s[ni][1]));
            rmax1 = fmaxf(rmax1, fmaxf(s[ni][2], s[ni][3]));
        }
        rmax0 = fmaxf(rmax0, __shfl_xor_sync(0xFFFFFFFFu, rmax0, 1));
        rmax0 = fmaxf(rmax0, __shfl_xor_sync(0xFFFFFFFFu, rmax0, 2));
        rmax1 = fmaxf(rmax1, __shfl_xor_sync(0xFFFFFFFFu, rmax1, 1));
        rmax1 = fmaxf(rmax1, __shfl_xor_sync(0xFFFFFFFFu, rmax1, 2));
        float mn0 = fmaxf(m0r, rmax0), mn1 = fmaxf(m1r, rmax1);
        float sc0 = expf(m0r - mn0), sc1 = expf(m1r - mn1);
        m0r = mn0; m1r = mn1;

        float* P = sh + FA_QSZ + (t & 1) * FA_STAGE;   // reuse K region
        float ps0 = 0.f, ps1 = 0.f;
#pragma unroll
        for (int ni = 0; ni < 8; ni++) {
            float p0 = expf(s[ni][0] - mn0), p1 = expf(s[ni][1] - mn0);
            float p2 = expf(s[ni][2] - mn1), p3 = expf(s[ni][3] - mn1);
            ps0 += p0 + p1; ps1 += p2 + p3;
            int col = ni * 8 + 2 * tg;
            *(float2*)&P[(wr + g) * FA_PSTR + col] = make_float2(p0, p1);
            *(float2*)&P[(wr + g + 8) * FA_PSTR + col] = make_float2(p2, p3);
        }
        ps0 += __shfl_xor_sync(0xFFFFFFFFu, ps0, 1);
        ps0 += __shfl_xor_sync(0xFFFFFFFFu, ps0, 2);
        ps1 += __shfl_xor_sync(0xFFFFFFFFu, ps1, 1);
        ps1 += __shfl_xor_sync(0xFFFFFFFFu, ps1, 2);
        l0 = l0 * sc0 + ps0;
        l1 = l1 * sc1 + ps1;
#pragma unroll
        for (int ni = 0; ni < 16; ni++) {
            o[ni][0] *= sc0; o[ni][1] *= sc0;
            o[ni][2] *= sc1; o[ni][3] *= sc1;
        }
        __syncthreads();   // P visible to all warps

        // ---- O += P @ V ----
        uint32_t pa = kpb + (uint32_t)((wr + lr + ((ls & 1) << 3)) * FA_PSTR
                                       + ((ls >> 1) << 2)) * 4;
        const float* Vst = sh + FA_QSZ + (t & 1) * FA_STAGE + FA_KP;
#pragma unroll
        for (int ks = 0; ks < 8; ks++) {
            uint32_t af[4];
            ldsm4(af, pa + (uint32_t)(ks * 8) * 4);
            int kk = ks * 8;
#pragma unroll
            for (int ni = 0; ni < 16; ni++) {
                uint32_t bf[2];
                const float* bp = Vst + (kk + tg) * FA_VSTR + ni * 8 + g;
                bf[0] = __float_as_uint(bp[0]);
                bf[1] = __float_as_uint(bp[4 * FA_VSTR]);
                mma8(o[ni], af, bf);
            }
        }
        __syncthreads();   // P/V reads complete before restaging this buffer
        if (t + 2 < nt) FA_STAGE_T(t + 2) else CP_COMMIT;
    }

    // ---- normalize + store ----
    float i0 = 1.f / l0, i1 = 1.f / l1;
    float* or0 = outr + (size_t)(b * Ss + qm0 + wr + g) * 128;
    float* or1 = or0 + 8 * 128;
#pragma unroll
    for (int ni = 0; ni < 16; ni++) {
        int col = ni * 8 + 2 * tg;
        *(float2*)&or0[col] = make_float2(o[ni][0] * i0, o[ni][1] * i0);
        *(float2*)&or1[col] = make_float2(o[ni][2] * i1, o[ni][3] * i1);
    }
}

// ================= mma.sync GEMM (unchanged from R12) =================
#define GTM 128
#define GTN 128
#define GTK 32
#define ASTR 36
#define BSTR 136
#define ASTAGE (128 * ASTR)
#define BSTAGE 4608
#define NSTAGE 3
#define GEMM_SMEM ((NSTAGE * ASTAGE + NSTAGE * BSTAGE) * 4)

template <int BNK>
__device__ __forceinline__ void stage_tile(
    const float* __restrict__ A, int lda, int m0,
    const float* __restrict__ Bm, int ldb, int n0,
    uint32_t asb, uint32_t bsb, int tid, int k0, int st)
{
    uint32_t ad = asb + st * (ASTAGE * 4);
    int c = tid;
#pragma unroll
    for (int p = 0; p < 4; p++, c += 256) {
        int m = c >> 3, ko = (c & 7) * 4;
        cpa16(ad + (uint32_t)(m * ASTR + ko) * 4, A + (long)(m0 + m) * lda + k0 + ko);
    }
    uint32_t bd = bsb + st * (BSTAGE * 4);
    if (BNK) {
        int c2 = tid;
#pragma unroll
        for (int p = 0; p < 4; p++, c2 += 256) {
            int n = c2 >> 3, ko = (c2 & 7) * 4;
            cpa16(bd + (uint32_t)(n * ASTR + ko) * 4, Bm + (long)(n0 + n) * ldb + k0 + ko);
        }
    } else {
        int c2 = tid;
#pragma unroll
        for (int p = 0; p < 4; p++, c2 += 256) {
            int k = c2 >> 5, no = (c2 & 31) * 4;
            cpa16(bd + (uint32_t)(k * BSTR + no) * 4, Bm + (long)(k0 + k) * ldb + n0 + no);
        }
    }
    CP_COMMIT;
}

template <int BNK, int ACT, int RESID, int SPLITK>
__global__ void __launch_bounds__(256, 2) gemm_tc(
    const float* __restrict__ A, int lda, long sA,
    const float* __restrict__ Bm, int ldb, long sB,
    const float* __restrict__ bias, long sBias,
    const float* __restrict__ resid,
    float* __restrict__ C, int ldc, long sC,
    int Kd, float alpha)
{
    extern __shared__ __align__(16) float sh[];
    __shared__ __align__(16) float sbias[GTN];
    long bz = blockIdx.z;
    A += bz * sA; Bm += bz * sB; C += bz * sC;
    if (RESID) resid += bz * sC;
    int n0 = SPLITK ? 0 : blockIdx.x * GTN;
    int m0 = blockIdx.y * GTM;
    int kbase = SPLITK ? blockIdx.x * Kd : 0;
    int tid = threadIdx.x;
    int warp = tid >> 5, lane = tid & 31;
    int g = lane >> 2, tg = lane & 3;
    int wm = (warp & 1) * 64, wn = (warp >> 1) * 32;

    if (!SPLITK && tid < GTN) sbias[tid] = bias ? bias[bz * sBias + n0 + tid] : 0.f;

    uint32_t asb = (uint32_t)__cvta_generic_to_shared(sh);
    uint32_t bsb = asb + NSTAGE * ASTAGE * 4;

    int lr = lane & 7, ls = lane >> 3;
    int a_row = wm + lr + ((ls & 1) << 3);
    int a_col = (ls >> 1) << 2;
    int b_row = wn + lr;
    int b_col = (ls & 1) << 2;

    float c[4][4][4];
#pragma unroll
    for (int a = 0; a < 4; a++)
#pragma unroll
        for (int b = 0; b < 4; b++)
#pragma unroll
            for (int e = 0; e < 4; e++) c[a][b][e] = 0.f;

    int nt = Kd >> 5;
    stage_tile<BNK>(A, lda, m0, Bm, ldb, n0, asb, bsb, tid, kbase, 0);
    if (nt > 1)
        stage_tile<BNK>(A, lda, m0, Bm, ldb, n0, asb, bsb, tid, kbase + GTK, 1);
    else
        CP_COMMIT;

    for (int t = 0; t < nt; t++) {
        CP_WAIT1;
        __syncthreads();
        if (t + 2 < nt)
            stage_tile<BNK>(A, lda, m0, Bm, ldb, n0, asb, bsb, tid,
                            kbase + (t + 2) * GTK, (t + 2) % NSTAGE);
        else
            CP_COMMIT;
        int st = t % NSTAGE;
        uint32_t abuf = asb + st * (ASTAGE * 4);
        uint32_t bbuf = bsb + st * (BSTAGE * 4);
        uint32_t aaddr = abuf + (uint32_t)(a_row * ASTR + a_col) * 4;
        uint32_t baddr = bbuf + (uint32_t)(b_row * ASTR + b_col) * 4;
        const float* BstKN = sh + NSTAGE * ASTAGE + st * BSTAGE;
#pragma unroll
        for (int ks = 0; ks < 4; ks++) {
            const int kk = ks * 8;
            uint32_t af[4][4], bf[4][2];
#pragma unroll
            for (int mi = 0; mi < 4; mi++)
                ldsm4(af[mi], aaddr + (uint32_t)(mi * 16 * ASTR + kk) * 4);
#pragma unroll
            for (int ni = 0; ni < 4; ni++) {
                if (BNK) {
                    ldsm2(bf[ni], baddr + (uint32_t)(ni * 8 * ASTR + kk) * 4);
                } else {
                    const float* bp = BstKN + (kk + tg) * BSTR + wn + ni * 8 + g;
                    bf[ni][0] = __float_as_uint(bp[0]);
                    bf[ni][1] = __float_as_uint(bp[4 * BSTR]);
                }
            }
#pragma unroll
            for (int mi = 0; mi < 4; mi++)
#pragma unroll
                for (int ni = 0; ni < 4; ni++) mma8(c[mi][ni], af[mi], bf[ni]);
        }
    }

#pragma unroll
    for (int mi = 0; mi < 4; mi++) {
#pragma unroll
        for (int ni = 0; ni < 4; ni++) {
            int row = m0 + wm + mi * 16 + g;
            int cb = wn + ni * 8 + 2 * tg;
            int col = n0 + cb;
            float v[4];
#pragma unroll
            for (int e = 0; e < 4; e++) v[e] = c[mi][ni][e] * alpha;
            if (SPLITK) {
                atomicAdd(&C[(long)row * ldc + col],     v[0]);
                atomicAdd(&C[(long)row * ldc + col + 1], v[1]);
                atomicAdd(&C[(long)(row + 8) * ldc + col],     v[2]);
                atomicAdd(&C[(long)(row + 8) * ldc + col + 1], v[3]);
            } else {
                v[0] += sbias[cb];     v[1] += sbias[cb + 1];
                v[2] += sbias[cb];     v[3] += sbias[cb + 1];
                if (ACT == 1) {
#pragma unroll
                    for (int e = 0; e < 4; e++)
                        v[e] = 0.5f * v[e] * (1.f + erff(v[e] * 0.7071067811865475f));
                }
                if (RESID) {
                    v[0] += resid[(long)row * ldc + col];
                    v[1] += resid[(long)row * ldc + col + 1];
                    v[2] += resid[(long)(row + 8) * ldc + col];
                    v[3] += resid[(long)(row + 8) * ldc + col + 1];
                }
                *(float2*)&C[(long)row * ldc + col] = make_float2(v[0], v[1]);
                *(float2*)&C[(long)(row + 8) * ldc + col] = make_float2(v[2], v[3]);
            }
        }
    }
}

// ---------------- tiled transpose ----------------
__global__ void tp32(const float* __restrict__ src, float* __restrict__ dst,
                     int K, int N) {
    __shared__ __align__(16) float t[32][33];
    int n0 = blockIdx.x * 32, k0 = blockIdx.y * 32;
    int tx = threadIdx.x, ty = threadIdx.y;
#pragma unroll
    for (int i = ty; i < 32; i += 8)
        t[i][tx] = src[(long)(k0 + i) * N + n0 + tx];
    __syncthreads();
#pragma unroll
    for (int i = ty; i < 32; i += 8)
        dst[(long)(n0 + i) * K + k0 + tx] = t[tx][i];
}

// ---------------- bias packing ----------------
__global__ void bias_pack(const float* __restrict__ b1k, const float* __restrict__ b1v,
                          const float* __restrict__ b1q, const float* __restrict__ b2k,
                          const float* __restrict__ b2v, const float* __restrict__ b2q) {
    int i = blockIdx.x * 256 + threadIdx.x;
    if (i < 3072) {
        int ch = i >> 10, col = i & 1023;
        g_b1pack[i] = (ch == 0 ? b1k : ch == 1 ? b1v : b1q)[col];
    } else if (i < 3072 + 384) {
        int j = i - 3072;
        int ch = j >> 7, col = j & 127;
        g_b2pack[j] = (ch == 0 ? b2k : ch == 1 ? b2v : b2q)[col];
    }
}

// ---------------- conv ----------------
#define TBK 32
#define TSTR 136
__device__ __forceinline__ int swz(int k, int m) { return m ^ (((k >> 2) & 7) << 2); }
__device__ __forceinline__ uint32_t f2tf32(float f) {
    uint32_t u;
    asm("cvt.rna.tf32.f32 %0, %1;" : "=r"(u) : "f"(f));
    return u;
}

__global__ void wt_kernel(const float* __restrict__ cw) {
    int idx = blockIdx.x * 256 + threadIdx.x;
    if (idx >= 3 * NGRP * 128 * 128) return;
    int o = idx & 127;
    int k = (idx >> 7) & 127;
    int hg = idx >> 14;
    int h = hg >> 3, grp = hg & 7;
    g_wt[idx] = cw[(((size_t)(grp * 128 + o)) * 128 + k) * 3 + h];
}

__global__ void __launch_bounds__(256, 2) conv_tc(const float* __restrict__ cb) {
    __shared__ __align__(16) uint32_t As[TBK * TSTR];
    __shared__ __align__(16) uint32_t Bs[TBK * TSTR];
    __shared__ __align__(16) float cbs[128];
    int b = blockIdx.z, grp = blockIdx.y, s0 = blockIdx.x * 128;
    int tid = threadIdx.x;
    int warp = tid >> 5, lane = tid & 31;
    int g = lane >> 2, tg = lane & 3;
    int wm = (warp & 1) * 64, wn = (warp >> 1) * 32;

    if (tid < 128) cbs[tid] = cb[grp * 128 + tid];

    float c[4][4][4];
#pragma unroll
    for (int a = 0; a < 4; a++)
#pragma unroll
        for (int d = 0; d < 4; d++)
#pragma unroll
            for (int e = 0; e < 4; e++) c[a][d][e] = 0.f;

    int arow = tid >> 3, acol = (tid & 7) * 4;

    for (int h = 0; h < 3; h++) {
        for (int k0 = 0; k0 < 128; k0 += TBK) {
#pragma unroll
            for (int p = 0; p < 4; p++) {
                int m = arow + p * 32;
                int s = s0 + m + h - 1;
                float4 v = make_float4(0.f, 0.f, 0.f, 0.f);
                if (s >= 0 && s < Ss)
                    v = *(const float4*)&g_qkv[((size_t)(b * Ss) + s) * 3072 + 2048 + grp * 128 + k0 + acol];
                As[(acol + 0) * TSTR + swz(acol + 0, m)] = f2tf32(v.x);
                As[(acol + 1) * TSTR + swz(acol + 1, m)] = f2tf32(v.y);
                As[(acol + 2) * TSTR + swz(acol + 2, m)] = f2tf32(v.z);
                As[(acol + 3) * TSTR + swz(acol + 3, m)] = f2tf32(v.w);
            }
            {
                int n = tid & 127, kb = tid >> 7;
#pragma unroll
                for (int p = 0; p < 16; p++) {
                    int k = kb + p * 2;
                    Bs[k * TSTR + swz(k, n)] =
                        f2tf32(g_wt[(((size_t)(h * NGRP + grp)) * 128 + k0 + k) * 128 + n]);
                }
            }
            __syncthreads();
#pragma unroll
            for (int ks = 0; ks < 4; ks++) {
                int kk = ks * 8;
                uint32_t af[4][4], bf[4][2];
#pragma unroll
                for (int mi = 0; mi < 4; mi++) {
                    int m = wm + mi * 16;
                    af[mi][0] = As[(kk + tg) * TSTR + swz(kk + tg, m + g)];
                    af[mi][1] = As[(kk + tg) * TSTR + swz(kk + tg, m + g + 8)];
                    af[mi][2] = As[(kk + tg + 4) * TSTR + swz(kk + tg + 4, m + g)];
                    af[mi][3] = As[(kk + tg + 4) * TSTR + swz(kk + tg + 4, m + g + 8)];
                }
#pragma unroll
                for (int ni = 0; ni < 4; ni++) {
                    int n = wn + ni * 8;
                    bf[ni][0] = Bs[(kk + tg) * TSTR + swz(kk + tg, n + g)];
                    bf[ni][1] = Bs[(kk + tg + 4) * TSTR + swz(kk + tg + 4, n + g)];
                }
#pragma unroll
                for (int mi = 0; mi < 4; mi++)
#pragma unroll
                    for (int ni = 0; ni < 4; ni++) mma8(c[mi][ni], af[mi], bf[ni]);
            }
            __syncthreads();
        }
    }

#pragma unroll
    for (int mi = 0; mi < 4; mi++) {
#pragma unroll
        for (int ni = 0; ni < 4; ni++) {
            int cbcol = wn + ni * 8 + 2 * tg;
            int o = grp * 128 + cbcol;
#pragma unroll
            for (int half = 0; half < 2; half++) {
                int s = s0 + wm + mi * 16 + g + half * 8;
                size_t idx = ((size_t)(b * Ss) + s) * Dd + o;
                size_t kidx = ((size_t)(b * Ss) + s) * 3072 + 1024 + o;
                float2 mo = *(const float2*)&g_memout[idx];
                float2 kv = *(const float2*)&g_qkv[kidx];
                float gc0 = g_gctx[b * Dd + o], gc1 = g_gctx[b * Dd + o + 1];
                float l0 = c[mi][ni][half * 2 + 0] + cbs[cbcol];
                float l1 = c[mi][ni][half * 2 + 1] + cbs[cbcol + 1];
                float p0 = 1.f / (1.f + expf(-kv.x));
                float p1 = 1.f / (1.f + expf(-kv.y));
                float r0 = (l0 + 0.1f * gc0 + 0.5f * mo.x) * p0;
                float r1 = (l1 + 0.1f * gc1 + 0.5f * mo.y) * p1;
                *(float2*)&g_h[idx] = make_float2(r0, r1);
            }
        }
    }
}

// ---------------- LayerNorm + write-gate ----------------
__global__ void ln_imp_kernel(const float* __restrict__ x,
                              const float* __restrict__ lng,
                              const float* __restrict__ lnb,
                              const float* __restrict__ wgw,
                              const float* __restrict__ wgb) {
    int row = blockIdx.x;
    int tid = threadIdx.x;
    const float* xr = x + (size_t)row * Dd + tid * 4;
    float x0 = xr[0], x1 = xr[1], x2 = xr[2], x3 = xr[3];
    __shared__ float red[256];

    red[tid] = x0 + x1 + x2 + x3; __syncthreads();
    for (int o = 128; o > 0; o >>= 1) { if (tid < o) red[tid] += red[tid + o]; __syncthreads(); }
    float mu = red[0] * (1.f / Dd);
    __syncthreads();

    float d0 = x0 - mu, d1 = x1 - mu, d2 = x2 - mu, d3 = x3 - mu;
    red[tid] = d0 * d0 + d1 * d1 + d2 * d2 + d3 * d3; __syncthreads();
    for (int o = 128; o > 0; o >>= 1) { if (tid < o) red[tid] += red[tid + o]; __syncthreads(); }
    float var = red[0] * (1.f / Dd);
    float rs = rsqrtf(var + 1e-5f);
    __syncthreads();

    float y0 = d0 * rs * lng[tid * 4 + 0] + lnb[tid * 4 + 0];
    float y1 = d1 * rs * lng[tid * 4 + 1] + lnb[tid * 4 + 1];
    float y2 = d2 * rs * lng[tid * 4 + 2] + lnb[tid * 4 + 2];
    float y3 = d3 * rs * lng[tid * 4 + 3] + lnb[tid * 4 + 3];
    ((float4*)(g_xn + (size_t)row * Dd))[tid] = make_float4(y0, y1, y2, y3);

    red[tid] = y0 * wgw[tid * 4 + 0] + y1 * wgw[tid * 4 + 1]
             + y2 * wgw[tid * 4 + 2] + y3 * wgw[tid * 4 + 3];
    __syncthreads();
    for (int o = 128; o > 0; o >>= 1) { if (tid < o) red[tid] += red[tid + o]; __syncthreads(); }
    if (tid == 0) {
        double l = (double)(red[0] + wgb[0]);
        g_sig[row] = (float)(1.0 / (1.0 + exp(-l)));
    }
}

// ---------------- top-k ----------------
__global__ void topk_kernel() {
    __shared__ __align__(16) unsigned long long sk[Ss];
    int b = blockIdx.x, tid = threadIdx.x;
    for (int i = tid; i < Ss; i += 1024) {
        unsigned u = __float_as_uint(g_sig[b * Ss + i]);
        u = (u & 0x80000000u) ? ~u : (u | 0x80000000u);
        sk[i] = ((unsigned long long)u << 32) | (unsigned)(0xFFFFFFFFu - i);
    }
    __syncthreads();
    for (int k = 2; k <= Ss; k <<= 1) {
        for (int j = k >> 1; j > 0; j >>= 1) {
            for (int i = tid; i < Ss; i += 1024) {
                int ixj = i ^ j;
                if (ixj > i) {
                    bool desc = ((i & k) == 0);
                    unsigned long long a = sk[i], c = sk[ixj];
                    if ((a < c) == desc) { sk[i] = c; sk[ixj] = a; }
                }
            }
            __syncthreads();
        }
    }
    for (int i = tid; i < NWRITES; i += 1024)
        g_topidx[b * NWRITES + i] = (int)(0xFFFFFFFFu - (unsigned)sk[i]);
}

// ---------------- splice memory -> d_out ----------------
__global__ void assemble_kernel(const float* __restrict__ md, float* __restrict__ om) {
    int idx = blockIdx.x * blockDim.x + threadIdx.x;
    if (idx >= Bb * Mm * 256) return;
    int c = idx & 255;
    int m = (idx >> 8) & (Mm - 1);
    int b = idx >> 19;
    float val;
    if (m < KEEP) val = md[idx];
    else {
        int id = g_topidx[b * NWRITES + (m - KEEP)];
        val = g_mem2[((size_t)(b * Ss) + id) * 384 + c];
    }
    om[idx] = val;
}

// ---------------- small SIMT GEMM (M=4 gctx only) ----------------
#define BM 64
#define BN 64
#define BKg 16
__global__ void gemm_small(const float* __restrict__ A, int lda,
                           const float* __restrict__ Bm, int ldb,
                           const float* __restrict__ bias,
                           float* __restrict__ C, int ldc, int Mr, int Kd) {
    __shared__ __align__(16) float As[BKg][BM + 4];
    __shared__ __align__(16) float Bs[BKg][BN + 4];
    __shared__ __align__(16) float sbias[BN];
    int n0 = blockIdx.x * BN, m0 = blockIdx.y * BM;
    int tid = threadIdx.x;
    int tx = tid & 15, ty = tid >> 4;
    if (tid < BN) sbias[tid] = bias ? bias[n0 + tid] : 0.f;
    float acc[4][4];
#pragma unroll
    for (int i = 0; i < 4; i++)
#pragma unroll
        for (int j = 0; j < 4; j++) acc[i][j] = 0.f;
    int aRow = tid >> 2, aCol = (tid & 3) * 4;
    for (int k0 = 0; k0 < Kd; k0 += BKg) {
        float4 av = make_float4(0.f, 0.f, 0.f, 0.f);
        if (m0 + aRow < Mr)
            av = *(const float4*)&A[(long)(m0 + aRow) * lda + k0 + aCol];
        As[aCol + 0][aRow] = av.x; As[aCol + 1][aRow] = av.y;
        As[aCol + 2][aRow] = av.z; As[aCol + 3][aRow] = av.w;
        int kr = tid >> 4, n = (tid & 15) * 4;
        const float* bp = &Bm[(long)(k0 + kr) * ldb + n0 + n];
        Bs[kr][n + 0] = bp[0]; Bs[kr][n + 1] = bp[1];
        Bs[kr][n + 2] = bp[2]; Bs[kr][n + 3] = bp[3];
        __syncthreads();
#pragma unroll
        for (int kk = 0; kk < BKg; kk++) {
            const float4 a = *(const float4*)&As[kk][ty * 4];
            const float4 b4 = *(const float4*)&Bs[kk][tx * 4];
            float ar[4] = {a.x, a.y, a.z, a.w};
            float br[4] = {b4.x, b4.y, b4.z, b4.w};
#pragma unroll
            for (int ii = 0; ii < 4; ii++)
#pragma unroll
                for (int jj = 0; jj < 4; jj++) acc[ii][jj] += ar[ii] * br[jj];
        }
        __syncthreads();
    }
#pragma unroll
    for (int i = 0; i < 4; i++) {
        int m = m0 + ty * 4 + i;
        if (m >= Mr) break;
#pragma unroll
        for (int j = 0; j < 4; j++) {
            int n = n0 + tx * 4 + j;
            C[(long)m * ldc + n] = acc[i][j] + sbias[tx * 4 + j];
        }
    }
}

// ---------------- mean over S of queries ----------------
__global__ void qmean_kernel() {
    int d = blockIdx.x * 256 + threadIdx.x;
    int b = blockIdx.y;
    const float* p = g_qkv + (size_t)b * Ss * 3072 + d;
    double s = 0.0;
    for (int t = 0; t < Ss; t++) s += p[(size_t)t * 3072];
    g_qmean[b * Dd + d] = (float)(s * (1.0 / Ss));
}

// ---------------- launch ----------------
template <int BNK, int ACT, int RESID, int SPLITK>
static void launch_tc(dim3 grid, cudaStream_t st, const float* A, int lda, long sA,
                      const float* B, int ldb, long sB,
                      const float* bias, long sBias, const float* resid,
                      float* C, int ldc, long sC, int Kd, float alpha) {
    cudaFuncSetAttribute(gemm_tc<BNK, ACT, RESID, SPLITK>,
                         cudaFuncAttributeMaxDynamicSharedMemorySize, GEMM_SMEM);
    gemm_tc<BNK, ACT, RESID, SPLITK><<<grid, 256, GEMM_SMEM, st>>>(
        A, lda, sA, B, ldb, sB, bias, sBias, resid, C, ldc, sC, Kd, alpha);
}

extern "C" void kernel_launch(void* const* d_in, const int* in_sizes, int n_in,
                              void* d_out, int out_size) {
    const float* x      = (const float*)d_in[0];
    const float* memdict= (const float*)d_in[1];
    const float* ln_g   = (const float*)d_in[2];
    const float* ln_b   = (const float*)d_in[3];
    const float* mk_w1  = (const float*)d_in[4];
    const float* mk_b1  = (const float*)d_in[5];
    const float* mk_w2  = (const float*)d_in[6];
    const float* mk_b2  = (const float*)d_in[7];
    const float* mv_w1  = (const float*)d_in[8];
    const float* mv_b1  = (const float*)d_in[9];
    const float* mv_w2  = (const float*)d_in[10];
    const float* mv_b2  = (const float*)d_in[11];
    const float* mq_w1  = (const float*)d_in[12];
    const float* mq_b1  = (const float*)d_in[13];
    const float* mq_w2  = (const float*)d_in[14];
    const float* mq_b2  = (const float*)d_in[15];
    const float* wg_w   = (const float*)d_in[16];
    const float* wg_b   = (const float*)d_in[17];
    const float* q_w    = (const float*)d_in[18];
    const float* k_w    = (const float*)d_in[19];
    const float* v_w    = (const float*)d_in[20];
    const float* conv_w = (const float*)d_in[21];
    const float* conv_b = (const float*)d_in[22];
    const float* gp_w   = (const float*)d_in[23];
    const float* gp_b   = (const float*)d_in[24];
    const float* mr_w   = (const float*)d_in[25];
    const float* mr_b   = (const float*)d_in[26];
    const float* out_w  = (const float*)d_in[27];
    const float* out_b  = (const float*)d_in[28];

    float* out_main = (float*)d_out;
    float* out_mem  = out_main + (size_t)Bb * Ss * Dd;

    float *p_xn, *p_h, *p_hpack, *p_qkv, *p_mem2, *p_retr, *p_memout, *p_qmean, *p_gctx;
    float *p_w1T, *p_qkvT, *p_w2T, *p_mrwT, *p_outT, *p_b1, *p_b2;
    cudaGetSymbolAddress((void**)&p_xn, g_xn);
    cudaGetSymbolAddress((void**)&p_h, g_h);
    cudaGetSymbolAddress((void**)&p_hpack, g_hpack);
    cudaGetSymbolAddress((void**)&p_qkv, g_qkv);
    cudaGetSymbolAddress((void**)&p_mem2, g_mem2);
    cudaGetSymbolAddress((void**)&p_retr, g_retr);
    cudaGetSymbolAddress((void**)&p_memout, g_memout);
    cudaGetSymbolAddress((void**)&p_qmean, g_qmean);
    cudaGetSymbolAddress((void**)&p_gctx, g_gctx);
    cudaGetSymbolAddress((void**)&p_w1T, g_w1T);
    cudaGetSymbolAddress((void**)&p_qkvT, g_qkvT);
    cudaGetSymbolAddress((void**)&p_w2T, g_w2T);
    cudaGetSymbolAddress((void**)&p_mrwT, g_mrwT);
    cudaGetSymbolAddress((void**)&p_outT, g_outT);
    cudaGetSymbolAddress((void**)&p_b1, g_b1pack);
    cudaGetSymbolAddress((void**)&p_b2, g_b2pack);

    const int ROWS = Bb * Ss;
    dim3 tpb(32, 8);
    cudaStream_t s0 = 0;

    cudaStream_t s1;
    cudaEvent_t evLN, evQKV;
    cudaStreamCreateWithFlags(&s1, cudaStreamNonBlocking);
    cudaEventCreateWithFlags(&evLN, cudaEventDisableTiming);
    cudaEventCreateWithFlags(&evQKV, cudaEventDisableTiming);

    cudaFuncSetAttribute(flash_attn, cudaFuncAttributeMaxDynamicSharedMemorySize, FA_SMEM);

    // ---- stream 0: LN ----
    ln_imp_kernel<<<ROWS, 256, 0, s0>>>(x, ln_g, ln_b, wg_w, wg_b);
    cudaEventRecord(evLN, s0);

    // ---- stream 1 (QKV branch) ----
    cudaStreamWaitEvent(s1, evLN, 0);
    tp32<<<dim3(32, 32), tpb, 0, s1>>>(q_w, p_qkvT + 0 * Dd * Dd, Dd, Dd);
    tp32<<<dim3(32, 32), tpb, 0, s1>>>(k_w, p_qkvT + 1 * Dd * Dd, Dd, Dd);
    tp32<<<dim3(32, 32), tpb, 0, s1>>>(v_w, p_qkvT + 2 * Dd * Dd, Dd, Dd);
    wt_kernel<<<(3 * NGRP * 128 * 128 + 255) / 256, 256, 0, s1>>>(conv_w);
    tp32<<<dim3(32, 32), tpb, 0, s1>>>(out_w, p_outT, Dd, Dd);
    launch_tc<1, 0, 0, 0>(dim3(24, 128), s1, p_xn, Dd, 0, p_qkvT, Dd, 0, nullptr, 0, nullptr,
                          p_qkv, 3072, 0, Dd, 1.f);
    qmean_kernel<<<dim3(Dd / 256, Bb), 256, 0, s1>>>();
    gemm_small<<<dim3(Dd / BN, 1), 256, 0, s1>>>(p_qmean, Dd, gp_w, Dd, gp_b, p_gctx, Dd, Bb, Dd);
    cudaEventRecord(evQKV, s1);

    // ---- stream 0 (memory-attention branch) ----
    tp32<<<dim3(32, 32), tpb, 0, s0>>>(mk_w1, p_w1T + 0 * Dd * Dd, Dd, Dd);
    tp32<<<dim3(32, 32), tpb, 0, s0>>>(mv_w1, p_w1T + 1 * Dd * Dd, Dd, Dd);
    tp32<<<dim3(32, 32), tpb, 0, s0>>>(mq_w1, p_w1T + 2 * Dd * Dd, Dd, Dd);
    tp32<<<dim3(4, 32), tpb, 0, s0>>>(mk_w2, p_w2T + 0 * 128 * Dd, Dd, 128);
    tp32<<<dim3(4, 32), tpb, 0, s0>>>(mv_w2, p_w2T + 1 * 128 * Dd, Dd, 128);
    tp32<<<dim3(4, 32), tpb, 0, s0>>>(mq_w2, p_w2T + 2 * 128 * Dd, Dd, 128);
    tp32<<<dim3(32, 4), tpb, 0, s0>>>(mr_w, p_mrwT, 128, Dd);
    bias_pack<<<(3456 + 255) / 256, 256, 0, s0>>>(mk_b1, mv_b1, mq_b1, mk_b2, mv_b2, mq_b2);
    topk_kernel<<<Bb, 1024, 0, s0>>>();

    // fused MLP1 (3 chains)
    launch_tc<1, 1, 0, 0>(dim3(24, 128), s0, p_xn, Dd, 0, p_w1T, Dd, 0, p_b1, 0, nullptr,
                          p_hpack, 3072, 0, Dd, 1.f);
    // fused MLP2
    launch_tc<1, 0, 0, 0>(dim3(1, 128, 3), s0, p_hpack, 3072, 1024, p_w2T, Dd, (long)128 * Dd,
                          p_b2, 128, nullptr, p_mem2, 384, 128, Dd, 1.f);
    // splice memory into d_out
    assemble_kernel<<<(Bb * Mm * 256 + 255) / 256, 256, 0, s0>>>(memdict, out_mem);

    // fused attention: sim + softmax + retr in one kernel
    flash_attn<<<dim3(Ss / 128, Bb), 256, FA_SMEM, s0>>>(p_mem2 + 256, out_mem, p_retr);

    // memout = retr @ mr_w + mr_b
    launch_tc<1, 0, 0, 0>(dim3(8, 128), s0, p_retr, Vv, 0, p_mrwT, Vv, 0, mr_b, 0, nullptr,
                          p_memout, Dd, 0, Vv, 1.f);

    // join, conv, out-proj
    cudaStreamWaitEvent(s0, evQKV, 0);
    conv_tc<<<dim3(Ss / 128, NGRP, Bb), 256, 0, s0>>>(conv_b);
    launch_tc<1, 0, 1, 0>(dim3(8, 128), s0, p_h, Dd, 0, p_outT, Dd, 0, out_b, 0, x,
                          out_main, Dd, 0, Dd, 1.f);
}

// round 16
// speedup vs baseline: 6.6622x; 1.3928x over previous
#include <cuda_runtime.h>
#include <cuda_fp16.h>
#include <math.h>
#include <stdint.h>

#define Bb 4
#define Ss 4096
#define Dd 1024
#define Mm 2048
#define Kk 128
#define Vv 128
#define NGRP 8
#define NWRITES 1024
#define KEEP 1024

// ---------------- scratch ----------------
__device__ __align__(16) __half g_xnh[(size_t)Bb * Ss * Dd];
__device__ __align__(16) __half g_hpackh[(size_t)Bb * Ss * 3072];
__device__ __align__(16) __half g_hh[(size_t)Bb * Ss * Dd];
__device__ __align__(16) __half g_retrh[Bb * Ss * Vv];
__device__ __align__(16) float g_qkv[(size_t)Bb * Ss * 3072];
__device__ __align__(16) float g_mem2[Bb * Ss * 384];
__device__ __align__(16) float g_sig[Bb * Ss];
__device__ __align__(16) int   g_topidx[Bb * NWRITES];
__device__ __align__(16) float g_retr[Bb * Ss * Vv];
__device__ __align__(16) float g_memout[Bb * Ss * Dd];
__device__ __align__(16) float g_qmean[Bb * Dd];
__device__ __align__(16) float g_gctx[Bb * Dd];
__device__ __align__(16) float g_wt[3 * NGRP * 128 * 128];
__device__ __align__(16) __half g_w1Th[3 * Dd * Dd];
__device__ __align__(16) __half g_qkvTh[3 * Dd * Dd];
__device__ __align__(16) __half g_w2Th[3 * 128 * Dd];
__device__ __align__(16) __half g_mrwTh[Dd * Vv];
__device__ __align__(16) __half g_outTh[Dd * Dd];
__device__ __align__(16) float g_b1pack[3072];
__device__ __align__(16) float g_b2pack[384];

// ---------------- helpers ----------------
__device__ __forceinline__ void mma8(float* c, const uint32_t* a, const uint32_t* b) {
    asm volatile(
        "mma.sync.aligned.m16n8k8.row.col.f32.tf32.tf32.f32 "
        "{%0,%1,%2,%3}, {%4,%5,%6,%7}, {%8,%9}, {%0,%1,%2,%3};\n"
        : "+f"(c[0]), "+f"(c[1]), "+f"(c[2]), "+f"(c[3])
        : "r"(a[0]), "r"(a[1]), "r"(a[2]), "r"(a[3]), "r"(b[0]), "r"(b[1]));
}
__device__ __forceinline__ void mma16h(float* c, const uint32_t* a, const uint32_t* b) {
    asm volatile(
        "mma.sync.aligned.m16n8k16.row.col.f32.f16.f16.f32 "
        "{%0,%1,%2,%3}, {%4,%5,%6,%7}, {%8,%9}, {%0,%1,%2,%3};\n"
        : "+f"(c[0]), "+f"(c[1]), "+f"(c[2]), "+f"(c[3])
        : "r"(a[0]), "r"(a[1]), "r"(a[2]), "r"(a[3]), "r"(b[0]), "r"(b[1]));
}
__device__ __forceinline__ void cpa16(uint32_t dst, const void* src) {
    asm volatile("cp.async.cg.shared.global [%0], [%1], 16;\n" :: "r"(dst), "l"(src));
}
#define CP_COMMIT asm volatile("cp.async.commit_group;\n" ::: "memory")
#define CP_WAIT1  asm volatile("cp.async.wait_group 1;\n" ::: "memory")
__device__ __forceinline__ void ldsm4(uint32_t* r, uint32_t addr) {
    asm volatile("ldmatrix.sync.aligned.m8n8.x4.shared.b16 {%0,%1,%2,%3}, [%4];\n"
                 : "=r"(r[0]), "=r"(r[1]), "=r"(r[2]), "=r"(r[3]) : "r"(addr));
}
__device__ __forceinline__ void ldsm2(uint32_t* r, uint32_t addr) {
    asm volatile("ldmatrix.sync.aligned.m8n8.x2.shared.b16 {%0,%1}, [%2];\n"
                 : "=r"(r[0]), "=r"(r[1]) : "r"(addr));
}

// ================= fp16 GEMM: 128x128 tile, K-tile 32, 3-stage =================
#define HSTR 40                      // halves per shared row (80B: 8 rows -> 8 banks)
#define HTILE (128 * HSTR)           // halves per matrix tile (10240 B)
#define HNST 3
#define HF_SMEM (HNST * 2 * HTILE * 2)   // 61440 B

template <int ACT, int RESID, int OUTH>
__global__ void __launch_bounds__(256, 2) gemm_hf(
    const __half* __restrict__ A, int lda, long sA,
    const __half* __restrict__ Bw, int ldb, long sB,
    const float* __restrict__ bias, long sBias,
    const float* __restrict__ resid,
    void* __restrict__ Cv, int ldc, long sC, int Kd)
{
    extern __shared__ __align__(16) __half shh[];
    __shared__ __align__(16) float sbias[128];
    long bz = blockIdx.z;
    A += bz * sA; Bw += bz * sB;
    int n0 = blockIdx.x * 128, m0 = blockIdx.y * 128;
    int tid = threadIdx.x;
    int warp = tid >> 5, lane = tid & 31;
    int g = lane >> 2, tg = lane & 3;
    int lr = lane & 7, ls = lane >> 3;
    int wm = (warp & 1) * 64, wn = (warp >> 1) * 32;

    if (tid < 128) sbias[tid] = bias ? bias[bz * sBias + n0 + tid] : 0.f;

    uint32_t asb = (uint32_t)__cvta_generic_to_shared(shh);
    uint32_t bsb = asb + HNST * HTILE * 2;

    // ldmatrix per-thread components (fp16 m16n8k16)
    int a_row = wm + lr + ((ls & 1) << 3);
    int a_col = (ls >> 1) << 3;            // 0 or 8 halves
    int b_row = wn + lr;
    int b_col = (ls & 1) << 3;

    float c[4][4][4];
#pragma unroll
    for (int a = 0; a < 4; a++)
#pragma unroll
        for (int b = 0; b < 4; b++)
#pragma unroll
            for (int e = 0; e < 4; e++) c[a][b][e] = 0.f;

#define HF_STAGE(tt)                                                              \
    {                                                                             \
        int t_ = (tt);                                                            \
        uint32_t ad_ = asb + (t_ % HNST) * HTILE * 2;                             \
        uint32_t bd_ = bsb + (t_ % HNST) * HTILE * 2;                             \
        int k0_ = t_ * 32;                                                        \
        _Pragma("unroll")                                                         \
        for (int p_ = 0; p_ < 2; p_++) {                                          \
            int u_ = tid + p_ * 256;                                              \
            int r_ = u_ >> 2, c8_ = (u_ & 3) * 8;                                 \
            cpa16(ad_ + (uint32_t)(r_ * HSTR + c8_) * 2,                          \
                  A + (long)(m0 + r_) * lda + k0_ + c8_);                         \
        }                                                                         \
        _Pragma("unroll")                                                         \
        for (int p_ = 0; p_ < 2; p_++) {                                          \
            int u_ = tid + p_ * 256;                                              \
            int r_ = u_ >> 2, c8_ = (u_ & 3) * 8;                                 \
            cpa16(bd_ + (uint32_t)(r_ * HSTR + c8_) * 2,                          \
                  Bw + (long)(n0 + r_) * ldb + k0_ + c8_);                        \
        }                                                                         \
        CP_COMMIT;                                                                \
    }

    int nt = Kd >> 5;
    HF_STAGE(0);
    if (nt > 1) HF_STAGE(1) else CP_COMMIT;

    for (int t = 0; t < nt; t++) {
        CP_WAIT1;
        __syncthreads();
        if (t + 2 < nt) HF_STAGE(t + 2) else CP_COMMIT;
        int st = t % HNST;
        uint32_t aaddr = asb + st * HTILE * 2 + (uint32_t)(a_row * HSTR + a_col) * 2;
        uint32_t baddr = bsb + st * HTILE * 2 + (uint32_t)(b_row * HSTR + b_col) * 2;
#pragma unroll
        for (int ks = 0; ks < 2; ks++) {
            const int kk = ks * 16;
            uint32_t af[4][4], bf[4][2];
#pragma unroll
            for (int mi = 0; mi < 4; mi++)
                ldsm4(af[mi], aaddr + (uint32_t)(mi * 16 * HSTR + kk) * 2);
#pragma unroll
            for (int ni = 0; ni < 4; ni++)
                ldsm2(bf[ni], baddr + (uint32_t)(ni * 8 * HSTR + kk) * 2);
#pragma unroll
            for (int mi = 0; mi < 4; mi++)
#pragma unroll
                for (int ni = 0; ni < 4; ni++) mma16h(c[mi][ni], af[mi], bf[ni]);
        }
    }

#pragma unroll
    for (int mi = 0; mi < 4; mi++) {
#pragma unroll
        for (int ni = 0; ni < 4; ni++) {
            int row = m0 + wm + mi * 16 + g;
            int cb = wn + ni * 8 + 2 * tg;
            int col = n0 + cb;
            float v[4];
#pragma unroll
            for (int e = 0; e < 4; e++) v[e] = c[mi][ni][e];
            v[0] += sbias[cb];     v[1] += sbias[cb + 1];
            v[2] += sbias[cb];     v[3] += sbias[cb + 1];
            if (ACT == 1) {
#pragma unroll
                for (int e = 0; e < 4; e++)
                    v[e] = 0.5f * v[e] * (1.f + erff(v[e] * 0.7071067811865475f));
            }
            if (RESID) {
                v[0] += resid[(long)row * ldc + col];
                v[1] += resid[(long)row * ldc + col + 1];
                v[2] += resid[(long)(row + 8) * ldc + col];
                v[3] += resid[(long)(row + 8) * ldc + col + 1];
            }
            if (OUTH) {
                __half* C = (__half*)Cv + bz * sC;
                *(__half2*)&C[(long)row * ldc + col] = __floats2half2_rn(v[0], v[1]);
                *(__half2*)&C[(long)(row + 8) * ldc + col] = __floats2half2_rn(v[2], v[3]);
            } else {
                float* C = (float*)Cv + bz * sC;
                *(float2*)&C[(long)row * ldc + col] = make_float2(v[0], v[1]);
                *(float2*)&C[(long)(row + 8) * ldc + col] = make_float2(v[2], v[3]);
            }
        }
    }
}

// ================= fused flash attention (fp32 mma; writes fp32 + fp16) =======
#define FA_QSTR 132
#define FA_PSTR 68
#define FA_VSTR 136
#define FA_QSZ (128 * 132)
#define FA_KP 8704
#define FA_STAGE 17408
#define FA_SMEM ((FA_QSZ + 2 * FA_STAGE) * 4)

__global__ void __launch_bounds__(256, 1) flash_attn(
    const float* __restrict__ memq,
    const float* __restrict__ kv,
    float* __restrict__ outr)
{
    extern __shared__ __align__(16) float sh[];
    int tid = threadIdx.x, warp = tid >> 5, lane = tid & 31;
    int b = blockIdx.y, qm0 = blockIdx.x * 128;
    int g = lane >> 2, tg = lane & 3;
    int lr = lane & 7, ls = lane >> 3;
    int wr = warp * 16;

    uint32_t shb = (uint32_t)__cvta_generic_to_shared(sh);

    const float* qsrc = memq + (size_t)(b * Ss + qm0) * 384;
#pragma unroll
    for (int p = 0; p < 16; p++) {
        int u = tid + p * 256;
        int r = u >> 5, c = u & 31;
        cpa16(shb + (uint32_t)(r * FA_QSTR + c * 4) * 4, qsrc + (size_t)r * 384 + c * 4);
    }

#define FA_STAGE_T(tt)                                                            \
    {                                                                             \
        int t_ = (tt);                                                            \
        uint32_t kpb_ = shb + (uint32_t)(FA_QSZ + (t_ & 1) * FA_STAGE) * 4;       \
        uint32_t vb_ = kpb_ + FA_KP * 4;                                          \
        const float* src_ = kv + ((size_t)(b * Mm) + t_ * 64) * 256;              \
        _Pragma("unroll")                                                         \
        for (int p_ = 0; p_ < 8; p_++) {                                          \
            int u_ = tid + p_ * 256;                                              \
            int n_ = u_ >> 5, c_ = u_ & 31;                                       \
            cpa16(kpb_ + (uint32_t)(n_ * FA_QSTR + c_ * 4) * 4,                   \
                  src_ + (size_t)n_ * 256 + c_ * 4);                              \
        }                                                                         \
        _Pragma("unroll")                                                         \
        for (int p_ = 0; p_ < 8; p_++) {                                          \
            int u_ = tid + p_ * 256;                                              \
            int n_ = u_ >> 5, c_ = u_ & 31;                                       \
            cpa16(vb_ + (uint32_t)(n_ * FA_VSTR + c_ * 4) * 4,                    \
                  src_ + (size_t)n_ * 256 + 128 + c_ * 4);                        \
        }                                                                         \
        CP_COMMIT;                                                                \
    }

    FA_STAGE_T(0);
    FA_STAGE_T(1);

    float o[16][4];
#pragma unroll
    for (int i = 0; i < 16; i++)
#pragma unroll
        for (int e = 0; e < 4; e++) o[i][e] = 0.f;
    float m0r = -3.4e38f, m1r = -3.4e38f, l0 = 0.f, l1 = 0.f;
    const float alpha = 0.08838834764831845f;

    uint32_t qaddr = shb + (uint32_t)((wr + lr + ((ls & 1) << 3)) * FA_QSTR
                                      + ((ls >> 1) << 2)) * 4;

    const int nt = Mm / 64;
    for (int t = 0; t < nt; t++) {
        CP_WAIT1;
        __syncthreads();
        uint32_t kpb = shb + (uint32_t)(FA_QSZ + (t & 1) * FA_STAGE) * 4;

        float s[8][4];
#pragma unroll
        for (int ni = 0; ni < 8; ni++)
#pragma unroll
            for (int e = 0; e < 4; e++) s[ni][e] = 0.f;
        uint32_t kaddr = kpb + (uint32_t)(lr * FA_QSTR + ((ls & 1) << 2)) * 4;
#pragma unroll
        for (int ks = 0; ks < 16; ks++) {
            uint32_t af[4];
            ldsm4(af, qaddr + (uint32_t)(ks * 8) * 4);
#pragma unroll
            for (int ni = 0; ni < 8; ni++) {
                uint32_t bf[2];
                ldsm2(bf, kaddr + (uint32_t)(ni * 8 * FA_QSTR + ks * 8) * 4);
                mma8(s[ni], af, bf);
            }
        }
        __syncthreads();

        float rmax0 = -3.4e38f, rmax1 = -3.4e38f;
#pragma unroll
        for (int ni = 0; ni < 8; ni++) {
#pragma unroll
            for (int e = 0; e < 4; e++) s[ni][e] *= alpha;
            rmax0 = fmaxf(rmax0, fmaxf(s[ni][0], s[ni][1]));
            rmax1 = fmaxf(rmax1, fmaxf(s[ni][2], s[ni][3]));
        }
        rmax0 = fmaxf(rmax0, __shfl_xor_sync(0xFFFFFFFFu, rmax0, 1));
        rmax0 = fmaxf(rmax0, __shfl_xor_sync(0xFFFFFFFFu, rmax0, 2));
        rmax1 = fmaxf(rmax1, __shfl_xor_sync(0xFFFFFFFFu, rmax1, 1));
        rmax1 = fmaxf(rmax1, __shfl_xor_sync(0xFFFFFFFFu, rmax1, 2));
        float mn0 = fmaxf(m0r, rmax0), mn1 = fmaxf(m1r, rmax1);
        float sc0 = expf(m0r - mn0), sc1 = expf(m1r - mn1);
        m0r = mn0; m1r = mn1;

        float* P = sh + FA_QSZ + (t & 1) * FA_STAGE;
        float ps0 = 0.f, ps1 = 0.f;
#pragma unroll
        for (int ni = 0; ni < 8; ni++) {
            float p0 = expf(s[ni][0] - mn0), p1 = expf(s[ni][1] - mn0);
            float p2 = expf(s[ni][2] - mn1), p3 = expf(s[ni][3] - mn1);
            ps0 += p0 + p1; ps1 += p2 + p3;
            int col = ni * 8 + 2 * tg;
            *(float2*)&P[(wr + g) * FA_PSTR + col] = make_float2(p0, p1);
            *(float2*)&P[(wr + g + 8) * FA_PSTR + col] = make_float2(p2, p3);
        }
        ps0 += __shfl_xor_sync(0xFFFFFFFFu, ps0, 1);
        ps0 += __shfl_xor_sync(0xFFFFFFFFu, ps0, 2);
        ps1 += __shfl_xor_sync(0xFFFFFFFFu, ps1, 1);
        ps1 += __shfl_xor_sync(0xFFFFFFFFu, ps1, 2);
        l0 = l0 * sc0 + ps0;
        l1 = l1 * sc1 + ps1;
#pragma unroll
        for (int ni = 0; ni < 16; ni++) {
            o[ni][0] *= sc0; o[ni][1] *= sc0;
            o[ni][2] *= sc1; o[ni][3] *= sc1;
        }
        __syncthreads();

        uint32_t pa = kpb + (uint32_t)((wr + lr + ((ls & 1) << 3)) * FA_PSTR
                                       + ((ls >> 1) << 2)) * 4;
        const float* Vst = sh + FA_QSZ + (t & 1) * FA_STAGE + FA_KP;
#pragma unroll
        for (int ks = 0; ks < 8; ks++) {
            uint32_t af[4];
            ldsm4(af, pa + (uint32_t)(ks * 8) * 4);
            int kk = ks * 8;
#pragma unroll
            for (int ni = 0; ni < 16; ni++) {
                uint32_t bf[2];
                const float* bp = Vst + (kk + tg) * FA_VSTR + ni * 8 + g;
                bf[0] = __float_as_uint(bp[0]);
                bf[1] = __float_as_uint(bp[4 * FA_VSTR]);
                mma8(o[ni], af, bf);
            }
        }
        __syncthreads();
        if (t + 2 < nt) FA_STAGE_T(t + 2) else CP_COMMIT;
    }

    float i0 = 1.f / l0, i1 = 1.f / l1;
    float* or0 = outr + (size_t)(b * Ss + qm0 + wr + g) * 128;
    float* or1 = or0 + 8 * 128;
    __half* oh0 = g_retrh + (size_t)(b * Ss + qm0 + wr + g) * 128;
    __half* oh1 = oh0 + 8 * 128;
#pragma unroll
    for (int ni = 0; ni < 16; ni++) {
        int col = ni * 8 + 2 * tg;
        float v0 = o[ni][0] * i0, v1 = o[ni][1] * i0;
        float v2 = o[ni][2] * i1, v3 = o[ni][3] * i1;
        *(float2*)&or0[col] = make_float2(v0, v1);
        *(float2*)&or1[col] = make_float2(v2, v3);
        *(__half2*)&oh0[col] = __floats2half2_rn(v0, v1);
        *(__half2*)&oh1[col] = __floats2half2_rn(v2, v3);
    }
}

// ---------------- transposes: fp32 src -> fp16 [n][k] ----------------
__global__ void tp32h(const float* __restrict__ src, __half* __restrict__ dst,
                      int K, int N) {
    __shared__ __align__(16) float t[32][33];
    int n0 = blockIdx.x * 32, k0 = blockIdx.y * 32;
    int tx = threadIdx.x, ty = threadIdx.y;
#pragma unroll
    for (int i = ty; i < 32; i += 8)
        t[i][tx] = src[(long)(k0 + i) * N + n0 + tx];
    __syncthreads();
#pragma unroll
    for (int i = ty; i < 32; i += 8)
        dst[(long)(n0 + i) * K + k0 + tx] = __float2half(t[tx][i]);
}

// ---------------- bias packing ----------------
__global__ void bias_pack(const float* __restrict__ b1k, const float* __restrict__ b1v,
                          const float* __restrict__ b1q, const float* __restrict__ b2k,
                          const float* __restrict__ b2v, const float* __restrict__ b2q) {
    int i = blockIdx.x * 256 + threadIdx.x;
    if (i < 3072) {
        int ch = i >> 10, col = i & 1023;
        g_b1pack[i] = (ch == 0 ? b1k : ch == 1 ? b1v : b1q)[col];
    } else if (i < 3072 + 384) {
        int j = i - 3072;
        int ch = j >> 7, col = j & 127;
        g_b2pack[j] = (ch == 0 ? b2k : ch == 1 ? b2v : b2q)[col];
    }
}

// ---------------- conv (tf32; A from fp32 qkv; outputs fp16 hh) ----------------
#define TBK 32
#define TSTR 136
__device__ __forceinline__ int swz(int k, int m) { return m ^ (((k >> 2) & 7) << 2); }
__device__ __forceinline__ uint32_t f2tf32(float f) {
    uint32_t u;
    asm("cvt.rna.tf32.f32 %0, %1;" : "=r"(u) : "f"(f));
    return u;
}

__global__ void wt_kernel(const float* __restrict__ cw) {
    int idx = blockIdx.x * 256 + threadIdx.x;
    if (idx >= 3 * NGRP * 128 * 128) return;
    int o = idx & 127;
    int k = (idx >> 7) & 127;
    int hg = idx >> 14;
    int h = hg >> 3, grp = hg & 7;
    g_wt[idx] = cw[(((size_t)(grp * 128 + o)) * 128 + k) * 3 + h];
}

__global__ void __launch_bounds__(256, 2) conv_tc(const float* __restrict__ cb) {
    __shared__ __align__(16) uint32_t As[TBK * TSTR];
    __shared__ __align__(16) uint32_t Bs[TBK * TSTR];
    __shared__ __align__(16) float cbs[128];
    int b = blockIdx.z, grp = blockIdx.y, s0 = blockIdx.x * 128;
    int tid = threadIdx.x;
    int warp = tid >> 5, lane = tid & 31;
    int g = lane >> 2, tg = lane & 3;
    int wm = (warp & 1) * 64, wn = (warp >> 1) * 32;

    if (tid < 128) cbs[tid] = cb[grp * 128 + tid];

    float c[4][4][4];
#pragma unroll
    for (int a = 0; a < 4; a++)
#pragma unroll
        for (int d = 0; d < 4; d++)
#pragma unroll
            for (int e = 0; e < 4; e++) c[a][d][e] = 0.f;

    int arow = tid >> 3, acol = (tid & 7) * 4;

    for (int h = 0; h < 3; h++) {
        for (int k0 = 0; k0 < 128; k0 += TBK) {
#pragma unroll
            for (int p = 0; p < 4; p++) {
                int m = arow + p * 32;
                int s = s0 + m + h - 1;
                float4 v = make_float4(0.f, 0.f, 0.f, 0.f);
                if (s >= 0 && s < Ss)
                    v = *(const float4*)&g_qkv[((size_t)(b * Ss) + s) * 3072 + 2048 + grp * 128 + k0 + acol];
                As[(acol + 0) * TSTR + swz(acol + 0, m)] = f2tf32(v.x);
                As[(acol + 1) * TSTR + swz(acol + 1, m)] = f2tf32(v.y);
                As[(acol + 2) * TSTR + swz(acol + 2, m)] = f2tf32(v.z);
                As[(acol + 3) * TSTR + swz(acol + 3, m)] = f2tf32(v.w);
            }
            {
                int n = tid & 127, kb = tid >> 7;
#pragma unroll
                for (int p = 0; p < 16; p++) {
                    int k = kb + p * 2;
                    Bs[k * TSTR + swz(k, n)] =
                        f2tf32(g_wt[(((size_t)(h * NGRP + grp)) * 128 + k0 + k) * 128 + n]);
                }
            }
            __syncthreads();
#pragma unroll
            for (int ks = 0; ks < 4; ks++) {
                int kk = ks * 8;
                uint32_t af[4][4], bf[4][2];
#pragma unroll
                for (int mi = 0; mi < 4; mi++) {
                    int m = wm + mi * 16;
                    af[mi][0] = As[(kk + tg) * TSTR + swz(kk + tg, m + g)];
                    af[mi][1] = As[(kk + tg) * TSTR + swz(kk + tg, m + g + 8)];
                    af[mi][2] = As[(kk + tg + 4) * TSTR + swz(kk + tg + 4, m + g)];
                    af[mi][3] = As[(kk + tg + 4) * TSTR + swz(kk + tg + 4, m + g + 8)];
                }
#pragma unroll
                for (int ni = 0; ni < 4; ni++) {
                    int n = wn + ni * 8;
                    bf[ni][0] = Bs[(kk + tg) * TSTR + swz(kk + tg, n + g)];
                    bf[ni][1] = Bs[(kk + tg + 4) * TSTR + swz(kk + tg + 4, n + g)];
                }
#pragma unroll
                for (int mi = 0; mi < 4; mi++)
#pragma unroll
                    for (int ni = 0; ni < 4; ni++) mma8(c[mi][ni], af[mi], bf[ni]);
            }
            __syncthreads();
        }
    }

#pragma unroll
    for (int mi = 0; mi < 4; mi++) {
#pragma unroll
        for (int ni = 0; ni < 4; ni++) {
            int cbcol = wn + ni * 8 + 2 * tg;
            int o = grp * 128 + cbcol;
#pragma unroll
            for (int half = 0; half < 2; half++) {
                int s = s0 + wm + mi * 16 + g + half * 8;
                size_t idx = ((size_t)(b * Ss) + s) * Dd + o;
                size_t kidx = ((size_t)(b * Ss) + s) * 3072 + 1024 + o;
                float2 mo = *(const float2*)&g_memout[idx];
                float2 kv = *(const float2*)&g_qkv[kidx];
                float gc0 = g_gctx[b * Dd + o], gc1 = g_gctx[b * Dd + o + 1];
                float l0 = c[mi][ni][half * 2 + 0] + cbs[cbcol];
                float l1 = c[mi][ni][half * 2 + 1] + cbs[cbcol + 1];
                float p0 = 1.f / (1.f + expf(-kv.x));
                float p1 = 1.f / (1.f + expf(-kv.y));
                float r0 = (l0 + 0.1f * gc0 + 0.5f * mo.x) * p0;
                float r1 = (l1 + 0.1f * gc1 + 0.5f * mo.y) * p1;
                *(__half2*)&g_hh[idx] = __floats2half2_rn(r0, r1);
            }
        }
    }
}

// ---------------- LayerNorm + write-gate (writes fp16 xn) ----------------
__global__ void ln_imp_kernel(const float* __restrict__ x,
                              const float* __restrict__ lng,
                              const float* __restrict__ lnb,
                              const float* __restrict__ wgw,
                              const float* __restrict__ wgb) {
    int row = blockIdx.x;
    int tid = threadIdx.x;
    const float* xr = x + (size_t)row * Dd + tid * 4;
    float x0 = xr[0], x1 = xr[1], x2 = xr[2], x3 = xr[3];
    __shared__ float red[256];

    red[tid] = x0 + x1 + x2 + x3; __syncthreads();
    for (int o = 128; o > 0; o >>= 1) { if (tid < o) red[tid] += red[tid + o]; __syncthreads(); }
    float mu = red[0] * (1.f / Dd);
    __syncthreads();

    float d0 = x0 - mu, d1 = x1 - mu, d2 = x2 - mu, d3 = x3 - mu;
    red[tid] = d0 * d0 + d1 * d1 + d2 * d2 + d3 * d3; __syncthreads();
    for (int o = 128; o > 0; o >>= 1) { if (tid < o) red[tid] += red[tid + o]; __syncthreads(); }
    float var = red[0] * (1.f / Dd);
    float rs = rsqrtf(var + 1e-5f);
    __syncthreads();

    float y0 = d0 * rs * lng[tid * 4 + 0] + lnb[tid * 4 + 0];
    float y1 = d1 * rs * lng[tid * 4 + 1] + lnb[tid * 4 + 1];
    float y2 = d2 * rs * lng[tid * 4 + 2] + lnb[tid * 4 + 2];
    float y3 = d3 * rs * lng[tid * 4 + 3] + lnb[tid * 4 + 3];
    __half* xh = g_xnh + (size_t)row * Dd + tid * 4;
    *(__half2*)&xh[0] = __floats2half2_rn(y0, y1);
    *(__half2*)&xh[2] = __floats2half2_rn(y2, y3);

    red[tid] = y0 * wgw[tid * 4 + 0] + y1 * wgw[tid * 4 + 1]
             + y2 * wgw[tid * 4 + 2] + y3 * wgw[tid * 4 + 3];
    __syncthreads();
    for (int o = 128; o > 0; o >>= 1) { if (tid < o) red[tid] += red[tid + o]; __syncthreads(); }
    if (tid == 0) {
        double l = (double)(red[0] + wgb[0]);
        g_sig[row] = (float)(1.0 / (1.0 + exp(-l)));
    }
}

// ---------------- top-k ----------------
__global__ void topk_kernel() {
    __shared__ __align__(16) unsigned long long sk[Ss];
    int b = blockIdx.x, tid = threadIdx.x;
    for (int i = tid; i < Ss; i += 1024) {
        unsigned u = __float_as_uint(g_sig[b * Ss + i]);
        u = (u & 0x80000000u) ? ~u : (u | 0x80000000u);
        sk[i] = ((unsigned long long)u << 32) | (unsigned)(0xFFFFFFFFu - i);
    }
    __syncthreads();
    for (int k = 2; k <= Ss; k <<= 1) {
        for (int j = k >> 1; j > 0; j >>= 1) {
            for (int i = tid; i < Ss; i += 1024) {
                int ixj = i ^ j;
                if (ixj > i) {
                    bool desc = ((i & k) == 0);
                    unsigned long long a = sk[i], c = sk[ixj];
                    if ((a < c) == desc) { sk[i] = c; sk[ixj] = a; }
                }
            }
            __syncthreads();
        }
    }
    for (int i = tid; i < NWRITES; i += 1024)
        g_topidx[b * NWRITES + i] = (int)(0xFFFFFFFFu - (unsigned)sk[i]);
}

// ---------------- splice memory -> d_out ----------------
__global__ void assemble_kernel(const float* __restrict__ md, float* __restrict__ om) {
    int idx = blockIdx.x * blockDim.x + threadIdx.x;
    if (idx >= Bb * Mm * 256) return;
    int c = idx & 255;
    int m = (idx >> 8) & (Mm - 1);
    int b = idx >> 19;
    float val;
    if (m < KEEP) val = md[idx];
    else {
        int id = g_topidx[b * NWRITES + (m - KEEP)];
        val = g_mem2[((size_t)(b * Ss) + id) * 384 + c];
    }
    om[idx] = val;
}

// ---------------- small SIMT GEMM (M=4 gctx only) ----------------
#define BM 64
#define BN 64
#define BKg 16
__global__ void gemm_small(const float* __restrict__ A, int lda,
                           const float* __restrict__ Bm, int ldb,
                           const float* __restrict__ bias,
                           float* __restrict__ C, int ldc, int Mr, int Kd) {
    __shared__ __align__(16) float As[BKg][BM + 4];
    __shared__ __align__(16) float Bs[BKg][BN + 4];
    __shared__ __align__(16) float sbias[BN];
    int n0 = blockIdx.x * BN, m0 = blockIdx.y * BM;
    int tid = threadIdx.x;
    int tx = tid & 15, ty = tid >> 4;
    if (tid < BN) sbias[tid] = bias ? bias[n0 + tid] : 0.f;
    float acc[4][4];
#pragma unroll
    for (int i = 0; i < 4; i++)
#pragma unroll
        for (int j = 0; j < 4; j++) acc[i][j] = 0.f;
    int aRow = tid >> 2, aCol = (tid & 3) * 4;
    for (int k0 = 0; k0 < Kd; k0 += BKg) {
        float4 av = make_float4(0.f, 0.f, 0.f, 0.f);
        if (m0 + aRow < Mr)
            av = *(const float4*)&A[(long)(m0 + aRow) * lda + k0 + aCol];
        As[aCol + 0][aRow] = av.x; As[aCol + 1][aRow] = av.y;
        As[aCol + 2][aRow] = av.z; As[aCol + 3][aRow] = av.w;
        int kr = tid >> 4, n = (tid & 15) * 4;
        const float* bp = &Bm[(long)(k0 + kr) * ldb + n0 + n];
        Bs[kr][n + 0] = bp[0]; Bs[kr][n + 1] = bp[1];
        Bs[kr][n + 2] = bp[2]; Bs[kr][n + 3] = bp[3];
        __syncthreads();
#pragma unroll
        for (int kk = 0; kk < BKg; kk++) {
            const float4 a = *(const float4*)&As[kk][ty * 4];
            const float4 b4 = *(const float4*)&Bs[kk][tx * 4];
            float ar[4] = {a.x, a.y, a.z, a.w};
            float br[4] = {b4.x, b4.y, b4.z, b4.w};
#pragma unroll
            for (int ii = 0; ii < 4; ii++)
#pragma unroll
                for (int jj = 0; jj < 4; jj++) acc[ii][jj] += ar[ii] * br[jj];
        }
        __syncthreads();
    }
#pragma unroll
    for (int i = 0; i < 4; i++) {
        int m = m0 + ty * 4 + i;
        if (m >= Mr) break;
#pragma unroll
        for (int j = 0; j < 4; j++) {
            int n = n0 + tx * 4 + j;
            C[(long)m * ldc + n] = acc[i][j] + sbias[tx * 4 + j];
        }
    }
}

// ---------------- mean over S of queries ----------------
__global__ void qmean_kernel() {
    int d = blockIdx.x * 256 + threadIdx.x;
    int b = blockIdx.y;
    const float* p = g_qkv + (size_t)b * Ss * 3072 + d;
    double s = 0.0;
    for (int t = 0; t < Ss; t++) s += p[(size_t)t * 3072];
    g_qmean[b * Dd + d] = (float)(s * (1.0 / Ss));
}

// ---------------- launch ----------------
extern "C" void kernel_launch(void* const* d_in, const int* in_sizes, int n_in,
                              void* d_out, int out_size) {
    const float* x      = (const float*)d_in[0];
    const float* memdict= (const float*)d_in[1];
    const float* ln_g   = (const float*)d_in[2];
    const float* ln_b   = (const float*)d_in[3];
    const float* mk_w1  = (const float*)d_in[4];
    const float* mk_b1  = (const float*)d_in[5];
    const float* mk_w2  = (const float*)d_in[6];
    const float* mk_b2  = (const float*)d_in[7];
    const float* mv_w1  = (const float*)d_in[8];
    const float* mv_b1  = (const float*)d_in[9];
    const float* mv_w2  = (const float*)d_in[10];
    const float* mv_b2  = (const float*)d_in[11];
    const float* mq_w1  = (const float*)d_in[12];
    const float* mq_b1  = (const float*)d_in[13];
    const float* mq_w2  = (const float*)d_in[14];
    const float* mq_b2  = (const float*)d_in[15];
    const float* wg_w   = (const float*)d_in[16];
    const float* wg_b   = (const float*)d_in[17];
    const float* q_w    = (const float*)d_in[18];
    const float* k_w    = (const float*)d_in[19];
    const float* v_w    = (const float*)d_in[20];
    const float* conv_w = (const float*)d_in[21];
    const float* conv_b = (const float*)d_in[22];
    const float* gp_w   = (const float*)d_in[23];
    const float* gp_b   = (const float*)d_in[24];
    const float* mr_w   = (const float*)d_in[25];
    const float* mr_b   = (const float*)d_in[26];
    const float* out_w  = (const float*)d_in[27];
    const float* out_b  = (const float*)d_in[28];

    float* out_main = (float*)d_out;
    float* out_mem  = out_main + (size_t)Bb * Ss * Dd;

    __half *p_xnh, *p_hpackh, *p_hh, *p_retrh, *p_w1Th, *p_qkvTh, *p_w2Th, *p_mrwTh, *p_outTh;
    float *p_qkv, *p_mem2, *p_retr, *p_memout, *p_qmean, *p_gctx, *p_b1, *p_b2;
    cudaGetSymbolAddress((void**)&p_xnh, g_xnh);
    cudaGetSymbolAddress((void**)&p_hpackh, g_hpackh);
    cudaGetSymbolAddress((void**)&p_hh, g_hh);
    cudaGetSymbolAddress((void**)&p_retrh, g_retrh);
    cudaGetSymbolAddress((void**)&p_qkv, g_qkv);
    cudaGetSymbolAddress((void**)&p_mem2, g_mem2);
    cudaGetSymbolAddress((void**)&p_retr, g_retr);
    cudaGetSymbolAddress((void**)&p_memout, g_memout);
    cudaGetSymbolAddress((void**)&p_qmean, g_qmean);
    cudaGetSymbolAddress((void**)&p_gctx, g_gctx);
    cudaGetSymbolAddress((void**)&p_w1Th, g_w1Th);
    cudaGetSymbolAddress((void**)&p_qkvTh, g_qkvTh);
    cudaGetSymbolAddress((void**)&p_w2Th, g_w2Th);
    cudaGetSymbolAddress((void**)&p_mrwTh, g_mrwTh);
    cudaGetSymbolAddress((void**)&p_outTh, g_outTh);
    cudaGetSymbolAddress((void**)&p_b1, g_b1pack);
    cudaGetSymbolAddress((void**)&p_b2, g_b2pack);

    const int ROWS = Bb * Ss;
    dim3 tpb(32, 8);
    cudaStream_t s0 = 0;

    cudaStream_t s1;
    cudaEvent_t evLN, evQKV;
    cudaStreamCreateWithFlags(&s1, cudaStreamNonBlocking);
    cudaEventCreateWithFlags(&evLN, cudaEventDisableTiming);
    cudaEventCreateWithFlags(&evQKV, cudaEventDisableTiming);

    cudaFuncSetAttribute(flash_attn, cudaFuncAttributeMaxDynamicSharedMemorySize, FA_SMEM);
    cudaFuncSetAttribute(gemm_hf<1, 0, 1>, cudaFuncAttributeMaxDynamicSharedMemorySize, HF_SMEM);
    cudaFuncSetAttribute(gemm_hf<0, 0, 0>, cudaFuncAttributeMaxDynamicSharedMemorySize, HF_SMEM);
    cudaFuncSetAttribute(gemm_hf<0, 1, 0>, cudaFuncAttributeMaxDynamicSharedMemorySize, HF_SMEM);

    // ---- stream 0: LN ----
    ln_imp_kernel<<<ROWS, 256, 0, s0>>>(x, ln_g, ln_b, wg_w, wg_b);
    cudaEventRecord(evLN, s0);

    // ---- stream 1 (QKV branch) ----
    cudaStreamWaitEvent(s1, evLN, 0);
    tp32h<<<dim3(32, 32), tpb, 0, s1>>>(q_w, p_qkvTh + 0 * Dd * Dd, Dd, Dd);
    tp32h<<<dim3(32, 32), tpb, 0, s1>>>(k_w, p_qkvTh + 1 * Dd * Dd, Dd, Dd);
    tp32h<<<dim3(32, 32), tpb, 0, s1>>>(v_w, p_qkvTh + 2 * Dd * Dd, Dd, Dd);
    wt_kernel<<<(3 * NGRP * 128 * 128 + 255) / 256, 256, 0, s1>>>(conv_w);
    tp32h<<<dim3(32, 32), tpb, 0, s1>>>(out_w, p_outTh, Dd, Dd);
    gemm_hf<0, 0, 0><<<dim3(24, 128), 256, HF_SMEM, s1>>>(
        p_xnh, Dd, 0, p_qkvTh, Dd, 0, nullptr, 0, nullptr, p_qkv, 3072, 0, Dd);
    qmean_kernel<<<dim3(Dd / 256, Bb), 256, 0, s1>>>();
    gemm_small<<<dim3(Dd / BN, 1), 256, 0, s1>>>(p_qmean, Dd, gp_w, Dd, gp_b, p_gctx, Dd, Bb, Dd);
    cudaEventRecord(evQKV, s1);

    // ---- stream 0 (memory-attention branch) ----
    tp32h<<<dim3(32, 32), tpb, 0, s0>>>(mk_w1, p_w1Th + 0 * Dd * Dd, Dd, Dd);
    tp32h<<<dim3(32, 32), tpb, 0, s0>>>(mv_w1, p_w1Th + 1 * Dd * Dd, Dd, Dd);
    tp32h<<<dim3(32, 32), tpb, 0, s0>>>(mq_w1, p_w1Th + 2 * Dd * Dd, Dd, Dd);
    tp32h<<<dim3(4, 32), tpb, 0, s0>>>(mk_w2, p_w2Th + 0 * 128 * Dd, Dd, 128);
    tp32h<<<dim3(4, 32), tpb, 0, s0>>>(mv_w2, p_w2Th + 1 * 128 * Dd, Dd, 128);
    tp32h<<<dim3(4, 32), tpb, 0, s0>>>(mq_w2, p_w2Th + 2 * 128 * Dd, Dd, 128);
    tp32h<<<dim3(32, 4), tpb, 0, s0>>>(mr_w, p_mrwTh, 128, Dd);
    bias_pack<<<(3456 + 255) / 256, 256, 0, s0>>>(mk_b1, mv_b1, mq_b1, mk_b2, mv_b2, mq_b2);
    topk_kernel<<<Bb, 1024, 0, s0>>>();

    // fused MLP1 (fp16 in, gelu, fp16 out)
    gemm_hf<1, 0, 1><<<dim3(24, 128), 256, HF_SMEM, s0>>>(
        p_xnh, Dd, 0, p_w1Th, Dd, 0, p_b1, 0, nullptr, p_hpackh, 3072, 0, Dd);
    // fused MLP2 (grid.z chains)
    gemm_hf<0, 0, 0><<<dim3(1, 128, 3), 256, HF_SMEM, s0>>>(
        p_hpackh, 3072, 1024, p_w2Th, Dd, (long)128 * Dd, p_b2, 128, nullptr,
        p_mem2, 384, 128, Dd);
    // splice memory into d_out
    assemble_kernel<<<(Bb * Mm * 256 + 255) / 256, 256, 0, s0>>>(memdict, out_mem);

    // fused attention (also emits fp16 retr)
    flash_attn<<<dim3(Ss / 128, Bb), 256, FA_SMEM, s0>>>(p_mem2 + 256, out_mem, p_retr);

    // memout = retr @ mr_w + mr_b (fp16 in)
    gemm_hf<0, 0, 0><<<dim3(8, 128), 256, HF_SMEM, s0>>>(
        p_retrh, Vv, 0, p_mrwTh, Vv, 0, mr_b, 0, nullptr, p_memout, Dd, 0, Vv);

    // join, conv (emits fp16 hh), out-proj (fp16 in + fp32 residual)
    cudaStreamWaitEvent(s0, evQKV, 0);
    conv_tc<<<dim3(Ss / 128, NGRP, Bb), 256, 0, s0>>>(conv_b);
    gemm_hf<0, 1, 0><<<dim3(8, 128), 256, HF_SMEM, s0>>>(
        p_hh, Dd, 0, p_outTh, Dd, 0, out_b, 0, x, out_main, Dd, 0, Dd);
}